// round 7
// baseline (speedup 1.0000x reference)
#include <cuda_runtime.h>
#include <cuda_bf16.h>
#include <cstdint>
#include <math.h>

static constexpr int B_   = 4;
static constexpr int N_   = 4096;
static constexpr int H_   = 16;
static constexpr int DK_  = 128;
static constexpr int DIM_ = 2048;
static constexpr int BH_  = B_ * H_;      // 64
static constexpr int MROWS_ = B_ * N_;    // 16384
static constexpr float INV_SQRT_DK = 0.08838834764831843f;

static constexpr long long OUT_OFF_MF  = 33554432LL;
static constexpr long long OUT_OFF_MS  = 34603008LL;
static constexpr long long OUT_OFF_PSI = 35651584LL;

// ---------------- scratch (allocation-free: device globals) ----------------
__device__ float g_q  [(size_t)BH_ * N_ * DK_];
__device__ float g_kf [(size_t)BH_ * N_ * DK_];
__device__ float g_ksl[(size_t)BH_ * N_ * DK_];
__device__ float g_v  [(size_t)BH_ * N_ * DK_];
__device__ float g_part[2LL * BH_ * 8 * DK_ * DK_];
__device__ float g_mblend[(size_t)BH_ * DK_ * DK_];
__device__ float g_meanpart[8 * B_ * DIM_];
__device__ float g_mean[B_ * DIM_];
__device__ float g_h1[B_ * 1024];

// bf16 split operands for HMMA GEMMs
__device__ __nv_bfloat16 g_xh [(size_t)MROWS_ * DIM_];
__device__ __nv_bfloat16 g_xl [(size_t)MROWS_ * DIM_];
__device__ __nv_bfloat16 g_wqkvh[(size_t)6144 * 2048];
__device__ __nv_bfloat16 g_wqkvl[(size_t)6144 * 2048];
__device__ __nv_bfloat16 g_woh [(size_t)2048 * 2048];
__device__ __nv_bfloat16 g_wol [(size_t)2048 * 2048];
__device__ __nv_bfloat16 g_obh [(size_t)MROWS_ * DIM_];
__device__ __nv_bfloat16 g_obl [(size_t)MROWS_ * DIM_];

// ===================== mma.sync helpers (base-target PTX) ==================
__device__ __forceinline__ uint32_t smem_u32(const void* p) {
    uint32_t a;
    asm("{ .reg .u64 t; cvta.to.shared.u64 t, %1; cvt.u32.u64 %0, t; }"
        : "=r"(a) : "l"(p));
    return a;
}

#define MMA16816(d, a, b0, b1) \
    asm volatile("mma.sync.aligned.m16n8k16.row.col.f32.bf16.bf16.f32 " \
        "{%0,%1,%2,%3}, {%4,%5,%6,%7}, {%8,%9}, {%0,%1,%2,%3};" \
        : "+f"((d)[0]), "+f"((d)[1]), "+f"((d)[2]), "+f"((d)[3]) \
        : "r"((a)[0]), "r"((a)[1]), "r"((a)[2]), "r"((a)[3]), "r"(b0), "r"(b1))

#define LDSM_X4(r, addr) \
    asm volatile("ldmatrix.sync.aligned.m8n8.x4.shared.b16 {%0,%1,%2,%3}, [%4];" \
        : "=r"((r)[0]), "=r"((r)[1]), "=r"((r)[2]), "=r"((r)[3]) : "r"(addr))

#define CP_ASYNC16(dst, src) \
    asm volatile("cp.async.cg.shared.global [%0], [%1], 16;" \
        :: "r"(dst), "l"(src) : "memory")
#define CP_COMMIT() asm volatile("cp.async.commit_group;" ::: "memory")
#define CP_WAIT(n)  asm volatile("cp.async.wait_group %0;" :: "n"(n) : "memory")

// ======================= bf16 split / transpose prep =======================
__global__ void k_split_x(const float* __restrict__ x) {
    size_t i = ((size_t)blockIdx.x * 256 + threadIdx.x) * 4;
    float4 v = *(const float4*)(x + i);
    float a[4] = {v.x, v.y, v.z, v.w};
    #pragma unroll
    for (int j = 0; j < 4; j++) {
        __nv_bfloat16 hi = __float2bfloat16_rn(a[j]);
        __nv_bfloat16 lo = __float2bfloat16_rn(a[j] - __bfloat162float(hi));
        g_xh[i + j] = hi; g_xl[i + j] = lo;
    }
}

__global__ void k_wsplit_qkv(const float* __restrict__ Wq, const float* __restrict__ Wk,
                             const float* __restrict__ Wv) {
    __shared__ float tile[32][33];
    int k0 = blockIdx.x * 32, n0 = blockIdx.y * 32;
    int which = n0 >> 11;
    const float* __restrict__ W = (which == 0) ? Wq : (which == 1 ? Wk : Wv);
    int nn0 = n0 & 2047;
    for (int r = threadIdx.y; r < 32; r += 8)
        tile[r][threadIdx.x] = W[(size_t)(k0 + r) * 2048 + nn0 + threadIdx.x];
    __syncthreads();
    for (int r = threadIdx.y; r < 32; r += 8) {
        float v = tile[threadIdx.x][r];
        __nv_bfloat16 hi = __float2bfloat16_rn(v);
        __nv_bfloat16 lo = __float2bfloat16_rn(v - __bfloat162float(hi));
        size_t o = (size_t)(n0 + r) * 2048 + k0 + threadIdx.x;
        g_wqkvh[o] = hi; g_wqkvl[o] = lo;
    }
}

__global__ void k_wsplit_o(const float* __restrict__ Wo) {
    __shared__ float tile[32][33];
    int k0 = blockIdx.x * 32, n0 = blockIdx.y * 32;
    for (int r = threadIdx.y; r < 32; r += 8)
        tile[r][threadIdx.x] = Wo[(size_t)(k0 + r) * 2048 + n0 + threadIdx.x];
    __syncthreads();
    for (int r = threadIdx.y; r < 32; r += 8) {
        float v = tile[threadIdx.x][r];
        __nv_bfloat16 hi = __float2bfloat16_rn(v);
        __nv_bfloat16 lo = __float2bfloat16_rn(v - __bfloat162float(hi));
        size_t o = (size_t)(n0 + r) * 2048 + k0 + threadIdx.x;
        g_woh[o] = hi; g_wol[o] = lo;
    }
}

// ======================= HMMA GEMM: C = A @ B^T (fp32 via bf16 3-pass split) ===
// 256(M) x 128(N) CTA tile, warp tile 64x64, BK=32, 2-stage cp.async.
// Smem per stage: Ah[256][40] Al[256][40] Bh[128][40] Bl[128][40] (80B rows,
// conflict-free ldmatrix). Stage = 30720 elems = 61440 B; 2 stages = 122880 B.
static constexpr int SSTG = 30720;                   // elems per stage
static constexpr int OFF_AL = 10240, OFF_BH = 20480, OFF_BL = 25600;

__global__ __launch_bounds__(256)
void k_mma_gemm(float* __restrict__ Cout, int mode) {
    extern __shared__ __align__(16) __nv_bfloat16 smb[];
    const __nv_bfloat16* __restrict__ Ah;
    const __nv_bfloat16* __restrict__ Al;
    const __nv_bfloat16* __restrict__ Bh;
    const __nv_bfloat16* __restrict__ Bl;
    if (mode == 0) { Ah = g_xh;  Al = g_xl;  Bh = g_wqkvh; Bl = g_wqkvl; }
    else           { Ah = g_obh; Al = g_obl; Bh = g_woh;   Bl = g_wol;   }

    const uint32_t sbase = smem_u32(smb);
    const int tid = threadIdx.x;
    const int wid = tid >> 5, lane = tid & 31;
    const int wr = wid >> 1, wc = wid & 1;           // warp row 0..3 (x64), col 0..1 (x64)
    const int j0 = blockIdx.x * 128;
    const int m0 = blockIdx.y * 256;
    const int l15 = lane & 15;
    const int lhalf = (lane >> 4) * 8;

    float acc[4][8][4];
    #pragma unroll
    for (int i = 0; i < 4; i++)
        #pragma unroll
        for (int j = 0; j < 8; j++)
            #pragma unroll
            for (int k = 0; k < 4; k++) acc[i][j][k] = 0.f;

    // global->smem: 3072 16B segs per chunk (A 2x1024, B 2x512), 12 per thread
    int gl_t[12], gl_row[12], gl_q[12];
    const __nv_bfloat16* gl_src[12];
    uint32_t gl_soff[12];
    #pragma unroll
    for (int i = 0; i < 12; i++) {
        int idx = i * 256 + tid;
        int t, local;
        if (idx < 1024)      { t = 0; local = idx; }
        else if (idx < 2048) { t = 1; local = idx - 1024; }
        else if (idx < 2560) { t = 2; local = idx - 2048; }
        else                 { t = 3; local = idx - 2560; }
        gl_t[i] = t;
        gl_row[i] = local >> 2;
        gl_q[i] = local & 3;
        gl_src[i] = (t == 0) ? Ah : (t == 1) ? Al : (t == 2) ? Bh : Bl;
        uint32_t toff = (t == 0) ? 0u : (t == 1) ? (uint32_t)OFF_AL
                      : (t == 2) ? (uint32_t)OFF_BH : (uint32_t)OFF_BL;
        gl_soff[i] = (toff + (uint32_t)gl_row[i] * 40 + (uint32_t)gl_q[i] * 8) * 2;
    }

    auto issue = [&](int c, int st) {
        #pragma unroll
        for (int i = 0; i < 12; i++) {
            int grow = (gl_t[i] < 2) ? (m0 + gl_row[i]) : (j0 + gl_row[i]);
            const __nv_bfloat16* src = gl_src[i] + (size_t)grow * 2048 + c * 32 + gl_q[i] * 8;
            uint32_t dst = sbase + (uint32_t)(st * SSTG) * 2 + gl_soff[i];
            CP_ASYNC16(dst, src);
        }
        CP_COMMIT();
    };

    issue(0, 0);
    for (int c = 0; c < 64; c++) {
        if (c < 63) { issue(c + 1, (c + 1) & 1); CP_WAIT(1); }
        else        { CP_WAIT(0); }
        __syncthreads();
        const uint32_t stg = sbase + (uint32_t)((c & 1) * SSTG) * 2;

        #pragma unroll
        for (int s = 0; s < 2; s++) {
            const uint32_t kcol = (uint32_t)(s * 16 + lhalf) * 2;
            uint32_t ah[4][4], al[4][4], bhf[4][4], blf[4][4];
            #pragma unroll
            for (int i = 0; i < 4; i++) {
                uint32_t ar = stg + (uint32_t)((wr * 64 + i * 16 + l15) * 40) * 2 + kcol;
                LDSM_X4(ah[i], ar);
                LDSM_X4(al[i], ar + (uint32_t)OFF_AL * 2);
            }
            #pragma unroll
            for (int p = 0; p < 4; p++) {
                uint32_t br = stg + (uint32_t)(OFF_BH + (wc * 64 + p * 16 + l15) * 40) * 2 + kcol;
                LDSM_X4(bhf[p], br);
                LDSM_X4(blf[p], br + (uint32_t)(OFF_BL - OFF_BH) * 2);
            }
            #pragma unroll
            for (int i = 0; i < 4; i++)
                #pragma unroll
                for (int t = 0; t < 8; t++) {
                    const int p = t >> 1, sel = t & 1;
                    MMA16816(acc[i][t], ah[i], bhf[p][sel], bhf[p][sel + 2]);
                    MMA16816(acc[i][t], ah[i], blf[p][sel], blf[p][sel + 2]);
                    MMA16816(acc[i][t], al[i], bhf[p][sel], bhf[p][sel + 2]);
                }
        }
        __syncthreads();
    }

    // epilogue
    const int gr = lane >> 2;
    const int lane2 = (lane & 3) * 2;
    if (mode == 0) {
        const int which = j0 >> 11;
        const int h = (j0 >> 7) & 15;
        const int b = m0 >> 12;
        float* slab = ((which == 0) ? g_q : (which == 1) ? g_kf : g_v)
                    + (size_t)(b * 16 + h) * 4096 * 128;
        #pragma unroll
        for (int i = 0; i < 4; i++) {
            int n = (m0 & 4095) + wr * 64 + i * 16 + gr;
            #pragma unroll
            for (int t = 0; t < 8; t++) {
                int col = wc * 64 + t * 8 + lane2;
                float* dst = slab + (size_t)n * 128 + col;
                *(float2*)dst = make_float2(acc[i][t][0], acc[i][t][1]);
                *(float2*)(dst + 8 * 128) = make_float2(acc[i][t][2], acc[i][t][3]);
            }
        }
    } else {
        #pragma unroll
        for (int i = 0; i < 4; i++) {
            int m = m0 + wr * 64 + i * 16 + gr;
            #pragma unroll
            for (int t = 0; t < 8; t++) {
                int col = j0 + wc * 64 + t * 8 + lane2;
                float* dst = Cout + (size_t)m * 2048 + col;
                *(float2*)dst = make_float2(acc[i][t][0], acc[i][t][1]);
                *(float2*)(dst + 8 * 2048) = make_float2(acc[i][t][2], acc[i][t][3]);
            }
        }
    }
}

// ======================= mean over N (float4-coalesced) =======================
__global__ void k_meanpart(const float* __restrict__ x) {
    int gid = blockIdx.x * 256 + threadIdx.x;        // 16384 threads
    int sp = gid >> 11;                               // 0..7
    int r  = gid & 2047;                              // b*512 + c (float4 col)
    int b = r >> 9, c = r & 511;
    const float4* xp = (const float4*)x + ((size_t)(b * N_ + sp * 512)) * 512 + c;
    float4 s = make_float4(0.f, 0.f, 0.f, 0.f);
    #pragma unroll 4
    for (int n = 0; n < 512; n++) {
        float4 v = xp[(size_t)n * 512];
        s.x += v.x; s.y += v.y; s.z += v.z; s.w += v.w;
    }
    ((float4*)g_meanpart)[(size_t)sp * 2048 + b * 512 + c] = s;
}

__global__ void k_meanred() {
    int r = blockIdx.x * 256 + threadIdx.x;
    float s = 0.f;
    #pragma unroll
    for (int sp = 0; sp < 8; sp++) s += g_meanpart[sp * 8192 + r];
    g_mean[r] = s * (1.f / 4096.f);
}

// ======================= gating MLP =======================
__global__ void k_mlp1(const float* __restrict__ f1_w, const float* __restrict__ f1_b) {
    __shared__ float xm[2048];
    int b = blockIdx.x;
    for (int i = threadIdx.x; i < 2048; i += 256) xm[i] = g_mean[b * 2048 + i];
    __syncthreads();
    int j = blockIdx.y * 256 + threadIdx.x;
    float s = 0.f;
    for (int k = 0; k < 2048; k++)
        s = fmaf(xm[k], f1_w[(size_t)k * 1024 + j], s);
    s += f1_b[j];
    g_h1[b * 1024 + j] = s / (1.f + expf(-s));
}

__global__ void k_mlp2(const float* __restrict__ f2_w, const float* __restrict__ f2_b,
                       float* __restrict__ dout) {
    __shared__ float red[128];
    int bh = blockIdx.x;
    int b = bh >> 4, h = bh & 15;
    float s = 0.f;
    for (int k = threadIdx.x; k < 1024; k += 128)
        s = fmaf(g_h1[b * 1024 + k], f2_w[k * 16 + h], s);
    red[threadIdx.x] = s; __syncthreads();
    for (int off = 64; off > 0; off >>= 1) {
        if (threadIdx.x < off) red[threadIdx.x] += red[threadIdx.x + off];
        __syncthreads();
    }
    if (threadIdx.x == 0) {
        float z = red[0] + f2_b[h];
        dout[OUT_OFF_PSI + bh] = 1.f / (1.f + expf(-z));
    }
}

// ======================= resonance + k_mod + decay split =======================
__global__ __launch_bounds__(256, 2)
void k_res(const float* __restrict__ Wb, const float* __restrict__ fast_slope,
           const float* __restrict__ slow_slope) {
    __shared__ float As[16][132];
    __shared__ float Bs[16][128];
    const int m0 = blockIdx.x * 128;
    const int bh = blockIdx.y;
    const int h = bh & 15;
    float* __restrict__ kslab = g_kf + (size_t)bh * N_ * DK_;
    float* __restrict__ kslow = g_ksl + (size_t)bh * N_ * DK_;
    const float* __restrict__ Wbh = Wb + (size_t)h * DK_ * DK_;
    const int tx = threadIdx.x, ty = threadIdx.y;
    const int tid = ty * 16 + tx;
    float acc[8][8];
    #pragma unroll
    for (int i = 0; i < 8; i++)
        #pragma unroll
        for (int j = 0; j < 8; j++) acc[i][j] = 0.f;

    const int arow = tid >> 2, acol = (tid & 3) * 4;
    const int brow = tid >> 5, bcol = (tid & 31) * 4;

    for (int kt = 0; kt < 128; kt += 16) {
        #pragma unroll
        for (int r = 0; r < 2; r++) {
            int row = arow + r * 64;
            float4 av = *(const float4*)&kslab[(size_t)(m0 + row) * DK_ + kt + acol];
            As[acol + 0][row] = av.x; As[acol + 1][row] = av.y;
            As[acol + 2][row] = av.z; As[acol + 3][row] = av.w;
        }
        #pragma unroll
        for (int r = 0; r < 2; r++) {
            int row = brow + r * 8;
            *(float4*)&Bs[row][bcol] =
                *(const float4*)&Wbh[(size_t)(kt + row) * DK_ + bcol];
        }
        __syncthreads();
        #pragma unroll
        for (int kk = 0; kk < 16; kk++) {
            float a[8], bb[8];
            *(float4*)&a[0]  = *(const float4*)&As[kk][ty * 8];
            *(float4*)&a[4]  = *(const float4*)&As[kk][ty * 8 + 4];
            *(float4*)&bb[0] = *(const float4*)&Bs[kk][tx * 8];
            *(float4*)&bb[4] = *(const float4*)&Bs[kk][tx * 8 + 4];
            #pragma unroll
            for (int i = 0; i < 8; i++)
                #pragma unroll
                for (int j = 0; j < 8; j++)
                    acc[i][j] = fmaf(a[i], bb[j], acc[i][j]);
        }
        __syncthreads();
    }
    const float fs = fast_slope[h], ss = slow_slope[h];
    #pragma unroll
    for (int i = 0; i < 8; i++) {
        int n = m0 + ty * 8 + i;
        float idx = (float)(n - (N_ - 1));
        float fw = expf(fs * idx);
        float sw = expf(ss * idx);
        #pragma unroll
        for (int j = 0; j < 8; j += 4) {
            size_t p = (size_t)n * DK_ + tx * 8 + j;
            float4 kr = *(const float4*)&kslab[p];
            float4 kf4, ks4;
            float r0, km;
            r0 = tanhf(acc[i][j+0]); km = kr.x * (1.f + 0.5f * r0) * INV_SQRT_DK; kf4.x = km * fw; ks4.x = km * sw;
            r0 = tanhf(acc[i][j+1]); km = kr.y * (1.f + 0.5f * r0) * INV_SQRT_DK; kf4.y = km * fw; ks4.y = km * sw;
            r0 = tanhf(acc[i][j+2]); km = kr.z * (1.f + 0.5f * r0) * INV_SQRT_DK; kf4.z = km * fw; ks4.z = km * sw;
            r0 = tanhf(acc[i][j+3]); km = kr.w * (1.f + 0.5f * r0) * INV_SQRT_DK; kf4.w = km * fw; ks4.w = km * sw;
            *(float4*)&kslab[p] = kf4;
            *(float4*)&kslow[p] = ks4;
        }
    }
}

// ======================= M = k^T @ v partials =======================
__global__ __launch_bounds__(256, 2)
void k_mpart() {
    __shared__ float As[16][128];
    __shared__ float Bs[16][128];
    const int split = blockIdx.x;
    const int bh = blockIdx.y;
    const int which = blockIdx.z;
    const float* __restrict__ kslab =
        (which ? g_ksl : g_kf) + (size_t)bh * N_ * DK_ + (size_t)split * 512 * DK_;
    const float* __restrict__ vslab =
        g_v + (size_t)bh * N_ * DK_ + (size_t)split * 512 * DK_;
    const int tx = threadIdx.x, ty = threadIdx.y;
    const int tid = ty * 16 + tx;
    float acc[8][8];
    #pragma unroll
    for (int i = 0; i < 8; i++)
        #pragma unroll
        for (int j = 0; j < 8; j++) acc[i][j] = 0.f;

    const int lrow = tid >> 5, lcol = (tid & 31) * 4;

    for (int nt = 0; nt < 512; nt += 16) {
        #pragma unroll
        for (int r = 0; r < 2; r++) {
            int row = lrow + r * 8;
            *(float4*)&As[row][lcol] = *(const float4*)&kslab[(size_t)(nt + row) * DK_ + lcol];
            *(float4*)&Bs[row][lcol] = *(const float4*)&vslab[(size_t)(nt + row) * DK_ + lcol];
        }
        __syncthreads();
        #pragma unroll
        for (int kk = 0; kk < 16; kk++) {
            float a[8], bb[8];
            *(float4*)&a[0]  = *(const float4*)&As[kk][ty * 8];
            *(float4*)&a[4]  = *(const float4*)&As[kk][ty * 8 + 4];
            *(float4*)&bb[0] = *(const float4*)&Bs[kk][tx * 8];
            *(float4*)&bb[4] = *(const float4*)&Bs[kk][tx * 8 + 4];
            #pragma unroll
            for (int i = 0; i < 8; i++)
                #pragma unroll
                for (int j = 0; j < 8; j++)
                    acc[i][j] = fmaf(a[i], bb[j], acc[i][j]);
        }
        __syncthreads();
    }
    float* dst = g_part + (((size_t)which * BH_ + bh) * 8 + split) * 16384;
    #pragma unroll
    for (int i = 0; i < 8; i++)
        #pragma unroll
        for (int j = 0; j < 8; j += 4) {
            float4 v4 = make_float4(acc[i][j], acc[i][j+1], acc[i][j+2], acc[i][j+3]);
            *(float4*)&dst[(ty * 8 + i) * 128 + tx * 8 + j] = v4;
        }
}

// ======================= M finalize =======================
__global__ void k_mfin(const float* __restrict__ Mf_prev, const float* __restrict__ Ms_prev,
                       const float* __restrict__ inter_fast, const float* __restrict__ inter_slow,
                       float* __restrict__ dout) {
    const int bh = blockIdx.x;
    const int which = blockIdx.y;
    const int h = bh & 15;
    const float inter = which ? inter_slow[h] : inter_fast[h];
    const float* prev = (which ? Ms_prev : Mf_prev) + (size_t)bh * 16384;
    const float* part = g_part + ((size_t)which * BH_ + bh) * 8 * 16384;
    float* dst = dout + (which ? OUT_OFF_MS : OUT_OFF_MF) + (size_t)bh * 16384;
    for (int e = threadIdx.x; e < 16384; e += 256) {
        float s = 0.f;
        #pragma unroll
        for (int sp = 0; sp < 8; sp++) s += part[(size_t)sp * 16384 + e];
        dst[e] = prev[e] * inter + s;
    }
}

// ======================= Mref = (I+S) @ M, blended =======================
__global__ __launch_bounds__(256, 2)
void k_mref(const float* __restrict__ S_fast, const float* __restrict__ S_slow,
            const float* __restrict__ dout, int which) {
    __shared__ float As[16][132];
    __shared__ float Bs[16][128];
    const int bh = blockIdx.x;
    const int h = bh & 15;
    const float* __restrict__ S = (which ? S_slow : S_fast) + (size_t)h * 16384;
    const float* __restrict__ M = dout + (which ? OUT_OFF_MS : OUT_OFF_MF) + (size_t)bh * 16384;
    const int tx = threadIdx.x, ty = threadIdx.y;
    const int tid = ty * 16 + tx;
    float acc[8][8];
    #pragma unroll
    for (int i = 0; i < 8; i++)
        #pragma unroll
        for (int j = 0; j < 8; j++) acc[i][j] = 0.f;

    const int arow = tid >> 2, acol = (tid & 3) * 4;
    const int brow = tid >> 5, bcol = (tid & 31) * 4;

    for (int kt = 0; kt < 128; kt += 16) {
        #pragma unroll
        for (int r = 0; r < 2; r++) {
            int row = arow + r * 64;
            float4 av = *(const float4*)&S[(size_t)row * 128 + kt + acol];
            As[acol + 0][row] = av.x + ((row == kt + acol + 0) ? 1.f : 0.f);
            As[acol + 1][row] = av.y + ((row == kt + acol + 1) ? 1.f : 0.f);
            As[acol + 2][row] = av.z + ((row == kt + acol + 2) ? 1.f : 0.f);
            As[acol + 3][row] = av.w + ((row == kt + acol + 3) ? 1.f : 0.f);
        }
        #pragma unroll
        for (int r = 0; r < 2; r++) {
            int row = brow + r * 8;
            *(float4*)&Bs[row][bcol] = *(const float4*)&M[(size_t)(kt + row) * 128 + bcol];
        }
        __syncthreads();
        #pragma unroll
        for (int kk = 0; kk < 16; kk++) {
            float a[8], bb[8];
            *(float4*)&a[0]  = *(const float4*)&As[kk][ty * 8];
            *(float4*)&a[4]  = *(const float4*)&As[kk][ty * 8 + 4];
            *(float4*)&bb[0] = *(const float4*)&Bs[kk][tx * 8];
            *(float4*)&bb[4] = *(const float4*)&Bs[kk][tx * 8 + 4];
            #pragma unroll
            for (int i = 0; i < 8; i++)
                #pragma unroll
                for (int j = 0; j < 8; j++)
                    acc[i][j] = fmaf(a[i], bb[j], acc[i][j]);
        }
        __syncthreads();
    }
    const float p = dout[OUT_OFF_PSI + bh];
    const float c0 = which ? p : (1.f - p);
    float* dst = g_mblend + (size_t)bh * 16384;
    #pragma unroll
    for (int i = 0; i < 8; i++)
        #pragma unroll
        for (int j = 0; j < 8; j++) {
            int idx = (ty * 8 + i) * 128 + tx * 8 + j;
            if (which == 0) dst[idx] = c0 * acc[i][j];
            else            dst[idx] += c0 * acc[i][j];
        }
}

// ======================= o_blend = q @ M_blend, bf16 split out =======================
__global__ __launch_bounds__(256, 2)
void k_oblend() {
    __shared__ float As[16][132];
    __shared__ float Bs[16][128];
    const int m0 = blockIdx.x * 128;
    const int bh = blockIdx.y;
    const float* __restrict__ qslab = g_q + (size_t)bh * N_ * DK_;
    const float* __restrict__ Mb = g_mblend + (size_t)bh * 16384;
    const int tx = threadIdx.x, ty = threadIdx.y;
    const int tid = ty * 16 + tx;
    float acc[8][8];
    #pragma unroll
    for (int i = 0; i < 8; i++)
        #pragma unroll
        for (int j = 0; j < 8; j++) acc[i][j] = 0.f;

    const int arow = tid >> 2, acol = (tid & 3) * 4;
    const int brow = tid >> 5, bcol = (tid & 31) * 4;

    for (int kt = 0; kt < 128; kt += 16) {
        #pragma unroll
        for (int r = 0; r < 2; r++) {
            int row = arow + r * 64;
            float4 av = *(const float4*)&qslab[(size_t)(m0 + row) * DK_ + kt + acol];
            As[acol + 0][row] = av.x; As[acol + 1][row] = av.y;
            As[acol + 2][row] = av.z; As[acol + 3][row] = av.w;
        }
        #pragma unroll
        for (int r = 0; r < 2; r++) {
            int row = brow + r * 8;
            *(float4*)&Bs[row][bcol] = *(const float4*)&Mb[(size_t)(kt + row) * 128 + bcol];
        }
        __syncthreads();
        #pragma unroll
        for (int kk = 0; kk < 16; kk++) {
            float a[8], bb[8];
            *(float4*)&a[0]  = *(const float4*)&As[kk][ty * 8];
            *(float4*)&a[4]  = *(const float4*)&As[kk][ty * 8 + 4];
            *(float4*)&bb[0] = *(const float4*)&Bs[kk][tx * 8];
            *(float4*)&bb[4] = *(const float4*)&Bs[kk][tx * 8 + 4];
            #pragma unroll
            for (int i = 0; i < 8; i++)
                #pragma unroll
                for (int j = 0; j < 8; j++)
                    acc[i][j] = fmaf(a[i], bb[j], acc[i][j]);
        }
        __syncthreads();
    }
    const int b = bh >> 4, h = bh & 15;
    #pragma unroll
    for (int i = 0; i < 8; i++) {
        int n = m0 + ty * 8 + i;
        size_t base = ((size_t)(b * N_ + n) * H_ + h) * DK_ + tx * 8;
        #pragma unroll
        for (int j = 0; j < 8; j++) {
            float v = acc[i][j];
            __nv_bfloat16 hi = __float2bfloat16_rn(v);
            __nv_bfloat16 lo = __float2bfloat16_rn(v - __bfloat162float(hi));
            g_obh[base + j] = hi; g_obl[base + j] = lo;
        }
    }
}

// ======================= launch =======================
extern "C" void kernel_launch(void* const* d_in, const int* in_sizes, int n_in,
                              void* d_out, int out_size) {
    (void)in_sizes; (void)n_in; (void)out_size;
    const float* x          = (const float*)d_in[0];
    const float* Mf_prev    = (const float*)d_in[1];
    const float* Ms_prev    = (const float*)d_in[2];
    const float* Wq         = (const float*)d_in[3];
    const float* Wk         = (const float*)d_in[4];
    const float* Wv         = (const float*)d_in[5];
    const float* Wo         = (const float*)d_in[6];
    const float* Wb         = (const float*)d_in[7];
    const float* fast_slope = (const float*)d_in[8];
    const float* slow_slope = (const float*)d_in[9];
    const float* inter_fast = (const float*)d_in[10];
    const float* inter_slow = (const float*)d_in[11];
    const float* S_fast     = (const float*)d_in[12];
    const float* S_slow     = (const float*)d_in[13];
    const float* f1_w       = (const float*)d_in[14];
    const float* f1_b       = (const float*)d_in[15];
    const float* f2_w       = (const float*)d_in[16];
    const float* f2_b       = (const float*)d_in[17];
    float* out = (float*)d_out;

    const int gemm_smem = 2 * SSTG * 2;   // 122880 bytes
    static bool attr_set = false;
    if (!attr_set) {
        cudaFuncSetAttribute(k_mma_gemm, cudaFuncAttributeMaxDynamicSharedMemorySize, gemm_smem);
        attr_set = true;
    }

    dim3 t16(16, 16);
    dim3 t328(32, 8);

    // prep: bf16 splits
    k_split_x<<<32768, 256>>>(x);
    k_wsplit_qkv<<<dim3(64, 192), t328>>>(Wq, Wk, Wv);
    k_wsplit_o<<<dim3(64, 64), t328>>>(Wo);

    // gating path
    k_meanpart<<<64, 256>>>(x);
    k_meanred<<<32, 256>>>();
    k_mlp1<<<dim3(4, 4), 256>>>(f1_w, f1_b);
    k_mlp2<<<64, 128>>>(f2_w, f2_b, out);

    // QKV projection (HMMA, 256x128 tiles; grid: x=j-blocks, y=m-blocks)
    k_mma_gemm<<<dim3(48, 64), 256, gemm_smem>>>(nullptr, 0);

    // per-head path
    k_res<<<dim3(32, 64), t16>>>(Wb, fast_slope, slow_slope);
    k_mpart<<<dim3(8, 64, 2), t16>>>();
    k_mfin<<<dim3(64, 2), 256>>>(Mf_prev, Ms_prev, inter_fast, inter_slow, out);
    k_mref<<<64, t16>>>(S_fast, S_slow, out, 0);
    k_mref<<<64, t16>>>(S_fast, S_slow, out, 1);
    k_oblend<<<dim3(32, 64), t16>>>();

    // output projection (HMMA)
    k_mma_gemm<<<dim3(16, 64), 256, gemm_smem>>>(out, 1);
}

// round 8
// speedup vs baseline: 1.6880x; 1.6880x over previous
#include <cuda_runtime.h>
#include <cuda_bf16.h>
#include <cstdint>
#include <math.h>

static constexpr int B_   = 4;
static constexpr int N_   = 4096;
static constexpr int H_   = 16;
static constexpr int DK_  = 128;
static constexpr int DIM_ = 2048;
static constexpr int BH_  = B_ * H_;      // 64
static constexpr int MROWS_ = B_ * N_;    // 16384
static constexpr float INV_SQRT_DK = 0.08838834764831843f;

static constexpr long long OUT_OFF_MF  = 33554432LL;
static constexpr long long OUT_OFF_MS  = 34603008LL;
static constexpr long long OUT_OFF_PSI = 35651584LL;

// ---------------- scratch (allocation-free: device globals) ----------------
__device__ float g_q  [(size_t)BH_ * N_ * DK_];
__device__ float g_kf [(size_t)BH_ * N_ * DK_];
__device__ float g_ksl[(size_t)BH_ * N_ * DK_];
__device__ float g_v  [(size_t)BH_ * N_ * DK_];
__device__ float g_part[2LL * BH_ * 8 * DK_ * DK_];
__device__ float g_mblend[(size_t)BH_ * DK_ * DK_];
__device__ float g_meanpart[8 * B_ * DIM_];
__device__ float g_mean[B_ * DIM_];
__device__ float g_h1[B_ * 1024];

// bf16 split operands for HMMA GEMMs
__device__ __nv_bfloat16 g_xh [(size_t)MROWS_ * DIM_];
__device__ __nv_bfloat16 g_xl [(size_t)MROWS_ * DIM_];
__device__ __nv_bfloat16 g_wqkvh[(size_t)6144 * 2048];
__device__ __nv_bfloat16 g_wqkvl[(size_t)6144 * 2048];
__device__ __nv_bfloat16 g_woh [(size_t)2048 * 2048];
__device__ __nv_bfloat16 g_wol [(size_t)2048 * 2048];
__device__ __nv_bfloat16 g_obh [(size_t)MROWS_ * DIM_];
__device__ __nv_bfloat16 g_obl [(size_t)MROWS_ * DIM_];

// ===================== mma.sync helpers (base-target PTX) ==================
__device__ __forceinline__ uint32_t smem_u32(const void* p) {
    uint32_t a;
    asm("{ .reg .u64 t; cvta.to.shared.u64 t, %1; cvt.u32.u64 %0, t; }"
        : "=r"(a) : "l"(p));
    return a;
}

#define MMA16816(d, a, b0, b1) \
    asm volatile("mma.sync.aligned.m16n8k16.row.col.f32.bf16.bf16.f32 " \
        "{%0,%1,%2,%3}, {%4,%5,%6,%7}, {%8,%9}, {%0,%1,%2,%3};" \
        : "+f"((d)[0]), "+f"((d)[1]), "+f"((d)[2]), "+f"((d)[3]) \
        : "r"((a)[0]), "r"((a)[1]), "r"((a)[2]), "r"((a)[3]), "r"(b0), "r"(b1))

#define LDSM_X4(r, addr) \
    asm volatile("ldmatrix.sync.aligned.m8n8.x4.shared.b16 {%0,%1,%2,%3}, [%4];" \
        : "=r"((r)[0]), "=r"((r)[1]), "=r"((r)[2]), "=r"((r)[3]) : "r"(addr))

#define CP_ASYNC16(dst, src) \
    asm volatile("cp.async.cg.shared.global [%0], [%1], 16;" \
        :: "r"(dst), "l"(src) : "memory")
#define CP_COMMIT() asm volatile("cp.async.commit_group;" ::: "memory")
#define CP_WAIT(n)  asm volatile("cp.async.wait_group %0;" :: "n"(n) : "memory")

// ======================= bf16 split / transpose prep =======================
__global__ void k_split_x(const float* __restrict__ x) {
    size_t i = ((size_t)blockIdx.x * 256 + threadIdx.x) * 4;
    float4 v = *(const float4*)(x + i);
    float a[4] = {v.x, v.y, v.z, v.w};
    #pragma unroll
    for (int j = 0; j < 4; j++) {
        __nv_bfloat16 hi = __float2bfloat16_rn(a[j]);
        __nv_bfloat16 lo = __float2bfloat16_rn(a[j] - __bfloat162float(hi));
        g_xh[i + j] = hi; g_xl[i + j] = lo;
    }
}

__global__ void k_wsplit_qkv(const float* __restrict__ Wq, const float* __restrict__ Wk,
                             const float* __restrict__ Wv) {
    __shared__ float tile[32][33];
    int k0 = blockIdx.x * 32, n0 = blockIdx.y * 32;
    int which = n0 >> 11;
    const float* __restrict__ W = (which == 0) ? Wq : (which == 1 ? Wk : Wv);
    int nn0 = n0 & 2047;
    for (int r = threadIdx.y; r < 32; r += 8)
        tile[r][threadIdx.x] = W[(size_t)(k0 + r) * 2048 + nn0 + threadIdx.x];
    __syncthreads();
    for (int r = threadIdx.y; r < 32; r += 8) {
        float v = tile[threadIdx.x][r];
        __nv_bfloat16 hi = __float2bfloat16_rn(v);
        __nv_bfloat16 lo = __float2bfloat16_rn(v - __bfloat162float(hi));
        size_t o = (size_t)(n0 + r) * 2048 + k0 + threadIdx.x;
        g_wqkvh[o] = hi; g_wqkvl[o] = lo;
    }
}

__global__ void k_wsplit_o(const float* __restrict__ Wo) {
    __shared__ float tile[32][33];
    int k0 = blockIdx.x * 32, n0 = blockIdx.y * 32;
    for (int r = threadIdx.y; r < 32; r += 8)
        tile[r][threadIdx.x] = Wo[(size_t)(k0 + r) * 2048 + n0 + threadIdx.x];
    __syncthreads();
    for (int r = threadIdx.y; r < 32; r += 8) {
        float v = tile[threadIdx.x][r];
        __nv_bfloat16 hi = __float2bfloat16_rn(v);
        __nv_bfloat16 lo = __float2bfloat16_rn(v - __bfloat162float(hi));
        size_t o = (size_t)(n0 + r) * 2048 + k0 + threadIdx.x;
        g_woh[o] = hi; g_wol[o] = lo;
    }
}

// ======================= HMMA GEMM: C = A @ B^T (fp32 via bf16 3-pass split) ===
// 128x128 CTA tile, warp tile 32x64, BK=32, 2-stage cp.async, ldmatrix.x4.
// Split passes hoisted OUTSIDE the tile loops: each pass issues 16 independent
// MMAs (distinct accumulators) -> no RAW chains, HMMA issue-rate bound.
static constexpr int SSTG = 4 * 128 * 40;            // elems per stage

__global__ __launch_bounds__(256)
void k_mma_gemm(float* __restrict__ Cout, int mode) {
    extern __shared__ __align__(16) __nv_bfloat16 smb[];   // 2 * SSTG elems
    const __nv_bfloat16* __restrict__ Ah;
    const __nv_bfloat16* __restrict__ Al;
    const __nv_bfloat16* __restrict__ Bh;
    const __nv_bfloat16* __restrict__ Bl;
    if (mode == 0) { Ah = g_xh;  Al = g_xl;  Bh = g_wqkvh; Bl = g_wqkvl; }
    else           { Ah = g_obh; Al = g_obl; Bh = g_woh;   Bl = g_wol;   }

    const uint32_t sbase = smem_u32(smb);
    const int tid = threadIdx.x;
    const int wid = tid >> 5, lane = tid & 31;
    const int wr = wid >> 1, wc = wid & 1;           // warp row 0..3, col 0..1
    const int j0 = blockIdx.x * 128;
    const int m0 = blockIdx.y * 128;
    const int l15 = lane & 15;
    const int lhalf = (lane >> 4) * 8;

    float acc[2][8][4];
    #pragma unroll
    for (int i = 0; i < 2; i++)
        #pragma unroll
        for (int j = 0; j < 8; j++)
            #pragma unroll
            for (int k = 0; k < 4; k++) acc[i][j][k] = 0.f;

    // global->smem: 2048 16B segments per chunk, 8 per thread
    int gl_t[8], gl_row[8], gl_q[8];
    const __nv_bfloat16* gl_src[8];
    #pragma unroll
    for (int i = 0; i < 8; i++) {
        int idx = i * 256 + tid;
        gl_t[i] = idx >> 9;              // 0: Ah, 1: Al, 2: Bh, 3: Bl
        int rem = idx & 511;
        gl_row[i] = rem >> 2;
        gl_q[i] = rem & 3;
        gl_src[i] = (gl_t[i] == 0) ? Ah : (gl_t[i] == 1) ? Al
                  : (gl_t[i] == 2) ? Bh : Bl;
    }

    auto issue = [&](int c, int st) {
        #pragma unroll
        for (int i = 0; i < 8; i++) {
            int grow = (gl_t[i] < 2) ? (m0 + gl_row[i]) : (j0 + gl_row[i]);
            const __nv_bfloat16* src = gl_src[i] + (size_t)grow * 2048 + c * 32 + gl_q[i] * 8;
            uint32_t dst = sbase +
                (uint32_t)(st * SSTG + gl_t[i] * 5120 + gl_row[i] * 40 + gl_q[i] * 8) * 2;
            CP_ASYNC16(dst, src);
        }
        CP_COMMIT();
    };

    issue(0, 0);
    for (int c = 0; c < 64; c++) {
        if (c < 63) { issue(c + 1, (c + 1) & 1); CP_WAIT(1); }
        else        { CP_WAIT(0); }
        __syncthreads();
        const uint32_t stg = sbase + (uint32_t)((c & 1) * SSTG) * 2;

        #pragma unroll
        for (int s = 0; s < 2; s++) {
            const uint32_t kcol = (uint32_t)(s * 16 + lhalf) * 2;   // bytes
            uint32_t ah[2][4], al[2][4], bhf[4][4], blf[4][4];
            #pragma unroll
            for (int i = 0; i < 2; i++) {
                uint32_t ar = stg + (uint32_t)((wr * 32 + i * 16 + l15) * 40) * 2 + kcol;
                LDSM_X4(ah[i], ar);
                LDSM_X4(al[i], ar + (uint32_t)5120 * 2);
            }
            #pragma unroll
            for (int p = 0; p < 4; p++) {
                uint32_t br = stg + (uint32_t)(2 * 5120 + (wc * 64 + p * 16 + l15) * 40) * 2 + kcol;
                LDSM_X4(bhf[p], br);
                LDSM_X4(blf[p], br + (uint32_t)5120 * 2);
            }
            // pass 1: Ah x Bh — 16 independent MMAs
            #pragma unroll
            for (int i = 0; i < 2; i++)
                #pragma unroll
                for (int t = 0; t < 8; t++) {
                    const int p = t >> 1, sel = t & 1;
                    MMA16816(acc[i][t], ah[i], bhf[p][sel], bhf[p][sel + 2]);
                }
            // pass 2: Ah x Bl — 16 independent MMAs
            #pragma unroll
            for (int i = 0; i < 2; i++)
                #pragma unroll
                for (int t = 0; t < 8; t++) {
                    const int p = t >> 1, sel = t & 1;
                    MMA16816(acc[i][t], ah[i], blf[p][sel], blf[p][sel + 2]);
                }
            // pass 3: Al x Bh — 16 independent MMAs
            #pragma unroll
            for (int i = 0; i < 2; i++)
                #pragma unroll
                for (int t = 0; t < 8; t++) {
                    const int p = t >> 1, sel = t & 1;
                    MMA16816(acc[i][t], al[i], bhf[p][sel], bhf[p][sel + 2]);
                }
        }
        __syncthreads();
    }

    // epilogue
    const int gr = lane >> 2;
    const int lane2 = (lane & 3) * 2;
    if (mode == 0) {
        const int which = j0 >> 11;
        const int h = (j0 >> 7) & 15;
        const int b = m0 >> 12;
        float* slab = ((which == 0) ? g_q : (which == 1) ? g_kf : g_v)
                    + (size_t)(b * 16 + h) * 4096 * 128;
        #pragma unroll
        for (int i = 0; i < 2; i++) {
            int n = (m0 & 4095) + wr * 32 + i * 16 + gr;
            #pragma unroll
            for (int t = 0; t < 8; t++) {
                int col = wc * 64 + t * 8 + lane2;
                float* dst = slab + (size_t)n * 128 + col;
                *(float2*)dst = make_float2(acc[i][t][0], acc[i][t][1]);
                *(float2*)(dst + 8 * 128) = make_float2(acc[i][t][2], acc[i][t][3]);
            }
        }
    } else {
        #pragma unroll
        for (int i = 0; i < 2; i++) {
            int m = m0 + wr * 32 + i * 16 + gr;
            #pragma unroll
            for (int t = 0; t < 8; t++) {
                int col = j0 + wc * 64 + t * 8 + lane2;
                float* dst = Cout + (size_t)m * 2048 + col;
                *(float2*)dst = make_float2(acc[i][t][0], acc[i][t][1]);
                *(float2*)(dst + 8 * 2048) = make_float2(acc[i][t][2], acc[i][t][3]);
            }
        }
    }
}

// ======================= mean over N =======================
__global__ void k_meanpart(const float* __restrict__ x) {
    int gid = blockIdx.x * 256 + threadIdx.x;
    int sp = gid >> 13;
    int r  = gid & 8191;
    int b = r >> 11, d = r & 2047;
    float s = 0.f;
    int nbeg = sp * 512;
    #pragma unroll 4
    for (int n = nbeg; n < nbeg + 512; n++)
        s += x[(size_t)(b * N_ + n) * DIM_ + d];
    g_meanpart[gid] = s;
}

__global__ void k_meanred() {
    int r = blockIdx.x * 256 + threadIdx.x;
    float s = 0.f;
    #pragma unroll
    for (int sp = 0; sp < 8; sp++) s += g_meanpart[sp * 8192 + r];
    g_mean[r] = s * (1.f / 4096.f);
}

// ======================= gating MLP =======================
__global__ void k_mlp1(const float* __restrict__ f1_w, const float* __restrict__ f1_b) {
    __shared__ float xm[2048];
    int b = blockIdx.x;
    for (int i = threadIdx.x; i < 2048; i += 256) xm[i] = g_mean[b * 2048 + i];
    __syncthreads();
    int j = blockIdx.y * 256 + threadIdx.x;
    float s = 0.f;
    for (int k = 0; k < 2048; k++)
        s = fmaf(xm[k], f1_w[(size_t)k * 1024 + j], s);
    s += f1_b[j];
    g_h1[b * 1024 + j] = s / (1.f + expf(-s));
}

__global__ void k_mlp2(const float* __restrict__ f2_w, const float* __restrict__ f2_b,
                       float* __restrict__ dout) {
    __shared__ float red[128];
    int bh = blockIdx.x;
    int b = bh >> 4, h = bh & 15;
    float s = 0.f;
    for (int k = threadIdx.x; k < 1024; k += 128)
        s = fmaf(g_h1[b * 1024 + k], f2_w[k * 16 + h], s);
    red[threadIdx.x] = s; __syncthreads();
    for (int off = 64; off > 0; off >>= 1) {
        if (threadIdx.x < off) red[threadIdx.x] += red[threadIdx.x + off];
        __syncthreads();
    }
    if (threadIdx.x == 0) {
        float z = red[0] + f2_b[h];
        dout[OUT_OFF_PSI + bh] = 1.f / (1.f + expf(-z));
    }
}

// ======================= resonance + k_mod + decay split =======================
__global__ __launch_bounds__(256, 2)
void k_res(const float* __restrict__ Wb, const float* __restrict__ fast_slope,
           const float* __restrict__ slow_slope) {
    __shared__ float As[16][132];
    __shared__ float Bs[16][128];
    const int m0 = blockIdx.x * 128;
    const int bh = blockIdx.y;
    const int h = bh & 15;
    float* __restrict__ kslab = g_kf + (size_t)bh * N_ * DK_;
    float* __restrict__ kslow = g_ksl + (size_t)bh * N_ * DK_;
    const float* __restrict__ Wbh = Wb + (size_t)h * DK_ * DK_;
    const int tx = threadIdx.x, ty = threadIdx.y;
    const int tid = ty * 16 + tx;
    float acc[8][8];
    #pragma unroll
    for (int i = 0; i < 8; i++)
        #pragma unroll
        for (int j = 0; j < 8; j++) acc[i][j] = 0.f;

    const int arow = tid >> 2, acol = (tid & 3) * 4;
    const int brow = tid >> 5, bcol = (tid & 31) * 4;

    for (int kt = 0; kt < 128; kt += 16) {
        #pragma unroll
        for (int r = 0; r < 2; r++) {
            int row = arow + r * 64;
            float4 av = *(const float4*)&kslab[(size_t)(m0 + row) * DK_ + kt + acol];
            As[acol + 0][row] = av.x; As[acol + 1][row] = av.y;
            As[acol + 2][row] = av.z; As[acol + 3][row] = av.w;
        }
        #pragma unroll
        for (int r = 0; r < 2; r++) {
            int row = brow + r * 8;
            *(float4*)&Bs[row][bcol] =
                *(const float4*)&Wbh[(size_t)(kt + row) * DK_ + bcol];
        }
        __syncthreads();
        #pragma unroll
        for (int kk = 0; kk < 16; kk++) {
            float a[8], bb[8];
            *(float4*)&a[0]  = *(const float4*)&As[kk][ty * 8];
            *(float4*)&a[4]  = *(const float4*)&As[kk][ty * 8 + 4];
            *(float4*)&bb[0] = *(const float4*)&Bs[kk][tx * 8];
            *(float4*)&bb[4] = *(const float4*)&Bs[kk][tx * 8 + 4];
            #pragma unroll
            for (int i = 0; i < 8; i++)
                #pragma unroll
                for (int j = 0; j < 8; j++)
                    acc[i][j] = fmaf(a[i], bb[j], acc[i][j]);
        }
        __syncthreads();
    }
    const float fs = fast_slope[h], ss = slow_slope[h];
    #pragma unroll
    for (int i = 0; i < 8; i++) {
        int n = m0 + ty * 8 + i;
        float idx = (float)(n - (N_ - 1));
        float fw = expf(fs * idx);
        float sw = expf(ss * idx);
        #pragma unroll
        for (int j = 0; j < 8; j += 4) {
            size_t p = (size_t)n * DK_ + tx * 8 + j;
            float4 kr = *(const float4*)&kslab[p];
            float4 kf4, ks4;
            float r0, km;
            r0 = tanhf(acc[i][j+0]); km = kr.x * (1.f + 0.5f * r0) * INV_SQRT_DK; kf4.x = km * fw; ks4.x = km * sw;
            r0 = tanhf(acc[i][j+1]); km = kr.y * (1.f + 0.5f * r0) * INV_SQRT_DK; kf4.y = km * fw; ks4.y = km * sw;
            r0 = tanhf(acc[i][j+2]); km = kr.z * (1.f + 0.5f * r0) * INV_SQRT_DK; kf4.z = km * fw; ks4.z = km * sw;
            r0 = tanhf(acc[i][j+3]); km = kr.w * (1.f + 0.5f * r0) * INV_SQRT_DK; kf4.w = km * fw; ks4.w = km * sw;
            *(float4*)&kslab[p] = kf4;
            *(float4*)&kslow[p] = ks4;
        }
    }
}

// ======================= M = k^T @ v partials =======================
__global__ __launch_bounds__(256, 2)
void k_mpart() {
    __shared__ float As[16][128];
    __shared__ float Bs[16][128];
    const int split = blockIdx.x;
    const int bh = blockIdx.y;
    const int which = blockIdx.z;
    const float* __restrict__ kslab =
        (which ? g_ksl : g_kf) + (size_t)bh * N_ * DK_ + (size_t)split * 512 * DK_;
    const float* __restrict__ vslab =
        g_v + (size_t)bh * N_ * DK_ + (size_t)split * 512 * DK_;
    const int tx = threadIdx.x, ty = threadIdx.y;
    const int tid = ty * 16 + tx;
    float acc[8][8];
    #pragma unroll
    for (int i = 0; i < 8; i++)
        #pragma unroll
        for (int j = 0; j < 8; j++) acc[i][j] = 0.f;

    const int lrow = tid >> 5, lcol = (tid & 31) * 4;

    for (int nt = 0; nt < 512; nt += 16) {
        #pragma unroll
        for (int r = 0; r < 2; r++) {
            int row = lrow + r * 8;
            *(float4*)&As[row][lcol] = *(const float4*)&kslab[(size_t)(nt + row) * DK_ + lcol];
            *(float4*)&Bs[row][lcol] = *(const float4*)&vslab[(size_t)(nt + row) * DK_ + lcol];
        }
        __syncthreads();
        #pragma unroll
        for (int kk = 0; kk < 16; kk++) {
            float a[8], bb[8];
            *(float4*)&a[0]  = *(const float4*)&As[kk][ty * 8];
            *(float4*)&a[4]  = *(const float4*)&As[kk][ty * 8 + 4];
            *(float4*)&bb[0] = *(const float4*)&Bs[kk][tx * 8];
            *(float4*)&bb[4] = *(const float4*)&Bs[kk][tx * 8 + 4];
            #pragma unroll
            for (int i = 0; i < 8; i++)
                #pragma unroll
                for (int j = 0; j < 8; j++)
                    acc[i][j] = fmaf(a[i], bb[j], acc[i][j]);
        }
        __syncthreads();
    }
    float* dst = g_part + (((size_t)which * BH_ + bh) * 8 + split) * 16384;
    #pragma unroll
    for (int i = 0; i < 8; i++)
        #pragma unroll
        for (int j = 0; j < 8; j += 4) {
            float4 v4 = make_float4(acc[i][j], acc[i][j+1], acc[i][j+2], acc[i][j+3]);
            *(float4*)&dst[(ty * 8 + i) * 128 + tx * 8 + j] = v4;
        }
}

// ======================= M finalize =======================
__global__ void k_mfin(const float* __restrict__ Mf_prev, const float* __restrict__ Ms_prev,
                       const float* __restrict__ inter_fast, const float* __restrict__ inter_slow,
                       float* __restrict__ dout) {
    const int bh = blockIdx.x;
    const int which = blockIdx.y;
    const int h = bh & 15;
    const float inter = which ? inter_slow[h] : inter_fast[h];
    const float* prev = (which ? Ms_prev : Mf_prev) + (size_t)bh * 16384;
    const float* part = g_part + ((size_t)which * BH_ + bh) * 8 * 16384;
    float* dst = dout + (which ? OUT_OFF_MS : OUT_OFF_MF) + (size_t)bh * 16384;
    for (int e = threadIdx.x; e < 16384; e += 256) {
        float s = 0.f;
        #pragma unroll
        for (int sp = 0; sp < 8; sp++) s += part[(size_t)sp * 16384 + e];
        dst[e] = prev[e] * inter + s;
    }
}

// ======================= Mref = (I+S) @ M, blended =======================
__global__ __launch_bounds__(256, 2)
void k_mref(const float* __restrict__ S_fast, const float* __restrict__ S_slow,
            const float* __restrict__ dout, int which) {
    __shared__ float As[16][132];
    __shared__ float Bs[16][128];
    const int bh = blockIdx.x;
    const int h = bh & 15;
    const float* __restrict__ S = (which ? S_slow : S_fast) + (size_t)h * 16384;
    const float* __restrict__ M = dout + (which ? OUT_OFF_MS : OUT_OFF_MF) + (size_t)bh * 16384;
    const int tx = threadIdx.x, ty = threadIdx.y;
    const int tid = ty * 16 + tx;
    float acc[8][8];
    #pragma unroll
    for (int i = 0; i < 8; i++)
        #pragma unroll
        for (int j = 0; j < 8; j++) acc[i][j] = 0.f;

    const int arow = tid >> 2, acol = (tid & 3) * 4;
    const int brow = tid >> 5, bcol = (tid & 31) * 4;

    for (int kt = 0; kt < 128; kt += 16) {
        #pragma unroll
        for (int r = 0; r < 2; r++) {
            int row = arow + r * 64;
            float4 av = *(const float4*)&S[(size_t)row * 128 + kt + acol];
            As[acol + 0][row] = av.x + ((row == kt + acol + 0) ? 1.f : 0.f);
            As[acol + 1][row] = av.y + ((row == kt + acol + 1) ? 1.f : 0.f);
            As[acol + 2][row] = av.z + ((row == kt + acol + 2) ? 1.f : 0.f);
            As[acol + 3][row] = av.w + ((row == kt + acol + 3) ? 1.f : 0.f);
        }
        #pragma unroll
        for (int r = 0; r < 2; r++) {
            int row = brow + r * 8;
            *(float4*)&Bs[row][bcol] = *(const float4*)&M[(size_t)(kt + row) * 128 + bcol];
        }
        __syncthreads();
        #pragma unroll
        for (int kk = 0; kk < 16; kk++) {
            float a[8], bb[8];
            *(float4*)&a[0]  = *(const float4*)&As[kk][ty * 8];
            *(float4*)&a[4]  = *(const float4*)&As[kk][ty * 8 + 4];
            *(float4*)&bb[0] = *(const float4*)&Bs[kk][tx * 8];
            *(float4*)&bb[4] = *(const float4*)&Bs[kk][tx * 8 + 4];
            #pragma unroll
            for (int i = 0; i < 8; i++)
                #pragma unroll
                for (int j = 0; j < 8; j++)
                    acc[i][j] = fmaf(a[i], bb[j], acc[i][j]);
        }
        __syncthreads();
    }
    const float p = dout[OUT_OFF_PSI + bh];
    const float c0 = which ? p : (1.f - p);
    float* dst = g_mblend + (size_t)bh * 16384;
    #pragma unroll
    for (int i = 0; i < 8; i++)
        #pragma unroll
        for (int j = 0; j < 8; j++) {
            int idx = (ty * 8 + i) * 128 + tx * 8 + j;
            if (which == 0) dst[idx] = c0 * acc[i][j];
            else            dst[idx] += c0 * acc[i][j];
        }
}

// ======================= o_blend = q @ M_blend, bf16 split out =======================
__global__ __launch_bounds__(256, 2)
void k_oblend() {
    __shared__ float As[16][132];
    __shared__ float Bs[16][128];
    const int m0 = blockIdx.x * 128;
    const int bh = blockIdx.y;
    const float* __restrict__ qslab = g_q + (size_t)bh * N_ * DK_;
    const float* __restrict__ Mb = g_mblend + (size_t)bh * 16384;
    const int tx = threadIdx.x, ty = threadIdx.y;
    const int tid = ty * 16 + tx;
    float acc[8][8];
    #pragma unroll
    for (int i = 0; i < 8; i++)
        #pragma unroll
        for (int j = 0; j < 8; j++) acc[i][j] = 0.f;

    const int arow = tid >> 2, acol = (tid & 3) * 4;
    const int brow = tid >> 5, bcol = (tid & 31) * 4;

    for (int kt = 0; kt < 128; kt += 16) {
        #pragma unroll
        for (int r = 0; r < 2; r++) {
            int row = arow + r * 64;
            float4 av = *(const float4*)&qslab[(size_t)(m0 + row) * DK_ + kt + acol];
            As[acol + 0][row] = av.x; As[acol + 1][row] = av.y;
            As[acol + 2][row] = av.z; As[acol + 3][row] = av.w;
        }
        #pragma unroll
        for (int r = 0; r < 2; r++) {
            int row = brow + r * 8;
            *(float4*)&Bs[row][bcol] = *(const float4*)&Mb[(size_t)(kt + row) * 128 + bcol];
        }
        __syncthreads();
        #pragma unroll
        for (int kk = 0; kk < 16; kk++) {
            float a[8], bb[8];
            *(float4*)&a[0]  = *(const float4*)&As[kk][ty * 8];
            *(float4*)&a[4]  = *(const float4*)&As[kk][ty * 8 + 4];
            *(float4*)&bb[0] = *(const float4*)&Bs[kk][tx * 8];
            *(float4*)&bb[4] = *(const float4*)&Bs[kk][tx * 8 + 4];
            #pragma unroll
            for (int i = 0; i < 8; i++)
                #pragma unroll
                for (int j = 0; j < 8; j++)
                    acc[i][j] = fmaf(a[i], bb[j], acc[i][j]);
        }
        __syncthreads();
    }
    const int b = bh >> 4, h = bh & 15;
    #pragma unroll
    for (int i = 0; i < 8; i++) {
        int n = m0 + ty * 8 + i;
        size_t base = ((size_t)(b * N_ + n) * H_ + h) * DK_ + tx * 8;
        #pragma unroll
        for (int j = 0; j < 8; j++) {
            float v = acc[i][j];
            __nv_bfloat16 hi = __float2bfloat16_rn(v);
            __nv_bfloat16 lo = __float2bfloat16_rn(v - __bfloat162float(hi));
            g_obh[base + j] = hi; g_obl[base + j] = lo;
        }
    }
}

// ======================= launch =======================
extern "C" void kernel_launch(void* const* d_in, const int* in_sizes, int n_in,
                              void* d_out, int out_size) {
    (void)in_sizes; (void)n_in; (void)out_size;
    const float* x          = (const float*)d_in[0];
    const float* Mf_prev    = (const float*)d_in[1];
    const float* Ms_prev    = (const float*)d_in[2];
    const float* Wq         = (const float*)d_in[3];
    const float* Wk         = (const float*)d_in[4];
    const float* Wv         = (const float*)d_in[5];
    const float* Wo         = (const float*)d_in[6];
    const float* Wb         = (const float*)d_in[7];
    const float* fast_slope = (const float*)d_in[8];
    const float* slow_slope = (const float*)d_in[9];
    const float* inter_fast = (const float*)d_in[10];
    const float* inter_slow = (const float*)d_in[11];
    const float* S_fast     = (const float*)d_in[12];
    const float* S_slow     = (const float*)d_in[13];
    const float* f1_w       = (const float*)d_in[14];
    const float* f1_b       = (const float*)d_in[15];
    const float* f2_w       = (const float*)d_in[16];
    const float* f2_b       = (const float*)d_in[17];
    float* out = (float*)d_out;

    const int gemm_smem = 2 * SSTG * 2;   // 81920 bytes
    static bool attr_set = false;
    if (!attr_set) {
        cudaFuncSetAttribute(k_mma_gemm, cudaFuncAttributeMaxDynamicSharedMemorySize, gemm_smem);
        attr_set = true;
    }

    dim3 t16(16, 16);
    dim3 t328(32, 8);

    // prep: bf16 splits
    k_split_x<<<32768, 256>>>(x);
    k_wsplit_qkv<<<dim3(64, 192), t328>>>(Wq, Wk, Wv);
    k_wsplit_o<<<dim3(64, 64), t328>>>(Wo);

    // gating path
    k_meanpart<<<256, 256>>>(x);
    k_meanred<<<32, 256>>>();
    k_mlp1<<<dim3(4, 4), 256>>>(f1_w, f1_b);
    k_mlp2<<<64, 128>>>(f2_w, f2_b, out);

    // QKV projection (HMMA, grid: x=j-blocks, y=m-blocks)
    k_mma_gemm<<<dim3(48, 128), 256, gemm_smem>>>(nullptr, 0);

    // per-head path
    k_res<<<dim3(32, 64), t16>>>(Wb, fast_slope, slow_slope);
    k_mpart<<<dim3(8, 64, 2), t16>>>();
    k_mfin<<<dim3(64, 2), 256>>>(Mf_prev, Ms_prev, inter_fast, inter_slow, out);
    k_mref<<<64, t16>>>(S_fast, S_slow, out, 0);
    k_mref<<<64, t16>>>(S_fast, S_slow, out, 1);
    k_oblend<<<dim3(32, 64), t16>>>();

    // output projection (HMMA)
    k_mma_gemm<<<dim3(16, 128), 256, gemm_smem>>>(out, 1);
}

// round 9
// speedup vs baseline: 1.8127x; 1.0739x over previous
#include <cuda_runtime.h>
#include <cuda_bf16.h>
#include <cstdint>
#include <math.h>

static constexpr int B_   = 4;
static constexpr int N_   = 4096;
static constexpr int H_   = 16;
static constexpr int DK_  = 128;
static constexpr int DIM_ = 2048;
static constexpr int BH_  = B_ * H_;      // 64
static constexpr int MROWS_ = B_ * N_;    // 16384
static constexpr float INV_SQRT_DK = 0.08838834764831843f;
static constexpr size_t SLAB = (size_t)N_ * DK_;   // 524288 per bh

static constexpr long long OUT_OFF_MF  = 33554432LL;
static constexpr long long OUT_OFF_MS  = 34603008LL;
static constexpr long long OUT_OFF_PSI = 35651584LL;

// ---------------- scratch (allocation-free: device globals) ----------------
__device__ float g_kf [(size_t)BH_ * SLAB];       // raw k fp32 (for k_res)
__device__ float g_part[2LL * BH_ * 8 * DK_ * DK_];
__device__ float g_mblend[(size_t)BH_ * DK_ * DK_];
__device__ float g_meanpart[8 * B_ * DIM_];
__device__ float g_mean[B_ * DIM_];
__device__ float g_h1[B_ * 1024];

// bf16 split operands
__device__ __nv_bfloat16 g_xh [(size_t)MROWS_ * DIM_];
__device__ __nv_bfloat16 g_xl [(size_t)MROWS_ * DIM_];
__device__ __nv_bfloat16 g_wqkvh[(size_t)6144 * 2048];
__device__ __nv_bfloat16 g_wqkvl[(size_t)6144 * 2048];
__device__ __nv_bfloat16 g_woh [(size_t)2048 * 2048];
__device__ __nv_bfloat16 g_wol [(size_t)2048 * 2048];
__device__ __nv_bfloat16 g_obh [(size_t)MROWS_ * DIM_];
__device__ __nv_bfloat16 g_obl [(size_t)MROWS_ * DIM_];
// per-head bf16 split tensors [bh][n][d]
__device__ __nv_bfloat16 g_qh [(size_t)BH_ * SLAB];
__device__ __nv_bfloat16 g_ql [(size_t)BH_ * SLAB];
__device__ __nv_bfloat16 g_vh [(size_t)BH_ * SLAB];
__device__ __nv_bfloat16 g_vl [(size_t)BH_ * SLAB];
__device__ __nv_bfloat16 g_kfh[(size_t)BH_ * SLAB];
__device__ __nv_bfloat16 g_kfl[(size_t)BH_ * SLAB];
__device__ __nv_bfloat16 g_ksh[(size_t)BH_ * SLAB];
__device__ __nv_bfloat16 g_ksl[(size_t)BH_ * SLAB];
// blended state matrix bf16 split [bh][d][v]
__device__ __nv_bfloat16 g_mbh[(size_t)BH_ * DK_ * DK_];
__device__ __nv_bfloat16 g_mbl[(size_t)BH_ * DK_ * DK_];

// ===================== mma.sync helpers (base-target PTX) ==================
__device__ __forceinline__ uint32_t smem_u32(const void* p) {
    uint32_t a;
    asm("{ .reg .u64 t; cvta.to.shared.u64 t, %1; cvt.u32.u64 %0, t; }"
        : "=r"(a) : "l"(p));
    return a;
}

#define MMA16816(d, a, b0, b1) \
    asm volatile("mma.sync.aligned.m16n8k16.row.col.f32.bf16.bf16.f32 " \
        "{%0,%1,%2,%3}, {%4,%5,%6,%7}, {%8,%9}, {%0,%1,%2,%3};" \
        : "+f"((d)[0]), "+f"((d)[1]), "+f"((d)[2]), "+f"((d)[3]) \
        : "r"((a)[0]), "r"((a)[1]), "r"((a)[2]), "r"((a)[3]), "r"(b0), "r"(b1))

#define LDSM_X4(r, addr) \
    asm volatile("ldmatrix.sync.aligned.m8n8.x4.shared.b16 {%0,%1,%2,%3}, [%4];" \
        : "=r"((r)[0]), "=r"((r)[1]), "=r"((r)[2]), "=r"((r)[3]) : "r"(addr))

#define LDSM_X4_T(r, addr) \
    asm volatile("ldmatrix.sync.aligned.m8n8.x4.trans.shared.b16 {%0,%1,%2,%3}, [%4];" \
        : "=r"((r)[0]), "=r"((r)[1]), "=r"((r)[2]), "=r"((r)[3]) : "r"(addr))

#define CP_ASYNC16(dst, src) \
    asm volatile("cp.async.cg.shared.global [%0], [%1], 16;" \
        :: "r"(dst), "l"(src) : "memory")
#define CP_COMMIT() asm volatile("cp.async.commit_group;" ::: "memory")
#define CP_WAIT(n)  asm volatile("cp.async.wait_group %0;" :: "n"(n) : "memory")

__device__ __forceinline__ void split2w(float a, float b,
                                        __nv_bfloat16* ph, __nv_bfloat16* pl) {
    __nv_bfloat16 h0 = __float2bfloat16_rn(a), h1 = __float2bfloat16_rn(b);
    __nv_bfloat16 l0 = __float2bfloat16_rn(a - __bfloat162float(h0));
    __nv_bfloat16 l1 = __float2bfloat16_rn(b - __bfloat162float(h1));
    __nv_bfloat162 hh; hh.x = h0; hh.y = h1;
    __nv_bfloat162 ll; ll.x = l0; ll.y = l1;
    *(__nv_bfloat162*)ph = hh;
    *(__nv_bfloat162*)pl = ll;
}

// ======================= bf16 split / transpose prep =======================
__global__ void k_split_x(const float* __restrict__ x) {
    size_t i = ((size_t)blockIdx.x * 256 + threadIdx.x) * 4;
    float4 v = *(const float4*)(x + i);
    float a[4] = {v.x, v.y, v.z, v.w};
    #pragma unroll
    for (int j = 0; j < 4; j++) {
        __nv_bfloat16 hi = __float2bfloat16_rn(a[j]);
        __nv_bfloat16 lo = __float2bfloat16_rn(a[j] - __bfloat162float(hi));
        g_xh[i + j] = hi; g_xl[i + j] = lo;
    }
}

__global__ void k_wsplit_qkv(const float* __restrict__ Wq, const float* __restrict__ Wk,
                             const float* __restrict__ Wv) {
    __shared__ float tile[32][33];
    int k0 = blockIdx.x * 32, n0 = blockIdx.y * 32;
    int which = n0 >> 11;
    const float* __restrict__ W = (which == 0) ? Wq : (which == 1 ? Wk : Wv);
    int nn0 = n0 & 2047;
    for (int r = threadIdx.y; r < 32; r += 8)
        tile[r][threadIdx.x] = W[(size_t)(k0 + r) * 2048 + nn0 + threadIdx.x];
    __syncthreads();
    for (int r = threadIdx.y; r < 32; r += 8) {
        float v = tile[threadIdx.x][r];
        __nv_bfloat16 hi = __float2bfloat16_rn(v);
        __nv_bfloat16 lo = __float2bfloat16_rn(v - __bfloat162float(hi));
        size_t o = (size_t)(n0 + r) * 2048 + k0 + threadIdx.x;
        g_wqkvh[o] = hi; g_wqkvl[o] = lo;
    }
}

__global__ void k_wsplit_o(const float* __restrict__ Wo) {
    __shared__ float tile[32][33];
    int k0 = blockIdx.x * 32, n0 = blockIdx.y * 32;
    for (int r = threadIdx.y; r < 32; r += 8)
        tile[r][threadIdx.x] = Wo[(size_t)(k0 + r) * 2048 + n0 + threadIdx.x];
    __syncthreads();
    for (int r = threadIdx.y; r < 32; r += 8) {
        float v = tile[threadIdx.x][r];
        __nv_bfloat16 hi = __float2bfloat16_rn(v);
        __nv_bfloat16 lo = __float2bfloat16_rn(v - __bfloat162float(hi));
        size_t o = (size_t)(n0 + r) * 2048 + k0 + threadIdx.x;
        g_woh[o] = hi; g_wol[o] = lo;
    }
}

// ======================= main HMMA GEMM (unchanged core) =====================
static constexpr int SSTG = 4 * 128 * 40;

__global__ __launch_bounds__(256)
void k_mma_gemm(float* __restrict__ Cout, int mode) {
    extern __shared__ __align__(16) __nv_bfloat16 smb[];
    const __nv_bfloat16* __restrict__ Ah;
    const __nv_bfloat16* __restrict__ Al;
    const __nv_bfloat16* __restrict__ Bh;
    const __nv_bfloat16* __restrict__ Bl;
    if (mode == 0) { Ah = g_xh;  Al = g_xl;  Bh = g_wqkvh; Bl = g_wqkvl; }
    else           { Ah = g_obh; Al = g_obl; Bh = g_woh;   Bl = g_wol;   }

    const uint32_t sbase = smem_u32(smb);
    const int tid = threadIdx.x;
    const int wid = tid >> 5, lane = tid & 31;
    const int wr = wid >> 1, wc = wid & 1;
    const int j0 = blockIdx.x * 128;
    const int m0 = blockIdx.y * 128;
    const int l15 = lane & 15;
    const int lhalf = (lane >> 4) * 8;

    float acc[2][8][4];
    #pragma unroll
    for (int i = 0; i < 2; i++)
        #pragma unroll
        for (int j = 0; j < 8; j++)
            #pragma unroll
            for (int k = 0; k < 4; k++) acc[i][j][k] = 0.f;

    int gl_t[8], gl_row[8], gl_q[8];
    const __nv_bfloat16* gl_src[8];
    #pragma unroll
    for (int i = 0; i < 8; i++) {
        int idx = i * 256 + tid;
        gl_t[i] = idx >> 9;
        int rem = idx & 511;
        gl_row[i] = rem >> 2;
        gl_q[i] = rem & 3;
        gl_src[i] = (gl_t[i] == 0) ? Ah : (gl_t[i] == 1) ? Al
                  : (gl_t[i] == 2) ? Bh : Bl;
    }

    auto issue = [&](int c, int st) {
        #pragma unroll
        for (int i = 0; i < 8; i++) {
            int grow = (gl_t[i] < 2) ? (m0 + gl_row[i]) : (j0 + gl_row[i]);
            const __nv_bfloat16* src = gl_src[i] + (size_t)grow * 2048 + c * 32 + gl_q[i] * 8;
            uint32_t dst = sbase +
                (uint32_t)(st * SSTG + gl_t[i] * 5120 + gl_row[i] * 40 + gl_q[i] * 8) * 2;
            CP_ASYNC16(dst, src);
        }
        CP_COMMIT();
    };

    issue(0, 0);
    for (int c = 0; c < 64; c++) {
        if (c < 63) { issue(c + 1, (c + 1) & 1); CP_WAIT(1); }
        else        { CP_WAIT(0); }
        __syncthreads();
        const uint32_t stg = sbase + (uint32_t)((c & 1) * SSTG) * 2;

        #pragma unroll
        for (int s = 0; s < 2; s++) {
            const uint32_t kcol = (uint32_t)(s * 16 + lhalf) * 2;
            uint32_t ah[2][4], al[2][4], bhf[4][4], blf[4][4];
            #pragma unroll
            for (int i = 0; i < 2; i++) {
                uint32_t ar = stg + (uint32_t)((wr * 32 + i * 16 + l15) * 40) * 2 + kcol;
                LDSM_X4(ah[i], ar);
                LDSM_X4(al[i], ar + (uint32_t)5120 * 2);
            }
            #pragma unroll
            for (int p = 0; p < 4; p++) {
                uint32_t br = stg + (uint32_t)(2 * 5120 + (wc * 64 + p * 16 + l15) * 40) * 2 + kcol;
                LDSM_X4(bhf[p], br);
                LDSM_X4(blf[p], br + (uint32_t)5120 * 2);
            }
            #pragma unroll
            for (int i = 0; i < 2; i++)
                #pragma unroll
                for (int t = 0; t < 8; t++) {
                    const int p = t >> 1, sel = t & 1;
                    MMA16816(acc[i][t], ah[i], bhf[p][sel], bhf[p][sel + 2]);
                }
            #pragma unroll
            for (int i = 0; i < 2; i++)
                #pragma unroll
                for (int t = 0; t < 8; t++) {
                    const int p = t >> 1, sel = t & 1;
                    MMA16816(acc[i][t], ah[i], blf[p][sel], blf[p][sel + 2]);
                }
            #pragma unroll
            for (int i = 0; i < 2; i++)
                #pragma unroll
                for (int t = 0; t < 8; t++) {
                    const int p = t >> 1, sel = t & 1;
                    MMA16816(acc[i][t], al[i], bhf[p][sel], bhf[p][sel + 2]);
                }
        }
        __syncthreads();
    }

    const int gr = lane >> 2;
    const int lane2 = (lane & 3) * 2;
    if (mode == 0) {
        const int which = j0 >> 11;
        const int h = (j0 >> 7) & 15;
        const int b = m0 >> 12;
        const size_t slab = (size_t)(b * 16 + h) * SLAB;
        if (which == 1) {
            float* dst0 = g_kf + slab;
            #pragma unroll
            for (int i = 0; i < 2; i++) {
                int n = (m0 & 4095) + wr * 32 + i * 16 + gr;
                #pragma unroll
                for (int t = 0; t < 8; t++) {
                    int col = wc * 64 + t * 8 + lane2;
                    float* dst = dst0 + (size_t)n * 128 + col;
                    *(float2*)dst = make_float2(acc[i][t][0], acc[i][t][1]);
                    *(float2*)(dst + 8 * 128) = make_float2(acc[i][t][2], acc[i][t][3]);
                }
            }
        } else {
            __nv_bfloat16* dh = ((which == 0) ? g_qh : g_vh) + slab;
            __nv_bfloat16* dl = ((which == 0) ? g_ql : g_vl) + slab;
            #pragma unroll
            for (int i = 0; i < 2; i++) {
                int n = (m0 & 4095) + wr * 32 + i * 16 + gr;
                #pragma unroll
                for (int t = 0; t < 8; t++) {
                    int col = wc * 64 + t * 8 + lane2;
                    size_t o0 = (size_t)n * 128 + col;
                    split2w(acc[i][t][0], acc[i][t][1], dh + o0, dl + o0);
                    split2w(acc[i][t][2], acc[i][t][3], dh + o0 + 8 * 128, dl + o0 + 8 * 128);
                }
            }
        }
    } else {
        #pragma unroll
        for (int i = 0; i < 2; i++) {
            int m = m0 + wr * 32 + i * 16 + gr;
            #pragma unroll
            for (int t = 0; t < 8; t++) {
                int col = j0 + wc * 64 + t * 8 + lane2;
                float* dst = Cout + (size_t)m * 2048 + col;
                *(float2*)dst = make_float2(acc[i][t][0], acc[i][t][1]);
                *(float2*)(dst + 8 * 2048) = make_float2(acc[i][t][2], acc[i][t][3]);
            }
        }
    }
}

// ======================= k_mpart HMMA: M_partial = k^T @ v ===================
// A = k^T via ldmatrix.trans of k[n][d]; B = v^T-frags via trans of v[n][v].
// CTA: full 128(d) x 128(v), K = 512 n-rows (split 8), BK=32, 2-stage.
// Smem tiles [32][136] (272B stride -> conflict-free trans ldmatrix).
static constexpr int MP_STG = 4 * 32 * 136;          // 17408 elems per stage

__global__ __launch_bounds__(256)
void k_mpart_mma() {
    extern __shared__ __align__(16) __nv_bfloat16 smb[];
    const int split = blockIdx.x, bh = blockIdx.y, which = blockIdx.z;
    const __nv_bfloat16* srcs[4] = {
        ((which ? g_ksh : g_kfh) + (size_t)bh * SLAB),
        ((which ? g_ksl : g_kfl) + (size_t)bh * SLAB),
        (g_vh + (size_t)bh * SLAB),
        (g_vl + (size_t)bh * SLAB)
    };
    const uint32_t sbase = smem_u32(smb);
    const int tid = threadIdx.x;
    const int wid = tid >> 5, lane = tid & 31;
    const int wr = wid >> 1, wc = wid & 1;

    float acc[2][8][4];
    #pragma unroll
    for (int i = 0; i < 2; i++)
        #pragma unroll
        for (int j = 0; j < 8; j++)
            #pragma unroll
            for (int k = 0; k < 4; k++) acc[i][j][k] = 0.f;

    // 2048 16B segs per chunk: tile t(4) x row r(32) x q(16)
    int gl_t[8], gl_r[8], gl_q[8];
    #pragma unroll
    for (int i = 0; i < 8; i++) {
        int idx = i * 256 + tid;
        gl_t[i] = idx >> 9;
        int rem = idx & 511;
        gl_r[i] = rem >> 4;
        gl_q[i] = rem & 15;
    }

    auto issue = [&](int c, int st) {
        #pragma unroll
        for (int i = 0; i < 8; i++) {
            const __nv_bfloat16* src = srcs[gl_t[i]]
                + (size_t)(split * 512 + c * 32 + gl_r[i]) * 128 + gl_q[i] * 8;
            uint32_t dst = sbase +
                (uint32_t)(st * MP_STG + gl_t[i] * 4352 + gl_r[i] * 136 + gl_q[i] * 8) * 2;
            CP_ASYNC16(dst, src);
        }
        CP_COMMIT();
    };

    const int rofs = (lane & 7) + ((lane >> 4) << 3);   // trans row within k16
    const int cofs = (lane & 8);                        // trans col half

    issue(0, 0);
    for (int c = 0; c < 16; c++) {
        if (c < 15) { issue(c + 1, (c + 1) & 1); CP_WAIT(1); }
        else        { CP_WAIT(0); }
        __syncthreads();
        const uint32_t stg = sbase + (uint32_t)((c & 1) * MP_STG) * 2;

        #pragma unroll
        for (int ks = 0; ks < 2; ks++) {
            const int rowk = ks * 16 + rofs;
            uint32_t ah[2][4], al[2][4], bhf[4][4], blf[4][4];
            #pragma unroll
            for (int i = 0; i < 2; i++) {
                uint32_t ad = stg + (uint32_t)(rowk * 136 + wr * 32 + i * 16 + cofs) * 2;
                LDSM_X4_T(ah[i], ad);                       // kh tile (offset 0)
                LDSM_X4_T(al[i], ad + (uint32_t)4352 * 2);  // kl
            }
            #pragma unroll
            for (int p = 0; p < 4; p++) {
                uint32_t bd = stg + (uint32_t)(2 * 4352 + rowk * 136 + wc * 64 + p * 16 + cofs) * 2;
                LDSM_X4_T(bhf[p], bd);                      // vh
                LDSM_X4_T(blf[p], bd + (uint32_t)4352 * 2); // vl
            }
            #pragma unroll
            for (int i = 0; i < 2; i++)
                #pragma unroll
                for (int t = 0; t < 8; t++) {
                    const int p = t >> 1, sel = t & 1;
                    MMA16816(acc[i][t], ah[i], bhf[p][sel], bhf[p][sel + 2]);
                }
            #pragma unroll
            for (int i = 0; i < 2; i++)
                #pragma unroll
                for (int t = 0; t < 8; t++) {
                    const int p = t >> 1, sel = t & 1;
                    MMA16816(acc[i][t], ah[i], blf[p][sel], blf[p][sel + 2]);
                }
            #pragma unroll
            for (int i = 0; i < 2; i++)
                #pragma unroll
                for (int t = 0; t < 8; t++) {
                    const int p = t >> 1, sel = t & 1;
                    MMA16816(acc[i][t], al[i], bhf[p][sel], bhf[p][sel + 2]);
                }
        }
        __syncthreads();
    }

    const int gr = lane >> 2;
    const int lane2 = (lane & 3) * 2;
    float* dst0 = g_part + (((size_t)which * BH_ + bh) * 8 + split) * 16384;
    #pragma unroll
    for (int i = 0; i < 2; i++) {
        int m = wr * 32 + i * 16 + gr;                   // d
        #pragma unroll
        for (int t = 0; t < 8; t++) {
            int col = wc * 64 + t * 8 + lane2;           // v
            float* dst = dst0 + m * 128 + col;
            *(float2*)dst = make_float2(acc[i][t][0], acc[i][t][1]);
            *(float2*)(dst + 8 * 128) = make_float2(acc[i][t][2], acc[i][t][3]);
        }
    }
}

// ======================= k_oblend HMMA: o = q @ Mb, bf16 split out ==========
// A = q[n][d] (non-trans, stride 40); B = Mb^T-frags via trans of Mb[d][v].
static constexpr int OB_STG = 2 * 128 * 40 + 2 * 32 * 136;   // 18944 elems

__global__ __launch_bounds__(256)
void k_oblend_mma() {
    extern __shared__ __align__(16) __nv_bfloat16 smb[];
    const int bh = blockIdx.y;
    const int m0 = blockIdx.x * 128;
    const __nv_bfloat16* qsrc[2] = { g_qh + (size_t)bh * SLAB, g_ql + (size_t)bh * SLAB };
    const __nv_bfloat16* msrc[2] = { g_mbh + (size_t)bh * 16384, g_mbl + (size_t)bh * 16384 };
    const uint32_t sbase = smem_u32(smb);
    const int tid = threadIdx.x;
    const int wid = tid >> 5, lane = tid & 31;
    const int wr = wid >> 1, wc = wid & 1;
    const int l15 = lane & 15;
    const int lhalf = (lane >> 4) * 8;

    float acc[2][8][4];
    #pragma unroll
    for (int i = 0; i < 2; i++)
        #pragma unroll
        for (int j = 0; j < 8; j++)
            #pragma unroll
            for (int k = 0; k < 4; k++) acc[i][j][k] = 0.f;

    // segs: q 2x128x4 = 1024, mb 2x32x16 = 1024
    int gA[8], gl_r[8], gl_q[8];
    #pragma unroll
    for (int i = 0; i < 8; i++) {
        int idx = i * 256 + tid;
        if (idx < 1024) {
            gA[i] = idx >> 9;                 // 0=qh,1=ql
            int rem = idx & 511;
            gl_r[i] = rem >> 2; gl_q[i] = rem & 3;
        } else {
            gA[i] = 2 + ((idx - 1024) >> 9);  // 2=mbh,3=mbl
            int rem = (idx - 1024) & 511;
            gl_r[i] = rem >> 4; gl_q[i] = rem & 15;
        }
    }

    auto issue = [&](int c, int st) {
        #pragma unroll
        for (int i = 0; i < 8; i++) {
            const __nv_bfloat16* src;
            uint32_t soff;
            if (gA[i] < 2) {
                src = qsrc[gA[i]] + (size_t)(m0 + gl_r[i]) * 128 + c * 32 + gl_q[i] * 8;
                soff = (uint32_t)(gA[i] * 5120 + gl_r[i] * 40 + gl_q[i] * 8);
            } else {
                src = msrc[gA[i] - 2] + (size_t)(c * 32 + gl_r[i]) * 128 + gl_q[i] * 8;
                soff = (uint32_t)(10240 + (gA[i] - 2) * 4352 + gl_r[i] * 136 + gl_q[i] * 8);
            }
            CP_ASYNC16(sbase + (uint32_t)(st * OB_STG) * 2 + soff * 2, src);
        }
        CP_COMMIT();
    };

    const int rofs = (lane & 7) + ((lane >> 4) << 3);
    const int cofs = (lane & 8);

    issue(0, 0);
    for (int c = 0; c < 4; c++) {
        if (c < 3) { issue(c + 1, (c + 1) & 1); CP_WAIT(1); }
        else       { CP_WAIT(0); }
        __syncthreads();
        const uint32_t stg = sbase + (uint32_t)((c & 1) * OB_STG) * 2;

        #pragma unroll
        for (int s = 0; s < 2; s++) {
            const uint32_t kcol = (uint32_t)(s * 16 + lhalf) * 2;
            const int rowd = s * 16 + rofs;
            uint32_t ah[2][4], al[2][4], bhf[4][4], blf[4][4];
            #pragma unroll
            for (int i = 0; i < 2; i++) {
                uint32_t ar = stg + (uint32_t)((wr * 32 + i * 16 + l15) * 40) * 2 + kcol;
                LDSM_X4(ah[i], ar);
                LDSM_X4(al[i], ar + (uint32_t)5120 * 2);
            }
            #pragma unroll
            for (int p = 0; p < 4; p++) {
                uint32_t bd = stg + (uint32_t)(10240 + rowd * 136 + wc * 64 + p * 16 + cofs) * 2;
                LDSM_X4_T(bhf[p], bd);
                LDSM_X4_T(blf[p], bd + (uint32_t)4352 * 2);
            }
            #pragma unroll
            for (int i = 0; i < 2; i++)
                #pragma unroll
                for (int t = 0; t < 8; t++) {
                    const int p = t >> 1, sel = t & 1;
                    MMA16816(acc[i][t], ah[i], bhf[p][sel], bhf[p][sel + 2]);
                }
            #pragma unroll
            for (int i = 0; i < 2; i++)
                #pragma unroll
                for (int t = 0; t < 8; t++) {
                    const int p = t >> 1, sel = t & 1;
                    MMA16816(acc[i][t], ah[i], blf[p][sel], blf[p][sel + 2]);
                }
            #pragma unroll
            for (int i = 0; i < 2; i++)
                #pragma unroll
                for (int t = 0; t < 8; t++) {
                    const int p = t >> 1, sel = t & 1;
                    MMA16816(acc[i][t], al[i], bhf[p][sel], bhf[p][sel + 2]);
                }
        }
        __syncthreads();
    }

    const int gr = lane >> 2;
    const int lane2 = (lane & 3) * 2;
    const int b = bh >> 4, h = bh & 15;
    #pragma unroll
    for (int i = 0; i < 2; i++) {
        int n = m0 + wr * 32 + i * 16 + gr;
        #pragma unroll
        for (int t = 0; t < 8; t++) {
            int col = wc * 64 + t * 8 + lane2;
            size_t b0 = ((size_t)(b * 4096 + n) * 16 + h) * 128 + col;
            size_t b8 = ((size_t)(b * 4096 + n + 8) * 16 + h) * 128 + col;
            split2w(acc[i][t][0], acc[i][t][1], g_obh + b0, g_obl + b0);
            split2w(acc[i][t][2], acc[i][t][3], g_obh + b8, g_obl + b8);
        }
    }
}

// ======================= mean over N =======================
__global__ void k_meanpart(const float* __restrict__ x) {
    int gid = blockIdx.x * 256 + threadIdx.x;
    int sp = gid >> 13;
    int r  = gid & 8191;
    int b = r >> 11, d = r & 2047;
    float s = 0.f;
    int nbeg = sp * 512;
    #pragma unroll 4
    for (int n = nbeg; n < nbeg + 512; n++)
        s += x[(size_t)(b * N_ + n) * DIM_ + d];
    g_meanpart[gid] = s;
}

__global__ void k_meanred() {
    int r = blockIdx.x * 256 + threadIdx.x;
    float s = 0.f;
    #pragma unroll
    for (int sp = 0; sp < 8; sp++) s += g_meanpart[sp * 8192 + r];
    g_mean[r] = s * (1.f / 4096.f);
}

// ======================= gating MLP =======================
__global__ void k_mlp1(const float* __restrict__ f1_w, const float* __restrict__ f1_b) {
    __shared__ float xm[2048];
    int b = blockIdx.x;
    for (int i = threadIdx.x; i < 2048; i += 256) xm[i] = g_mean[b * 2048 + i];
    __syncthreads();
    int j = blockIdx.y * 256 + threadIdx.x;
    float s = 0.f;
    for (int k = 0; k < 2048; k++)
        s = fmaf(xm[k], f1_w[(size_t)k * 1024 + j], s);
    s += f1_b[j];
    g_h1[b * 1024 + j] = s / (1.f + expf(-s));
}

__global__ void k_mlp2(const float* __restrict__ f2_w, const float* __restrict__ f2_b,
                       float* __restrict__ dout) {
    __shared__ float red[128];
    int bh = blockIdx.x;
    int b = bh >> 4, h = bh & 15;
    float s = 0.f;
    for (int k = threadIdx.x; k < 1024; k += 128)
        s = fmaf(g_h1[b * 1024 + k], f2_w[k * 16 + h], s);
    red[threadIdx.x] = s; __syncthreads();
    for (int off = 64; off > 0; off >>= 1) {
        if (threadIdx.x < off) red[threadIdx.x] += red[threadIdx.x + off];
        __syncthreads();
    }
    if (threadIdx.x == 0) {
        float z = red[0] + f2_b[h];
        dout[OUT_OFF_PSI + bh] = 1.f / (1.f + expf(-z));
    }
}

// ======================= resonance + k_mod + decay split =======================
__global__ __launch_bounds__(256, 2)
void k_res(const float* __restrict__ Wb, const float* __restrict__ fast_slope,
           const float* __restrict__ slow_slope) {
    __shared__ float As[16][132];
    __shared__ float Bs[16][128];
    const int m0 = blockIdx.x * 128;
    const int bh = blockIdx.y;
    const int h = bh & 15;
    const size_t slb = (size_t)bh * SLAB;
    const float* __restrict__ kslab = g_kf + slb;
    const float* __restrict__ Wbh = Wb + (size_t)h * DK_ * DK_;
    const int tx = threadIdx.x, ty = threadIdx.y;
    const int tid = ty * 16 + tx;
    float acc[8][8];
    #pragma unroll
    for (int i = 0; i < 8; i++)
        #pragma unroll
        for (int j = 0; j < 8; j++) acc[i][j] = 0.f;

    const int arow = tid >> 2, acol = (tid & 3) * 4;
    const int brow = tid >> 5, bcol = (tid & 31) * 4;

    for (int kt = 0; kt < 128; kt += 16) {
        #pragma unroll
        for (int r = 0; r < 2; r++) {
            int row = arow + r * 64;
            float4 av = *(const float4*)&kslab[(size_t)(m0 + row) * DK_ + kt + acol];
            As[acol + 0][row] = av.x; As[acol + 1][row] = av.y;
            As[acol + 2][row] = av.z; As[acol + 3][row] = av.w;
        }
        #pragma unroll
        for (int r = 0; r < 2; r++) {
            int row = brow + r * 8;
            *(float4*)&Bs[row][bcol] =
                *(const float4*)&Wbh[(size_t)(kt + row) * DK_ + bcol];
        }
        __syncthreads();
        #pragma unroll
        for (int kk = 0; kk < 16; kk++) {
            float a[8], bb[8];
            *(float4*)&a[0]  = *(const float4*)&As[kk][ty * 8];
            *(float4*)&a[4]  = *(const float4*)&As[kk][ty * 8 + 4];
            *(float4*)&bb[0] = *(const float4*)&Bs[kk][tx * 8];
            *(float4*)&bb[4] = *(const float4*)&Bs[kk][tx * 8 + 4];
            #pragma unroll
            for (int i = 0; i < 8; i++)
                #pragma unroll
                for (int j = 0; j < 8; j++)
                    acc[i][j] = fmaf(a[i], bb[j], acc[i][j]);
        }
        __syncthreads();
    }
    const float fs = fast_slope[h], ss = slow_slope[h];
    #pragma unroll
    for (int i = 0; i < 8; i++) {
        int n = m0 + ty * 8 + i;
        float idx = (float)(n - (N_ - 1));
        float fw = expf(fs * idx);
        float sw = expf(ss * idx);
        #pragma unroll
        for (int j = 0; j < 8; j += 4) {
            size_t p = slb + (size_t)n * DK_ + tx * 8 + j;
            float4 kr = *(const float4*)&g_kf[p];
            float kf0, kf1, kf2, kf3, ks0, ks1, ks2, ks3;
            float r0, km;
            r0 = tanhf(acc[i][j+0]); km = kr.x * (1.f + 0.5f * r0) * INV_SQRT_DK; kf0 = km * fw; ks0 = km * sw;
            r0 = tanhf(acc[i][j+1]); km = kr.y * (1.f + 0.5f * r0) * INV_SQRT_DK; kf1 = km * fw; ks1 = km * sw;
            r0 = tanhf(acc[i][j+2]); km = kr.z * (1.f + 0.5f * r0) * INV_SQRT_DK; kf2 = km * fw; ks2 = km * sw;
            r0 = tanhf(acc[i][j+3]); km = kr.w * (1.f + 0.5f * r0) * INV_SQRT_DK; kf3 = km * fw; ks3 = km * sw;
            split2w(kf0, kf1, g_kfh + p,     g_kfl + p);
            split2w(kf2, kf3, g_kfh + p + 2, g_kfl + p + 2);
            split2w(ks0, ks1, g_ksh + p,     g_ksl + p);
            split2w(ks2, ks3, g_ksh + p + 2, g_ksl + p + 2);
        }
    }
}

// ======================= M finalize =======================
__global__ void k_mfin(const float* __restrict__ Mf_prev, const float* __restrict__ Ms_prev,
                       const float* __restrict__ inter_fast, const float* __restrict__ inter_slow,
                       float* __restrict__ dout) {
    const int bh = blockIdx.x;
    const int which = blockIdx.y;
    const int h = bh & 15;
    const float inter = which ? inter_slow[h] : inter_fast[h];
    const float* prev = (which ? Ms_prev : Mf_prev) + (size_t)bh * 16384;
    const float* part = g_part + ((size_t)which * BH_ + bh) * 8 * 16384;
    float* dst = dout + (which ? OUT_OFF_MS : OUT_OFF_MF) + (size_t)bh * 16384;
    for (int e = threadIdx.x; e < 16384; e += 256) {
        float s = 0.f;
        #pragma unroll
        for (int sp = 0; sp < 8; sp++) s += part[(size_t)sp * 16384 + e];
        dst[e] = prev[e] * inter + s;
    }
}

// ======================= Mref = (I+S) @ M, blended -> fp32 + bf16 split =====
__global__ __launch_bounds__(256, 2)
void k_mref(const float* __restrict__ S_fast, const float* __restrict__ S_slow,
            const float* __restrict__ dout, int which) {
    __shared__ float As[16][132];
    __shared__ float Bs[16][128];
    const int bh = blockIdx.x;
    const int h = bh & 15;
    const float* __restrict__ S = (which ? S_slow : S_fast) + (size_t)h * 16384;
    const float* __restrict__ M = dout + (which ? OUT_OFF_MS : OUT_OFF_MF) + (size_t)bh * 16384;
    const int tx = threadIdx.x, ty = threadIdx.y;
    const int tid = ty * 16 + tx;
    float acc[8][8];
    #pragma unroll
    for (int i = 0; i < 8; i++)
        #pragma unroll
        for (int j = 0; j < 8; j++) acc[i][j] = 0.f;

    const int arow = tid >> 2, acol = (tid & 3) * 4;
    const int brow = tid >> 5, bcol = (tid & 31) * 4;

    for (int kt = 0; kt < 128; kt += 16) {
        #pragma unroll
        for (int r = 0; r < 2; r++) {
            int row = arow + r * 64;
            float4 av = *(const float4*)&S[(size_t)row * 128 + kt + acol];
            As[acol + 0][row] = av.x + ((row == kt + acol + 0) ? 1.f : 0.f);
            As[acol + 1][row] = av.y + ((row == kt + acol + 1) ? 1.f : 0.f);
            As[acol + 2][row] = av.z + ((row == kt + acol + 2) ? 1.f : 0.f);
            As[acol + 3][row] = av.w + ((row == kt + acol + 3) ? 1.f : 0.f);
        }
        #pragma unroll
        for (int r = 0; r < 2; r++) {
            int row = brow + r * 8;
            *(float4*)&Bs[row][bcol] = *(const float4*)&M[(size_t)(kt + row) * 128 + bcol];
        }
        __syncthreads();
        #pragma unroll
        for (int kk = 0; kk < 16; kk++) {
            float a[8], bb[8];
            *(float4*)&a[0]  = *(const float4*)&As[kk][ty * 8];
            *(float4*)&a[4]  = *(const float4*)&As[kk][ty * 8 + 4];
            *(float4*)&bb[0] = *(const float4*)&Bs[kk][tx * 8];
            *(float4*)&bb[4] = *(const float4*)&Bs[kk][tx * 8 + 4];
            #pragma unroll
            for (int i = 0; i < 8; i++)
                #pragma unroll
                for (int j = 0; j < 8; j++)
                    acc[i][j] = fmaf(a[i], bb[j], acc[i][j]);
        }
        __syncthreads();
    }
    const float p = dout[OUT_OFF_PSI + bh];
    const float c0 = which ? p : (1.f - p);
    float* dst = g_mblend + (size_t)bh * 16384;
    __nv_bfloat16* mh = g_mbh + (size_t)bh * 16384;
    __nv_bfloat16* ml = g_mbl + (size_t)bh * 16384;
    #pragma unroll
    for (int i = 0; i < 8; i++)
        #pragma unroll
        for (int j = 0; j < 8; j += 2) {
            int idx = (ty * 8 + i) * 128 + tx * 8 + j;
            if (which == 0) {
                dst[idx]     = c0 * acc[i][j];
                dst[idx + 1] = c0 * acc[i][j + 1];
            } else {
                float v0 = dst[idx]     + c0 * acc[i][j];
                float v1 = dst[idx + 1] + c0 * acc[i][j + 1];
                split2w(v0, v1, mh + idx, ml + idx);
            }
        }
}

// ======================= launch =======================
extern "C" void kernel_launch(void* const* d_in, const int* in_sizes, int n_in,
                              void* d_out, int out_size) {
    (void)in_sizes; (void)n_in; (void)out_size;
    const float* x          = (const float*)d_in[0];
    const float* Mf_prev    = (const float*)d_in[1];
    const float* Ms_prev    = (const float*)d_in[2];
    const float* Wq         = (const float*)d_in[3];
    const float* Wk         = (const float*)d_in[4];
    const float* Wv         = (const float*)d_in[5];
    const float* Wo         = (const float*)d_in[6];
    const float* Wb         = (const float*)d_in[7];
    const float* fast_slope = (const float*)d_in[8];
    const float* slow_slope = (const float*)d_in[9];
    const float* inter_fast = (const float*)d_in[10];
    const float* inter_slow = (const float*)d_in[11];
    const float* S_fast     = (const float*)d_in[12];
    const float* S_slow     = (const float*)d_in[13];
    const float* f1_w       = (const float*)d_in[14];
    const float* f1_b       = (const float*)d_in[15];
    const float* f2_w       = (const float*)d_in[16];
    const float* f2_b       = (const float*)d_in[17];
    float* out = (float*)d_out;

    const int gemm_smem = 2 * SSTG * 2;       // 81920
    const int mp_smem   = 2 * MP_STG * 2;     // 69632
    const int ob_smem   = 2 * OB_STG * 2;     // 75776
    static bool attr_set = false;
    if (!attr_set) {
        cudaFuncSetAttribute(k_mma_gemm,   cudaFuncAttributeMaxDynamicSharedMemorySize, gemm_smem);
        cudaFuncSetAttribute(k_mpart_mma,  cudaFuncAttributeMaxDynamicSharedMemorySize, mp_smem);
        cudaFuncSetAttribute(k_oblend_mma, cudaFuncAttributeMaxDynamicSharedMemorySize, ob_smem);
        attr_set = true;
    }

    dim3 t16(16, 16);
    dim3 t328(32, 8);

    // prep: bf16 splits
    k_split_x<<<32768, 256>>>(x);
    k_wsplit_qkv<<<dim3(64, 192), t328>>>(Wq, Wk, Wv);
    k_wsplit_o<<<dim3(64, 64), t328>>>(Wo);

    // gating path
    k_meanpart<<<256, 256>>>(x);
    k_meanred<<<32, 256>>>();
    k_mlp1<<<dim3(4, 4), 256>>>(f1_w, f1_b);
    k_mlp2<<<64, 128>>>(f2_w, f2_b, out);

    // QKV projection (HMMA; q,v -> bf16 split, k -> fp32)
    k_mma_gemm<<<dim3(48, 128), 256, gemm_smem>>>(nullptr, 0);

    // per-head path
    k_res<<<dim3(32, 64), t16>>>(Wb, fast_slope, slow_slope);
    k_mpart_mma<<<dim3(8, 64, 2), 256, mp_smem>>>();
    k_mfin<<<dim3(64, 2), 256>>>(Mf_prev, Ms_prev, inter_fast, inter_slow, out);
    k_mref<<<64, t16>>>(S_fast, S_slow, out, 0);
    k_mref<<<64, t16>>>(S_fast, S_slow, out, 1);
    k_oblend_mma<<<dim3(32, 64), 256, ob_smem>>>();

    // output projection (HMMA)
    k_mma_gemm<<<dim3(16, 128), 256, gemm_smem>>>(out, 1);
}

// round 10
// speedup vs baseline: 2.5553x; 1.4097x over previous
#include <cuda_runtime.h>
#include <cuda_bf16.h>
#include <cstdint>
#include <math.h>

static constexpr int B_   = 4;
static constexpr int N_   = 4096;
static constexpr int H_   = 16;
static constexpr int DK_  = 128;
static constexpr int DIM_ = 2048;
static constexpr int BH_  = B_ * H_;      // 64
static constexpr int MROWS_ = B_ * N_;    // 16384
static constexpr float INV_SQRT_DK = 0.08838834764831843f;
static constexpr size_t SLAB = (size_t)N_ * DK_;

static constexpr long long OUT_OFF_MF  = 33554432LL;
static constexpr long long OUT_OFF_MS  = 34603008LL;
static constexpr long long OUT_OFF_PSI = 35651584LL;

// ---------------- scratch (allocation-free: device globals) ----------------
__device__ float g_kf [(size_t)BH_ * SLAB];       // raw k fp32
__device__ float g_part[2LL * BH_ * 8 * DK_ * DK_];
__device__ float g_mblend[(size_t)BH_ * DK_ * DK_];
__device__ float g_meanpart[8 * B_ * DIM_];
__device__ float g_mean[B_ * DIM_];
__device__ float g_h1[B_ * 1024];

// tf32-rounded fp32 operands for big GEMMs
__device__ float g_xt [(size_t)MROWS_ * DIM_];    // x (tf32-rounded)
__device__ float g_wqkvt[(size_t)6144 * 2048];    // [Wq|Wk|Wv]^T
__device__ float g_wot[(size_t)2048 * 2048];      // Wo^T
__device__ float g_obt[(size_t)MROWS_ * DIM_];    // o_blend (b,n,h,v)

// per-head bf16 split tensors [bh][n][d] (for bf16 3-pass HMMA kernels)
__device__ __nv_bfloat16 g_qh [(size_t)BH_ * SLAB];
__device__ __nv_bfloat16 g_ql [(size_t)BH_ * SLAB];
__device__ __nv_bfloat16 g_vh [(size_t)BH_ * SLAB];
__device__ __nv_bfloat16 g_vl [(size_t)BH_ * SLAB];
__device__ __nv_bfloat16 g_kfh[(size_t)BH_ * SLAB];
__device__ __nv_bfloat16 g_kfl[(size_t)BH_ * SLAB];
__device__ __nv_bfloat16 g_ksh[(size_t)BH_ * SLAB];
__device__ __nv_bfloat16 g_ksl[(size_t)BH_ * SLAB];
__device__ __nv_bfloat16 g_mbh[(size_t)BH_ * DK_ * DK_];
__device__ __nv_bfloat16 g_mbl[(size_t)BH_ * DK_ * DK_];

// ===================== PTX helpers (base-target) ===========================
__device__ __forceinline__ uint32_t smem_u32(const void* p) {
    uint32_t a;
    asm("{ .reg .u64 t; cvta.to.shared.u64 t, %1; cvt.u32.u64 %0, t; }"
        : "=r"(a) : "l"(p));
    return a;
}
__device__ __forceinline__ float tf32r(float x) {
    float r;
    asm("cvt.rna.tf32.f32 %0, %1;" : "=f"(r) : "f"(x));
    return r;
}

#define MMA16816(d, a, b0, b1) \
    asm volatile("mma.sync.aligned.m16n8k16.row.col.f32.bf16.bf16.f32 " \
        "{%0,%1,%2,%3}, {%4,%5,%6,%7}, {%8,%9}, {%0,%1,%2,%3};" \
        : "+f"((d)[0]), "+f"((d)[1]), "+f"((d)[2]), "+f"((d)[3]) \
        : "r"((a)[0]), "r"((a)[1]), "r"((a)[2]), "r"((a)[3]), "r"(b0), "r"(b1))

#define MMATF32(d, a, b0, b1) \
    asm volatile("mma.sync.aligned.m16n8k8.row.col.f32.tf32.tf32.f32 " \
        "{%0,%1,%2,%3}, {%4,%5,%6,%7}, {%8,%9}, {%0,%1,%2,%3};" \
        : "+f"((d)[0]), "+f"((d)[1]), "+f"((d)[2]), "+f"((d)[3]) \
        : "r"((a)[0]), "r"((a)[1]), "r"((a)[2]), "r"((a)[3]), "r"(b0), "r"(b1))

#define LDSM_X4(r, addr) \
    asm volatile("ldmatrix.sync.aligned.m8n8.x4.shared.b16 {%0,%1,%2,%3}, [%4];" \
        : "=r"((r)[0]), "=r"((r)[1]), "=r"((r)[2]), "=r"((r)[3]) : "r"(addr))
#define LDSM_X4_T(r, addr) \
    asm volatile("ldmatrix.sync.aligned.m8n8.x4.trans.shared.b16 {%0,%1,%2,%3}, [%4];" \
        : "=r"((r)[0]), "=r"((r)[1]), "=r"((r)[2]), "=r"((r)[3]) : "r"(addr))

#define CP_ASYNC16(dst, src) \
    asm volatile("cp.async.cg.shared.global [%0], [%1], 16;" \
        :: "r"(dst), "l"(src) : "memory")
#define CP_COMMIT() asm volatile("cp.async.commit_group;" ::: "memory")
#define CP_WAIT(n)  asm volatile("cp.async.wait_group %0;" :: "n"(n) : "memory")

__device__ __forceinline__ void split2w(float a, float b,
                                        __nv_bfloat16* ph, __nv_bfloat16* pl) {
    __nv_bfloat16 h0 = __float2bfloat16_rn(a), h1 = __float2bfloat16_rn(b);
    __nv_bfloat16 l0 = __float2bfloat16_rn(a - __bfloat162float(h0));
    __nv_bfloat16 l1 = __float2bfloat16_rn(b - __bfloat162float(h1));
    __nv_bfloat162 hh; hh.x = h0; hh.y = h1;
    __nv_bfloat162 ll; ll.x = l0; ll.y = l1;
    *(__nv_bfloat162*)ph = hh;
    *(__nv_bfloat162*)pl = ll;
}

// ======================= tf32 prep =======================
__global__ void k_cvt_x(const float* __restrict__ x) {
    size_t i = ((size_t)blockIdx.x * 256 + threadIdx.x) * 4;
    float4 v = *(const float4*)(x + i);
    float4 o = make_float4(tf32r(v.x), tf32r(v.y), tf32r(v.z), tf32r(v.w));
    *(float4*)(g_xt + i) = o;
}

__global__ void k_wcvt_qkv(const float* __restrict__ Wq, const float* __restrict__ Wk,
                           const float* __restrict__ Wv) {
    __shared__ float tile[32][33];
    int k0 = blockIdx.x * 32, n0 = blockIdx.y * 32;
    int which = n0 >> 11;
    const float* __restrict__ W = (which == 0) ? Wq : (which == 1 ? Wk : Wv);
    int nn0 = n0 & 2047;
    for (int r = threadIdx.y; r < 32; r += 8)
        tile[r][threadIdx.x] = W[(size_t)(k0 + r) * 2048 + nn0 + threadIdx.x];
    __syncthreads();
    for (int r = threadIdx.y; r < 32; r += 8)
        g_wqkvt[(size_t)(n0 + r) * 2048 + k0 + threadIdx.x] = tf32r(tile[threadIdx.x][r]);
}

__global__ void k_wcvt_o(const float* __restrict__ Wo) {
    __shared__ float tile[32][33];
    int k0 = blockIdx.x * 32, n0 = blockIdx.y * 32;
    for (int r = threadIdx.y; r < 32; r += 8)
        tile[r][threadIdx.x] = Wo[(size_t)(k0 + r) * 2048 + n0 + threadIdx.x];
    __syncthreads();
    for (int r = threadIdx.y; r < 32; r += 8)
        g_wot[(size_t)(n0 + r) * 2048 + k0 + threadIdx.x] = tf32r(tile[threadIdx.x][r]);
}

// ======================= tf32 single-pass GEMM =============================
// C = A @ B^T; A [M][2048], B [Ntot][2048] both tf32-rounded fp32 K-major.
// 128x128 CTA tile, warp tile 32x64, BK=32 (4 k8 steps), 2-stage cp.async.
// Smem rows stride 36 floats (conflict-free scalar frag loads).
static constexpr int TSTG = 2 * 128 * 36;            // floats per stage

__global__ __launch_bounds__(256)
void k_tf32_gemm(float* __restrict__ Cout, int mode) {
    extern __shared__ __align__(16) float smf[];
    const float* __restrict__ A  = (mode == 0) ? g_xt  : g_obt;
    const float* __restrict__ Bm = (mode == 0) ? g_wqkvt : g_wot;

    const int tid = threadIdx.x;
    const int wid = tid >> 5, lane = tid & 31;
    const int wr = wid >> 1, wc = wid & 1;
    const int j0 = blockIdx.x * 128;
    const int m0 = blockIdx.y * 128;
    const int fr = lane >> 2;        // frag row 0..7
    const int fc = lane & 3;         // frag col 0..3

    float acc[2][8][4];
    #pragma unroll
    for (int i = 0; i < 2; i++)
        #pragma unroll
        for (int j = 0; j < 8; j++)
            #pragma unroll
            for (int k = 0; k < 4; k++) acc[i][j][k] = 0.f;

    // global->smem: 2048 float4 per chunk (A 1024 + B 1024), 8 per thread
    int gl_isB[8], gl_r[8], gl_q[8];
    #pragma unroll
    for (int i = 0; i < 8; i++) {
        int idx = i * 256 + tid;
        gl_isB[i] = idx >> 10;
        int local = idx & 1023;
        gl_r[i] = local >> 3;
        gl_q[i] = local & 7;
    }
    const uint32_t sbase = smem_u32(smf);

    auto issue = [&](int c, int st) {
        #pragma unroll
        for (int i = 0; i < 8; i++) {
            const float* src = (gl_isB[i] ? Bm + (size_t)(j0 + gl_r[i]) * 2048
                                          : A  + (size_t)(m0 + gl_r[i]) * 2048)
                               + c * 32 + gl_q[i] * 4;
            uint32_t dst = sbase +
                (uint32_t)(st * TSTG + gl_isB[i] * 128 * 36 + gl_r[i] * 36 + gl_q[i] * 4) * 4;
            CP_ASYNC16(dst, src);
        }
        CP_COMMIT();
    };

    issue(0, 0);
    for (int c = 0; c < 64; c++) {
        if (c < 63) { issue(c + 1, (c + 1) & 1); CP_WAIT(1); }
        else        { CP_WAIT(0); }
        __syncthreads();
        const float* As = smf + (c & 1) * TSTG;
        const float* Bs = As + 128 * 36;

        #pragma unroll
        for (int k8 = 0; k8 < 4; k8++) {
            const int kb = k8 * 8;
            uint32_t af[2][4], bf[8][2];
            #pragma unroll
            for (int i = 0; i < 2; i++) {
                int m = wr * 32 + i * 16 + fr;
                af[i][0] = *(const uint32_t*)&As[m * 36 + kb + fc];
                af[i][1] = *(const uint32_t*)&As[(m + 8) * 36 + kb + fc];
                af[i][2] = *(const uint32_t*)&As[m * 36 + kb + fc + 4];
                af[i][3] = *(const uint32_t*)&As[(m + 8) * 36 + kb + fc + 4];
            }
            #pragma unroll
            for (int p = 0; p < 8; p++) {
                int n = wc * 64 + p * 8 + fr;
                bf[p][0] = *(const uint32_t*)&Bs[n * 36 + kb + fc];
                bf[p][1] = *(const uint32_t*)&Bs[n * 36 + kb + fc + 4];
            }
            #pragma unroll
            for (int i = 0; i < 2; i++)
                #pragma unroll
                for (int p = 0; p < 8; p++)
                    MMATF32(acc[i][p], af[i], bf[p][0], bf[p][1]);
        }
        __syncthreads();
    }

    // epilogue (C frag: c0,c1 at (fr, 2*fc), c2,c3 at (fr+8, 2*fc))
    const int lane2 = fc * 2;
    if (mode == 0) {
        const int which = j0 >> 11;
        const int h = (j0 >> 7) & 15;
        const int b = m0 >> 12;
        const size_t slab = (size_t)(b * 16 + h) * SLAB;
        if (which == 1) {
            float* dst0 = g_kf + slab;
            #pragma unroll
            for (int i = 0; i < 2; i++) {
                int n = (m0 & 4095) + wr * 32 + i * 16 + fr;
                #pragma unroll
                for (int p = 0; p < 8; p++) {
                    int col = wc * 64 + p * 8 + lane2;
                    float* dst = dst0 + (size_t)n * 128 + col;
                    *(float2*)dst = make_float2(acc[i][p][0], acc[i][p][1]);
                    *(float2*)(dst + 8 * 128) = make_float2(acc[i][p][2], acc[i][p][3]);
                }
            }
        } else {
            __nv_bfloat16* dh = ((which == 0) ? g_qh : g_vh) + slab;
            __nv_bfloat16* dl = ((which == 0) ? g_ql : g_vl) + slab;
            #pragma unroll
            for (int i = 0; i < 2; i++) {
                int n = (m0 & 4095) + wr * 32 + i * 16 + fr;
                #pragma unroll
                for (int p = 0; p < 8; p++) {
                    int col = wc * 64 + p * 8 + lane2;
                    size_t o0 = (size_t)n * 128 + col;
                    split2w(acc[i][p][0], acc[i][p][1], dh + o0, dl + o0);
                    split2w(acc[i][p][2], acc[i][p][3], dh + o0 + 8 * 128, dl + o0 + 8 * 128);
                }
            }
        }
    } else {
        #pragma unroll
        for (int i = 0; i < 2; i++) {
            int m = m0 + wr * 32 + i * 16 + fr;
            #pragma unroll
            for (int p = 0; p < 8; p++) {
                int col = j0 + wc * 64 + p * 8 + lane2;
                float* dst = Cout + (size_t)m * 2048 + col;
                *(float2*)dst = make_float2(acc[i][p][0], acc[i][p][1]);
                *(float2*)(dst + 8 * 2048) = make_float2(acc[i][p][2], acc[i][p][3]);
            }
        }
    }
}

// ======================= k_mpart HMMA (bf16 3-pass, unchanged) ==============
static constexpr int MP_STG = 4 * 32 * 136;

__global__ __launch_bounds__(256)
void k_mpart_mma() {
    extern __shared__ __align__(16) __nv_bfloat16 smb[];
    const int split = blockIdx.x, bh = blockIdx.y, which = blockIdx.z;
    const __nv_bfloat16* srcs[4] = {
        ((which ? g_ksh : g_kfh) + (size_t)bh * SLAB),
        ((which ? g_ksl : g_kfl) + (size_t)bh * SLAB),
        (g_vh + (size_t)bh * SLAB),
        (g_vl + (size_t)bh * SLAB)
    };
    const uint32_t sbase = smem_u32(smb);
    const int tid = threadIdx.x;
    const int wid = tid >> 5, lane = tid & 31;
    const int wr = wid >> 1, wc = wid & 1;

    float acc[2][8][4];
    #pragma unroll
    for (int i = 0; i < 2; i++)
        #pragma unroll
        for (int j = 0; j < 8; j++)
            #pragma unroll
            for (int k = 0; k < 4; k++) acc[i][j][k] = 0.f;

    int gl_t[8], gl_r[8], gl_q[8];
    #pragma unroll
    for (int i = 0; i < 8; i++) {
        int idx = i * 256 + tid;
        gl_t[i] = idx >> 9;
        int rem = idx & 511;
        gl_r[i] = rem >> 4;
        gl_q[i] = rem & 15;
    }

    auto issue = [&](int c, int st) {
        #pragma unroll
        for (int i = 0; i < 8; i++) {
            const __nv_bfloat16* src = srcs[gl_t[i]]
                + (size_t)(split * 512 + c * 32 + gl_r[i]) * 128 + gl_q[i] * 8;
            uint32_t dst = sbase +
                (uint32_t)(st * MP_STG + gl_t[i] * 4352 + gl_r[i] * 136 + gl_q[i] * 8) * 2;
            CP_ASYNC16(dst, src);
        }
        CP_COMMIT();
    };

    const int rofs = (lane & 7) + ((lane >> 4) << 3);
    const int cofs = (lane & 8);

    issue(0, 0);
    for (int c = 0; c < 16; c++) {
        if (c < 15) { issue(c + 1, (c + 1) & 1); CP_WAIT(1); }
        else        { CP_WAIT(0); }
        __syncthreads();
        const uint32_t stg = sbase + (uint32_t)((c & 1) * MP_STG) * 2;

        #pragma unroll
        for (int ks = 0; ks < 2; ks++) {
            const int rowk = ks * 16 + rofs;
            uint32_t ah[2][4], al[2][4], bhf[4][4], blf[4][4];
            #pragma unroll
            for (int i = 0; i < 2; i++) {
                uint32_t ad = stg + (uint32_t)(rowk * 136 + wr * 32 + i * 16 + cofs) * 2;
                LDSM_X4_T(ah[i], ad);
                LDSM_X4_T(al[i], ad + (uint32_t)4352 * 2);
            }
            #pragma unroll
            for (int p = 0; p < 4; p++) {
                uint32_t bd = stg + (uint32_t)(2 * 4352 + rowk * 136 + wc * 64 + p * 16 + cofs) * 2;
                LDSM_X4_T(bhf[p], bd);
                LDSM_X4_T(blf[p], bd + (uint32_t)4352 * 2);
            }
            #pragma unroll
            for (int i = 0; i < 2; i++)
                #pragma unroll
                for (int t = 0; t < 8; t++) {
                    const int p = t >> 1, sel = t & 1;
                    MMA16816(acc[i][t], ah[i], bhf[p][sel], bhf[p][sel + 2]);
                }
            #pragma unroll
            for (int i = 0; i < 2; i++)
                #pragma unroll
                for (int t = 0; t < 8; t++) {
                    const int p = t >> 1, sel = t & 1;
                    MMA16816(acc[i][t], ah[i], blf[p][sel], blf[p][sel + 2]);
                }
            #pragma unroll
            for (int i = 0; i < 2; i++)
                #pragma unroll
                for (int t = 0; t < 8; t++) {
                    const int p = t >> 1, sel = t & 1;
                    MMA16816(acc[i][t], al[i], bhf[p][sel], bhf[p][sel + 2]);
                }
        }
        __syncthreads();
    }

    const int gr = lane >> 2;
    const int lane2 = (lane & 3) * 2;
    float* dst0 = g_part + (((size_t)which * BH_ + bh) * 8 + split) * 16384;
    #pragma unroll
    for (int i = 0; i < 2; i++) {
        int m = wr * 32 + i * 16 + gr;
        #pragma unroll
        for (int t = 0; t < 8; t++) {
            int col = wc * 64 + t * 8 + lane2;
            float* dst = dst0 + m * 128 + col;
            *(float2*)dst = make_float2(acc[i][t][0], acc[i][t][1]);
            *(float2*)(dst + 8 * 128) = make_float2(acc[i][t][2], acc[i][t][3]);
        }
    }
}

// ======================= k_oblend HMMA (bf16 3-pass, tf32 fp32 out) =========
static constexpr int OB_STG = 2 * 128 * 40 + 2 * 32 * 136;

__global__ __launch_bounds__(256)
void k_oblend_mma() {
    extern __shared__ __align__(16) __nv_bfloat16 smb[];
    const int bh = blockIdx.y;
    const int m0 = blockIdx.x * 128;
    const __nv_bfloat16* qsrc[2] = { g_qh + (size_t)bh * SLAB, g_ql + (size_t)bh * SLAB };
    const __nv_bfloat16* msrc[2] = { g_mbh + (size_t)bh * 16384, g_mbl + (size_t)bh * 16384 };
    const uint32_t sbase = smem_u32(smb);
    const int tid = threadIdx.x;
    const int wid = tid >> 5, lane = tid & 31;
    const int wr = wid >> 1, wc = wid & 1;
    const int l15 = lane & 15;
    const int lhalf = (lane >> 4) * 8;

    float acc[2][8][4];
    #pragma unroll
    for (int i = 0; i < 2; i++)
        #pragma unroll
        for (int j = 0; j < 8; j++)
            #pragma unroll
            for (int k = 0; k < 4; k++) acc[i][j][k] = 0.f;

    int gA[8], gl_r[8], gl_q[8];
    #pragma unroll
    for (int i = 0; i < 8; i++) {
        int idx = i * 256 + tid;
        if (idx < 1024) {
            gA[i] = idx >> 9;
            int rem = idx & 511;
            gl_r[i] = rem >> 2; gl_q[i] = rem & 3;
        } else {
            gA[i] = 2 + ((idx - 1024) >> 9);
            int rem = (idx - 1024) & 511;
            gl_r[i] = rem >> 4; gl_q[i] = rem & 15;
        }
    }

    auto issue = [&](int c, int st) {
        #pragma unroll
        for (int i = 0; i < 8; i++) {
            const __nv_bfloat16* src;
            uint32_t soff;
            if (gA[i] < 2) {
                src = qsrc[gA[i]] + (size_t)(m0 + gl_r[i]) * 128 + c * 32 + gl_q[i] * 8;
                soff = (uint32_t)(gA[i] * 5120 + gl_r[i] * 40 + gl_q[i] * 8);
            } else {
                src = msrc[gA[i] - 2] + (size_t)(c * 32 + gl_r[i]) * 128 + gl_q[i] * 8;
                soff = (uint32_t)(10240 + (gA[i] - 2) * 4352 + gl_r[i] * 136 + gl_q[i] * 8);
            }
            CP_ASYNC16(sbase + (uint32_t)(st * OB_STG) * 2 + soff * 2, src);
        }
        CP_COMMIT();
    };

    const int rofs = (lane & 7) + ((lane >> 4) << 3);
    const int cofs = (lane & 8);

    issue(0, 0);
    for (int c = 0; c < 4; c++) {
        if (c < 3) { issue(c + 1, (c + 1) & 1); CP_WAIT(1); }
        else       { CP_WAIT(0); }
        __syncthreads();
        const uint32_t stg = sbase + (uint32_t)((c & 1) * OB_STG) * 2;

        #pragma unroll
        for (int s = 0; s < 2; s++) {
            const uint32_t kcol = (uint32_t)(s * 16 + lhalf) * 2;
            const int rowd = s * 16 + rofs;
            uint32_t ah[2][4], al[2][4], bhf[4][4], blf[4][4];
            #pragma unroll
            for (int i = 0; i < 2; i++) {
                uint32_t ar = stg + (uint32_t)((wr * 32 + i * 16 + l15) * 40) * 2 + kcol;
                LDSM_X4(ah[i], ar);
                LDSM_X4(al[i], ar + (uint32_t)5120 * 2);
            }
            #pragma unroll
            for (int p = 0; p < 4; p++) {
                uint32_t bd = stg + (uint32_t)(10240 + rowd * 136 + wc * 64 + p * 16 + cofs) * 2;
                LDSM_X4_T(bhf[p], bd);
                LDSM_X4_T(blf[p], bd + (uint32_t)4352 * 2);
            }
            #pragma unroll
            for (int i = 0; i < 2; i++)
                #pragma unroll
                for (int t = 0; t < 8; t++) {
                    const int p = t >> 1, sel = t & 1;
                    MMA16816(acc[i][t], ah[i], bhf[p][sel], bhf[p][sel + 2]);
                }
            #pragma unroll
            for (int i = 0; i < 2; i++)
                #pragma unroll
                for (int t = 0; t < 8; t++) {
                    const int p = t >> 1, sel = t & 1;
                    MMA16816(acc[i][t], ah[i], blf[p][sel], blf[p][sel + 2]);
                }
            #pragma unroll
            for (int i = 0; i < 2; i++)
                #pragma unroll
                for (int t = 0; t < 8; t++) {
                    const int p = t >> 1, sel = t & 1;
                    MMA16816(acc[i][t], al[i], bhf[p][sel], bhf[p][sel + 2]);
                }
        }
        __syncthreads();
    }

    const int gr = lane >> 2;
    const int lane2 = (lane & 3) * 2;
    const int b = bh >> 4, h = bh & 15;
    #pragma unroll
    for (int i = 0; i < 2; i++) {
        int n = m0 + wr * 32 + i * 16 + gr;
        #pragma unroll
        for (int t = 0; t < 8; t++) {
            int col = wc * 64 + t * 8 + lane2;
            size_t b0 = ((size_t)(b * 4096 + n) * 16 + h) * 128 + col;
            size_t b8 = ((size_t)(b * 4096 + n + 8) * 16 + h) * 128 + col;
            *(float2*)(g_obt + b0) = make_float2(tf32r(acc[i][t][0]), tf32r(acc[i][t][1]));
            *(float2*)(g_obt + b8) = make_float2(tf32r(acc[i][t][2]), tf32r(acc[i][t][3]));
        }
    }
}

// ======================= mean over N =======================
__global__ void k_meanpart(const float* __restrict__ x) {
    int gid = blockIdx.x * 256 + threadIdx.x;
    int sp = gid >> 13;
    int r  = gid & 8191;
    int b = r >> 11, d = r & 2047;
    float s = 0.f;
    int nbeg = sp * 512;
    #pragma unroll 4
    for (int n = nbeg; n < nbeg + 512; n++)
        s += x[(size_t)(b * N_ + n) * DIM_ + d];
    g_meanpart[gid] = s;
}

__global__ void k_meanred() {
    int r = blockIdx.x * 256 + threadIdx.x;
    float s = 0.f;
    #pragma unroll
    for (int sp = 0; sp < 8; sp++) s += g_meanpart[sp * 8192 + r];
    g_mean[r] = s * (1.f / 4096.f);
}

// ======================= gating MLP =======================
__global__ void k_mlp1(const float* __restrict__ f1_w, const float* __restrict__ f1_b) {
    __shared__ float xm[2048];
    int b = blockIdx.x;
    for (int i = threadIdx.x; i < 2048; i += 256) xm[i] = g_mean[b * 2048 + i];
    __syncthreads();
    int j = blockIdx.y * 256 + threadIdx.x;
    float s = 0.f;
    for (int k = 0; k < 2048; k++)
        s = fmaf(xm[k], f1_w[(size_t)k * 1024 + j], s);
    s += f1_b[j];
    g_h1[b * 1024 + j] = s / (1.f + expf(-s));
}

__global__ void k_mlp2(const float* __restrict__ f2_w, const float* __restrict__ f2_b,
                       float* __restrict__ dout) {
    __shared__ float red[128];
    int bh = blockIdx.x;
    int b = bh >> 4, h = bh & 15;
    float s = 0.f;
    for (int k = threadIdx.x; k < 1024; k += 128)
        s = fmaf(g_h1[b * 1024 + k], f2_w[k * 16 + h], s);
    red[threadIdx.x] = s; __syncthreads();
    for (int off = 64; off > 0; off >>= 1) {
        if (threadIdx.x < off) red[threadIdx.x] += red[threadIdx.x + off];
        __syncthreads();
    }
    if (threadIdx.x == 0) {
        float z = red[0] + f2_b[h];
        dout[OUT_OFF_PSI + bh] = 1.f / (1.f + expf(-z));
    }
}

// ======================= resonance + k_mod + decay split =======================
__global__ __launch_bounds__(256, 2)
void k_res(const float* __restrict__ Wb, const float* __restrict__ fast_slope,
           const float* __restrict__ slow_slope) {
    __shared__ float As[16][132];
    __shared__ float Bs[16][128];
    const int m0 = blockIdx.x * 128;
    const int bh = blockIdx.y;
    const int h = bh & 15;
    const size_t slb = (size_t)bh * SLAB;
    const float* __restrict__ kslab = g_kf + slb;
    const float* __restrict__ Wbh = Wb + (size_t)h * DK_ * DK_;
    const int tx = threadIdx.x, ty = threadIdx.y;
    const int tid = ty * 16 + tx;
    float acc[8][8];
    #pragma unroll
    for (int i = 0; i < 8; i++)
        #pragma unroll
        for (int j = 0; j < 8; j++) acc[i][j] = 0.f;

    const int arow = tid >> 2, acol = (tid & 3) * 4;
    const int brow = tid >> 5, bcol = (tid & 31) * 4;

    for (int kt = 0; kt < 128; kt += 16) {
        #pragma unroll
        for (int r = 0; r < 2; r++) {
            int row = arow + r * 64;
            float4 av = *(const float4*)&kslab[(size_t)(m0 + row) * DK_ + kt + acol];
            As[acol + 0][row] = av.x; As[acol + 1][row] = av.y;
            As[acol + 2][row] = av.z; As[acol + 3][row] = av.w;
        }
        #pragma unroll
        for (int r = 0; r < 2; r++) {
            int row = brow + r * 8;
            *(float4*)&Bs[row][bcol] =
                *(const float4*)&Wbh[(size_t)(kt + row) * DK_ + bcol];
        }
        __syncthreads();
        #pragma unroll
        for (int kk = 0; kk < 16; kk++) {
            float a[8], bb[8];
            *(float4*)&a[0]  = *(const float4*)&As[kk][ty * 8];
            *(float4*)&a[4]  = *(const float4*)&As[kk][ty * 8 + 4];
            *(float4*)&bb[0] = *(const float4*)&Bs[kk][tx * 8];
            *(float4*)&bb[4] = *(const float4*)&Bs[kk][tx * 8 + 4];
            #pragma unroll
            for (int i = 0; i < 8; i++)
                #pragma unroll
                for (int j = 0; j < 8; j++)
                    acc[i][j] = fmaf(a[i], bb[j], acc[i][j]);
        }
        __syncthreads();
    }
    const float fs = fast_slope[h], ss = slow_slope[h];
    #pragma unroll
    for (int i = 0; i < 8; i++) {
        int n = m0 + ty * 8 + i;
        float idx = (float)(n - (N_ - 1));
        float fw = expf(fs * idx);
        float sw = expf(ss * idx);
        #pragma unroll
        for (int j = 0; j < 8; j += 4) {
            size_t p = slb + (size_t)n * DK_ + tx * 8 + j;
            float4 kr = *(const float4*)&g_kf[p];
            float kf0, kf1, kf2, kf3, ks0, ks1, ks2, ks3;
            float r0, km;
            r0 = tanhf(acc[i][j+0]); km = kr.x * (1.f + 0.5f * r0) * INV_SQRT_DK; kf0 = km * fw; ks0 = km * sw;
            r0 = tanhf(acc[i][j+1]); km = kr.y * (1.f + 0.5f * r0) * INV_SQRT_DK; kf1 = km * fw; ks1 = km * sw;
            r0 = tanhf(acc[i][j+2]); km = kr.z * (1.f + 0.5f * r0) * INV_SQRT_DK; kf2 = km * fw; ks2 = km * sw;
            r0 = tanhf(acc[i][j+3]); km = kr.w * (1.f + 0.5f * r0) * INV_SQRT_DK; kf3 = km * fw; ks3 = km * sw;
            split2w(kf0, kf1, g_kfh + p,     g_kfl + p);
            split2w(kf2, kf3, g_kfh + p + 2, g_kfl + p + 2);
            split2w(ks0, ks1, g_ksh + p,     g_ksl + p);
            split2w(ks2, ks3, g_ksh + p + 2, g_ksl + p + 2);
        }
    }
}

// ======================= M finalize =======================
__global__ void k_mfin(const float* __restrict__ Mf_prev, const float* __restrict__ Ms_prev,
                       const float* __restrict__ inter_fast, const float* __restrict__ inter_slow,
                       float* __restrict__ dout) {
    const int bh = blockIdx.x;
    const int which = blockIdx.y;
    const int h = bh & 15;
    const float inter = which ? inter_slow[h] : inter_fast[h];
    const float* prev = (which ? Ms_prev : Mf_prev) + (size_t)bh * 16384;
    const float* part = g_part + ((size_t)which * BH_ + bh) * 8 * 16384;
    float* dst = dout + (which ? OUT_OFF_MS : OUT_OFF_MF) + (size_t)bh * 16384;
    for (int e = threadIdx.x; e < 16384; e += 256) {
        float s = 0.f;
        #pragma unroll
        for (int sp = 0; sp < 8; sp++) s += part[(size_t)sp * 16384 + e];
        dst[e] = prev[e] * inter + s;
    }
}

// ======================= Mref = (I+S) @ M, blended -> bf16 split ============
__global__ __launch_bounds__(256, 2)
void k_mref(const float* __restrict__ S_fast, const float* __restrict__ S_slow,
            const float* __restrict__ dout, int which) {
    __shared__ float As[16][132];
    __shared__ float Bs[16][128];
    const int bh = blockIdx.x;
    const int h = bh & 15;
    const float* __restrict__ S = (which ? S_slow : S_fast) + (size_t)h * 16384;
    const float* __restrict__ M = dout + (which ? OUT_OFF_MS : OUT_OFF_MF) + (size_t)bh * 16384;
    const int tx = threadIdx.x, ty = threadIdx.y;
    const int tid = ty * 16 + tx;
    float acc[8][8];
    #pragma unroll
    for (int i = 0; i < 8; i++)
        #pragma unroll
        for (int j = 0; j < 8; j++) acc[i][j] = 0.f;

    const int arow = tid >> 2, acol = (tid & 3) * 4;
    const int brow = tid >> 5, bcol = (tid & 31) * 4;

    for (int kt = 0; kt < 128; kt += 16) {
        #pragma unroll
        for (int r = 0; r < 2; r++) {
            int row = arow + r * 64;
            float4 av = *(const float4*)&S[(size_t)row * 128 + kt + acol];
            As[acol + 0][row] = av.x + ((row == kt + acol + 0) ? 1.f : 0.f);
            As[acol + 1][row] = av.y + ((row == kt + acol + 1) ? 1.f : 0.f);
            As[acol + 2][row] = av.z + ((row == kt + acol + 2) ? 1.f : 0.f);
            As[acol + 3][row] = av.w + ((row == kt + acol + 3) ? 1.f : 0.f);
        }
        #pragma unroll
        for (int r = 0; r < 2; r++) {
            int row = brow + r * 8;
            *(float4*)&Bs[row][bcol] = *(const float4*)&M[(size_t)(kt + row) * 128 + bcol];
        }
        __syncthreads();
        #pragma unroll
        for (int kk = 0; kk < 16; kk++) {
            float a[8], bb[8];
            *(float4*)&a[0]  = *(const float4*)&As[kk][ty * 8];
            *(float4*)&a[4]  = *(const float4*)&As[kk][ty * 8 + 4];
            *(float4*)&bb[0] = *(const float4*)&Bs[kk][tx * 8];
            *(float4*)&bb[4] = *(const float4*)&Bs[kk][tx * 8 + 4];
            #pragma unroll
            for (int i = 0; i < 8; i++)
                #pragma unroll
                for (int j = 0; j < 8; j++)
                    acc[i][j] = fmaf(a[i], bb[j], acc[i][j]);
        }
        __syncthreads();
    }
    const float p = dout[OUT_OFF_PSI + bh];
    const float c0 = which ? p : (1.f - p);
    float* dst = g_mblend + (size_t)bh * 16384;
    __nv_bfloat16* mh = g_mbh + (size_t)bh * 16384;
    __nv_bfloat16* ml = g_mbl + (size_t)bh * 16384;
    #pragma unroll
    for (int i = 0; i < 8; i++)
        #pragma unroll
        for (int j = 0; j < 8; j += 2) {
            int idx = (ty * 8 + i) * 128 + tx * 8 + j;
            if (which == 0) {
                dst[idx]     = c0 * acc[i][j];
                dst[idx + 1] = c0 * acc[i][j + 1];
            } else {
                float v0 = dst[idx]     + c0 * acc[i][j];
                float v1 = dst[idx + 1] + c0 * acc[i][j + 1];
                split2w(v0, v1, mh + idx, ml + idx);
            }
        }
}

// ======================= launch =======================
extern "C" void kernel_launch(void* const* d_in, const int* in_sizes, int n_in,
                              void* d_out, int out_size) {
    (void)in_sizes; (void)n_in; (void)out_size;
    const float* x          = (const float*)d_in[0];
    const float* Mf_prev    = (const float*)d_in[1];
    const float* Ms_prev    = (const float*)d_in[2];
    const float* Wq         = (const float*)d_in[3];
    const float* Wk         = (const float*)d_in[4];
    const float* Wv         = (const float*)d_in[5];
    const float* Wo         = (const float*)d_in[6];
    const float* Wb         = (const float*)d_in[7];
    const float* fast_slope = (const float*)d_in[8];
    const float* slow_slope = (const float*)d_in[9];
    const float* inter_fast = (const float*)d_in[10];
    const float* inter_slow = (const float*)d_in[11];
    const float* S_fast     = (const float*)d_in[12];
    const float* S_slow     = (const float*)d_in[13];
    const float* f1_w       = (const float*)d_in[14];
    const float* f1_b       = (const float*)d_in[15];
    const float* f2_w       = (const float*)d_in[16];
    const float* f2_b       = (const float*)d_in[17];
    float* out = (float*)d_out;

    const int tg_smem = 2 * TSTG * 4;         // 73728
    const int mp_smem = 2 * MP_STG * 2;       // 69632
    const int ob_smem = 2 * OB_STG * 2;       // 75776
    static bool attr_set = false;
    if (!attr_set) {
        cudaFuncSetAttribute(k_tf32_gemm,  cudaFuncAttributeMaxDynamicSharedMemorySize, tg_smem);
        cudaFuncSetAttribute(k_mpart_mma,  cudaFuncAttributeMaxDynamicSharedMemorySize, mp_smem);
        cudaFuncSetAttribute(k_oblend_mma, cudaFuncAttributeMaxDynamicSharedMemorySize, ob_smem);
        attr_set = true;
    }

    dim3 t16(16, 16);
    dim3 t328(32, 8);

    // launches ordered so the 6th is the QKV GEMM (ncu -s 5 -c 1 profiles it)
    k_cvt_x<<<32768, 256>>>(x);
    k_wcvt_qkv<<<dim3(64, 192), t328>>>(Wq, Wk, Wv);
    k_meanpart<<<256, 256>>>(x);
    k_meanred<<<32, 256>>>();
    k_mlp1<<<dim3(4, 4), 256>>>(f1_w, f1_b);

    // QKV projection (tf32 single-pass)
    k_tf32_gemm<<<dim3(48, 128), 256, tg_smem>>>(nullptr, 0);

    k_mlp2<<<64, 128>>>(f2_w, f2_b, out);
    k_wcvt_o<<<dim3(64, 64), t328>>>(Wo);

    // per-head path
    k_res<<<dim3(32, 64), t16>>>(Wb, fast_slope, slow_slope);
    k_mpart_mma<<<dim3(8, 64, 2), 256, mp_smem>>>();
    k_mfin<<<dim3(64, 2), 256>>>(Mf_prev, Ms_prev, inter_fast, inter_slow, out);
    k_mref<<<64, t16>>>(S_fast, S_slow, out, 0);
    k_mref<<<64, t16>>>(S_fast, S_slow, out, 1);
    k_oblend_mma<<<dim3(32, 64), 256, ob_smem>>>();

    // output projection (tf32 single-pass)
    k_tf32_gemm<<<dim3(16, 128), 256, tg_smem>>>(out, 1);
}

// round 11
// speedup vs baseline: 3.7932x; 1.4844x over previous
#include <cuda_runtime.h>
#include <cuda_bf16.h>
#include <cuda_fp16.h>
#include <cstdint>
#include <math.h>

static constexpr int B_   = 4;
static constexpr int N_   = 4096;
static constexpr int H_   = 16;
static constexpr int DK_  = 128;
static constexpr int DIM_ = 2048;
static constexpr int BH_  = B_ * H_;      // 64
static constexpr int MROWS_ = B_ * N_;    // 16384
static constexpr float INV_SQRT_DK = 0.08838834764831843f;
static constexpr size_t SLAB = (size_t)N_ * DK_;

static constexpr long long OUT_OFF_MF  = 33554432LL;
static constexpr long long OUT_OFF_MS  = 34603008LL;
static constexpr long long OUT_OFF_PSI = 35651584LL;

// ---------------- scratch (allocation-free: device globals) ----------------
__device__ float g_kf [(size_t)BH_ * SLAB];       // raw k fp32
__device__ float g_part[2LL * BH_ * 8 * DK_ * DK_];
__device__ float g_mblend[(size_t)BH_ * DK_ * DK_];
__device__ float g_meanpart[8 * B_ * DIM_];
__device__ float g_mean[B_ * DIM_];
__device__ float g_h1[B_ * 1024];

// fp16 operands for the two big GEMMs
__device__ __half g_x16 [(size_t)MROWS_ * DIM_];
__device__ __half g_wqkv16[(size_t)6144 * 2048];
__device__ __half g_wo16[(size_t)2048 * 2048];
__device__ __half g_ob16[(size_t)MROWS_ * DIM_];  // o_blend (b,n,h,v)

// per-head bf16 split tensors [bh][n][d] (bf16 3-pass HMMA kernels)
__device__ __nv_bfloat16 g_qh [(size_t)BH_ * SLAB];
__device__ __nv_bfloat16 g_ql [(size_t)BH_ * SLAB];
__device__ __nv_bfloat16 g_vh [(size_t)BH_ * SLAB];
__device__ __nv_bfloat16 g_vl [(size_t)BH_ * SLAB];
__device__ __nv_bfloat16 g_kfh[(size_t)BH_ * SLAB];
__device__ __nv_bfloat16 g_kfl[(size_t)BH_ * SLAB];
__device__ __nv_bfloat16 g_ksh[(size_t)BH_ * SLAB];
__device__ __nv_bfloat16 g_ksl[(size_t)BH_ * SLAB];
__device__ __nv_bfloat16 g_mbh[(size_t)BH_ * DK_ * DK_];
__device__ __nv_bfloat16 g_mbl[(size_t)BH_ * DK_ * DK_];

// ===================== PTX helpers (base-target) ===========================
__device__ __forceinline__ uint32_t smem_u32(const void* p) {
    uint32_t a;
    asm("{ .reg .u64 t; cvta.to.shared.u64 t, %1; cvt.u32.u64 %0, t; }"
        : "=r"(a) : "l"(p));
    return a;
}

#define MMA16816(d, a, b0, b1) \
    asm volatile("mma.sync.aligned.m16n8k16.row.col.f32.bf16.bf16.f32 " \
        "{%0,%1,%2,%3}, {%4,%5,%6,%7}, {%8,%9}, {%0,%1,%2,%3};" \
        : "+f"((d)[0]), "+f"((d)[1]), "+f"((d)[2]), "+f"((d)[3]) \
        : "r"((a)[0]), "r"((a)[1]), "r"((a)[2]), "r"((a)[3]), "r"(b0), "r"(b1))

#define MMAF16(d, a, b0, b1) \
    asm volatile("mma.sync.aligned.m16n8k16.row.col.f32.f16.f16.f32 " \
        "{%0,%1,%2,%3}, {%4,%5,%6,%7}, {%8,%9}, {%0,%1,%2,%3};" \
        : "+f"((d)[0]), "+f"((d)[1]), "+f"((d)[2]), "+f"((d)[3]) \
        : "r"((a)[0]), "r"((a)[1]), "r"((a)[2]), "r"((a)[3]), "r"(b0), "r"(b1))

#define LDSM_X4(r, addr) \
    asm volatile("ldmatrix.sync.aligned.m8n8.x4.shared.b16 {%0,%1,%2,%3}, [%4];" \
        : "=r"((r)[0]), "=r"((r)[1]), "=r"((r)[2]), "=r"((r)[3]) : "r"(addr))
#define LDSM_X4_T(r, addr) \
    asm volatile("ldmatrix.sync.aligned.m8n8.x4.trans.shared.b16 {%0,%1,%2,%3}, [%4];" \
        : "=r"((r)[0]), "=r"((r)[1]), "=r"((r)[2]), "=r"((r)[3]) : "r"(addr))

#define CP_ASYNC16(dst, src) \
    asm volatile("cp.async.cg.shared.global [%0], [%1], 16;" \
        :: "r"(dst), "l"(src) : "memory")
#define CP_COMMIT() asm volatile("cp.async.commit_group;" ::: "memory")
#define CP_WAIT(n)  asm volatile("cp.async.wait_group %0;" :: "n"(n) : "memory")

__device__ __forceinline__ void split2w(float a, float b,
                                        __nv_bfloat16* ph, __nv_bfloat16* pl) {
    __nv_bfloat16 h0 = __float2bfloat16_rn(a), h1 = __float2bfloat16_rn(b);
    __nv_bfloat16 l0 = __float2bfloat16_rn(a - __bfloat162float(h0));
    __nv_bfloat16 l1 = __float2bfloat16_rn(b - __bfloat162float(h1));
    __nv_bfloat162 hh; hh.x = h0; hh.y = h1;
    __nv_bfloat162 ll; ll.x = l0; ll.y = l1;
    *(__nv_bfloat162*)ph = hh;
    *(__nv_bfloat162*)pl = ll;
}

// ======================= fp16 prep =======================
__global__ void k_cvt_x(const float* __restrict__ x) {
    size_t i = ((size_t)blockIdx.x * 256 + threadIdx.x) * 4;
    float4 v = *(const float4*)(x + i);
    __half2 a = __floats2half2_rn(v.x, v.y);
    __half2 b = __floats2half2_rn(v.z, v.w);
    *(__half2*)(g_x16 + i) = a;
    *(__half2*)(g_x16 + i + 2) = b;
}

__global__ void k_wcvt_qkv(const float* __restrict__ Wq, const float* __restrict__ Wk,
                           const float* __restrict__ Wv) {
    __shared__ float tile[32][33];
    int k0 = blockIdx.x * 32, n0 = blockIdx.y * 32;
    int which = n0 >> 11;
    const float* __restrict__ W = (which == 0) ? Wq : (which == 1 ? Wk : Wv);
    int nn0 = n0 & 2047;
    for (int r = threadIdx.y; r < 32; r += 8)
        tile[r][threadIdx.x] = W[(size_t)(k0 + r) * 2048 + nn0 + threadIdx.x];
    __syncthreads();
    for (int r = threadIdx.y; r < 32; r += 8)
        g_wqkv16[(size_t)(n0 + r) * 2048 + k0 + threadIdx.x] = __float2half_rn(tile[threadIdx.x][r]);
}

__global__ void k_wcvt_o(const float* __restrict__ Wo) {
    __shared__ float tile[32][33];
    int k0 = blockIdx.x * 32, n0 = blockIdx.y * 32;
    for (int r = threadIdx.y; r < 32; r += 8)
        tile[r][threadIdx.x] = Wo[(size_t)(k0 + r) * 2048 + n0 + threadIdx.x];
    __syncthreads();
    for (int r = threadIdx.y; r < 32; r += 8)
        g_wo16[(size_t)(n0 + r) * 2048 + k0 + threadIdx.x] = __float2half_rn(tile[threadIdx.x][r]);
}

// ======================= fp16 single-pass GEMM =============================
// C = A @ B^T; A [M][2048], B [Ntot][2048] fp16 K-major.
// 128x128 CTA tile, warp tile 32x64, BK=32, 2-stage cp.async, ldmatrix.
// Static smem: 2 stages x 2 tiles x [128][40] halves = 40960 B.
__global__ __launch_bounds__(256)
void k_f16_gemm(float* __restrict__ Cout, int mode) {
    __shared__ __align__(16) __half sm[2][2][128][40];
    const __half* __restrict__ A  = (mode == 0) ? g_x16  : g_ob16;
    const __half* __restrict__ Bm = (mode == 0) ? g_wqkv16 : g_wo16;

    const uint32_t sbase = smem_u32(sm);
    const int tid = threadIdx.x;
    const int wid = tid >> 5, lane = tid & 31;
    const int wr = wid >> 1, wc = wid & 1;
    const int j0 = blockIdx.x * 128;
    const int m0 = blockIdx.y * 128;
    const int l15 = lane & 15;
    const int lhalf = (lane >> 4) * 8;

    float acc[2][8][4];
    #pragma unroll
    for (int i = 0; i < 2; i++)
        #pragma unroll
        for (int j = 0; j < 8; j++)
            #pragma unroll
            for (int k = 0; k < 4; k++) acc[i][j][k] = 0.f;

    // 1024 16B segs per chunk (A 512 + B 512), 4 per thread
    int gl_isB[4], gl_r[4], gl_q[4];
    #pragma unroll
    for (int i = 0; i < 4; i++) {
        int idx = i * 256 + tid;
        gl_isB[i] = idx >> 9;
        int rem = idx & 511;
        gl_r[i] = rem >> 2;
        gl_q[i] = rem & 3;
    }

    auto issue = [&](int c, int st) {
        #pragma unroll
        for (int i = 0; i < 4; i++) {
            const __half* src = (gl_isB[i] ? Bm + (size_t)(j0 + gl_r[i]) * 2048
                                           : A  + (size_t)(m0 + gl_r[i]) * 2048)
                                + c * 32 + gl_q[i] * 8;
            uint32_t dst = sbase +
                (uint32_t)(((st * 2 + gl_isB[i]) * 128 + gl_r[i]) * 40 + gl_q[i] * 8) * 2;
            CP_ASYNC16(dst, src);
        }
        CP_COMMIT();
    };

    issue(0, 0);
    for (int c = 0; c < 64; c++) {
        if (c < 63) { issue(c + 1, (c + 1) & 1); CP_WAIT(1); }
        else        { CP_WAIT(0); }
        __syncthreads();
        const uint32_t stg = sbase + (uint32_t)((c & 1) * 2 * 128 * 40) * 2;

        #pragma unroll
        for (int s = 0; s < 2; s++) {
            const uint32_t kcol = (uint32_t)(s * 16 + lhalf) * 2;
            uint32_t af[2][4], bf[4][4];
            #pragma unroll
            for (int i = 0; i < 2; i++) {
                uint32_t ar = stg + (uint32_t)((wr * 32 + i * 16 + l15) * 40) * 2 + kcol;
                LDSM_X4(af[i], ar);
            }
            #pragma unroll
            for (int p = 0; p < 4; p++) {
                uint32_t br = stg + (uint32_t)((128 + wc * 64 + p * 16 + l15) * 40) * 2 + kcol;
                LDSM_X4(bf[p], br);
            }
            #pragma unroll
            for (int i = 0; i < 2; i++)
                #pragma unroll
                for (int t = 0; t < 8; t++) {
                    const int p = t >> 1, sel = t & 1;
                    MMAF16(acc[i][t], af[i], bf[p][sel], bf[p][sel + 2]);
                }
        }
        __syncthreads();
    }

    // epilogue (C frag: c0,c1 at (gr, lane2), c2,c3 at (gr+8, lane2))
    const int gr = lane >> 2;
    const int lane2 = (lane & 3) * 2;
    if (mode == 0) {
        const int which = j0 >> 11;
        const int h = (j0 >> 7) & 15;
        const int b = m0 >> 12;
        const size_t slab = (size_t)(b * 16 + h) * SLAB;
        if (which == 1) {
            float* dst0 = g_kf + slab;
            #pragma unroll
            for (int i = 0; i < 2; i++) {
                int n = (m0 & 4095) + wr * 32 + i * 16 + gr;
                #pragma unroll
                for (int t = 0; t < 8; t++) {
                    int col = wc * 64 + t * 8 + lane2;
                    float* dst = dst0 + (size_t)n * 128 + col;
                    *(float2*)dst = make_float2(acc[i][t][0], acc[i][t][1]);
                    *(float2*)(dst + 8 * 128) = make_float2(acc[i][t][2], acc[i][t][3]);
                }
            }
        } else {
            __nv_bfloat16* dh = ((which == 0) ? g_qh : g_vh) + slab;
            __nv_bfloat16* dl = ((which == 0) ? g_ql : g_vl) + slab;
            #pragma unroll
            for (int i = 0; i < 2; i++) {
                int n = (m0 & 4095) + wr * 32 + i * 16 + gr;
                #pragma unroll
                for (int t = 0; t < 8; t++) {
                    int col = wc * 64 + t * 8 + lane2;
                    size_t o0 = (size_t)n * 128 + col;
                    split2w(acc[i][t][0], acc[i][t][1], dh + o0, dl + o0);
                    split2w(acc[i][t][2], acc[i][t][3], dh + o0 + 8 * 128, dl + o0 + 8 * 128);
                }
            }
        }
    } else {
        #pragma unroll
        for (int i = 0; i < 2; i++) {
            int m = m0 + wr * 32 + i * 16 + gr;
            #pragma unroll
            for (int t = 0; t < 8; t++) {
                int col = j0 + wc * 64 + t * 8 + lane2;
                float* dst = Cout + (size_t)m * 2048 + col;
                *(float2*)dst = make_float2(acc[i][t][0], acc[i][t][1]);
                *(float2*)(dst + 8 * 2048) = make_float2(acc[i][t][2], acc[i][t][3]);
            }
        }
    }
}

// ======================= k_mpart HMMA (bf16 3-pass, unchanged) ==============
static constexpr int MP_STG = 4 * 32 * 136;

__global__ __launch_bounds__(256)
void k_mpart_mma() {
    extern __shared__ __align__(16) __nv_bfloat16 smb[];
    const int split = blockIdx.x, bh = blockIdx.y, which = blockIdx.z;
    const __nv_bfloat16* srcs[4] = {
        ((which ? g_ksh : g_kfh) + (size_t)bh * SLAB),
        ((which ? g_ksl : g_kfl) + (size_t)bh * SLAB),
        (g_vh + (size_t)bh * SLAB),
        (g_vl + (size_t)bh * SLAB)
    };
    const uint32_t sbase = smem_u32(smb);
    const int tid = threadIdx.x;
    const int wid = tid >> 5, lane = tid & 31;
    const int wr = wid >> 1, wc = wid & 1;

    float acc[2][8][4];
    #pragma unroll
    for (int i = 0; i < 2; i++)
        #pragma unroll
        for (int j = 0; j < 8; j++)
            #pragma unroll
            for (int k = 0; k < 4; k++) acc[i][j][k] = 0.f;

    int gl_t[8], gl_r[8], gl_q[8];
    #pragma unroll
    for (int i = 0; i < 8; i++) {
        int idx = i * 256 + tid;
        gl_t[i] = idx >> 9;
        int rem = idx & 511;
        gl_r[i] = rem >> 4;
        gl_q[i] = rem & 15;
    }

    auto issue = [&](int c, int st) {
        #pragma unroll
        for (int i = 0; i < 8; i++) {
            const __nv_bfloat16* src = srcs[gl_t[i]]
                + (size_t)(split * 512 + c * 32 + gl_r[i]) * 128 + gl_q[i] * 8;
            uint32_t dst = sbase +
                (uint32_t)(st * MP_STG + gl_t[i] * 4352 + gl_r[i] * 136 + gl_q[i] * 8) * 2;
            CP_ASYNC16(dst, src);
        }
        CP_COMMIT();
    };

    const int rofs = (lane & 7) + ((lane >> 4) << 3);
    const int cofs = (lane & 8);

    issue(0, 0);
    for (int c = 0; c < 16; c++) {
        if (c < 15) { issue(c + 1, (c + 1) & 1); CP_WAIT(1); }
        else        { CP_WAIT(0); }
        __syncthreads();
        const uint32_t stg = sbase + (uint32_t)((c & 1) * MP_STG) * 2;

        #pragma unroll
        for (int ks = 0; ks < 2; ks++) {
            const int rowk = ks * 16 + rofs;
            uint32_t ah[2][4], al[2][4], bhf[4][4], blf[4][4];
            #pragma unroll
            for (int i = 0; i < 2; i++) {
                uint32_t ad = stg + (uint32_t)(rowk * 136 + wr * 32 + i * 16 + cofs) * 2;
                LDSM_X4_T(ah[i], ad);
                LDSM_X4_T(al[i], ad + (uint32_t)4352 * 2);
            }
            #pragma unroll
            for (int p = 0; p < 4; p++) {
                uint32_t bd = stg + (uint32_t)(2 * 4352 + rowk * 136 + wc * 64 + p * 16 + cofs) * 2;
                LDSM_X4_T(bhf[p], bd);
                LDSM_X4_T(blf[p], bd + (uint32_t)4352 * 2);
            }
            #pragma unroll
            for (int i = 0; i < 2; i++)
                #pragma unroll
                for (int t = 0; t < 8; t++) {
                    const int p = t >> 1, sel = t & 1;
                    MMA16816(acc[i][t], ah[i], bhf[p][sel], bhf[p][sel + 2]);
                }
            #pragma unroll
            for (int i = 0; i < 2; i++)
                #pragma unroll
                for (int t = 0; t < 8; t++) {
                    const int p = t >> 1, sel = t & 1;
                    MMA16816(acc[i][t], ah[i], blf[p][sel], blf[p][sel + 2]);
                }
            #pragma unroll
            for (int i = 0; i < 2; i++)
                #pragma unroll
                for (int t = 0; t < 8; t++) {
                    const int p = t >> 1, sel = t & 1;
                    MMA16816(acc[i][t], al[i], bhf[p][sel], bhf[p][sel + 2]);
                }
        }
        __syncthreads();
    }

    const int gr = lane >> 2;
    const int lane2 = (lane & 3) * 2;
    float* dst0 = g_part + (((size_t)which * BH_ + bh) * 8 + split) * 16384;
    #pragma unroll
    for (int i = 0; i < 2; i++) {
        int m = wr * 32 + i * 16 + gr;
        #pragma unroll
        for (int t = 0; t < 8; t++) {
            int col = wc * 64 + t * 8 + lane2;
            float* dst = dst0 + m * 128 + col;
            *(float2*)dst = make_float2(acc[i][t][0], acc[i][t][1]);
            *(float2*)(dst + 8 * 128) = make_float2(acc[i][t][2], acc[i][t][3]);
        }
    }
}

// ======================= k_oblend HMMA (bf16 3-pass, fp16 out) ==============
static constexpr int OB_STG = 2 * 128 * 40 + 2 * 32 * 136;

__global__ __launch_bounds__(256)
void k_oblend_mma() {
    extern __shared__ __align__(16) __nv_bfloat16 smb[];
    const int bh = blockIdx.y;
    const int m0 = blockIdx.x * 128;
    const __nv_bfloat16* qsrc[2] = { g_qh + (size_t)bh * SLAB, g_ql + (size_t)bh * SLAB };
    const __nv_bfloat16* msrc[2] = { g_mbh + (size_t)bh * 16384, g_mbl + (size_t)bh * 16384 };
    const uint32_t sbase = smem_u32(smb);
    const int tid = threadIdx.x;
    const int wid = tid >> 5, lane = tid & 31;
    const int wr = wid >> 1, wc = wid & 1;
    const int l15 = lane & 15;
    const int lhalf = (lane >> 4) * 8;

    float acc[2][8][4];
    #pragma unroll
    for (int i = 0; i < 2; i++)
        #pragma unroll
        for (int j = 0; j < 8; j++)
            #pragma unroll
            for (int k = 0; k < 4; k++) acc[i][j][k] = 0.f;

    int gA[8], gl_r[8], gl_q[8];
    #pragma unroll
    for (int i = 0; i < 8; i++) {
        int idx = i * 256 + tid;
        if (idx < 1024) {
            gA[i] = idx >> 9;
            int rem = idx & 511;
            gl_r[i] = rem >> 2; gl_q[i] = rem & 3;
        } else {
            gA[i] = 2 + ((idx - 1024) >> 9);
            int rem = (idx - 1024) & 511;
            gl_r[i] = rem >> 4; gl_q[i] = rem & 15;
        }
    }

    auto issue = [&](int c, int st) {
        #pragma unroll
        for (int i = 0; i < 8; i++) {
            const __nv_bfloat16* src;
            uint32_t soff;
            if (gA[i] < 2) {
                src = qsrc[gA[i]] + (size_t)(m0 + gl_r[i]) * 128 + c * 32 + gl_q[i] * 8;
                soff = (uint32_t)(gA[i] * 5120 + gl_r[i] * 40 + gl_q[i] * 8);
            } else {
                src = msrc[gA[i] - 2] + (size_t)(c * 32 + gl_r[i]) * 128 + gl_q[i] * 8;
                soff = (uint32_t)(10240 + (gA[i] - 2) * 4352 + gl_r[i] * 136 + gl_q[i] * 8);
            }
            CP_ASYNC16(sbase + (uint32_t)(st * OB_STG) * 2 + soff * 2, src);
        }
        CP_COMMIT();
    };

    const int rofs = (lane & 7) + ((lane >> 4) << 3);
    const int cofs = (lane & 8);

    issue(0, 0);
    for (int c = 0; c < 4; c++) {
        if (c < 3) { issue(c + 1, (c + 1) & 1); CP_WAIT(1); }
        else       { CP_WAIT(0); }
        __syncthreads();
        const uint32_t stg = sbase + (uint32_t)((c & 1) * OB_STG) * 2;

        #pragma unroll
        for (int s = 0; s < 2; s++) {
            const uint32_t kcol = (uint32_t)(s * 16 + lhalf) * 2;
            const int rowd = s * 16 + rofs;
            uint32_t ah[2][4], al[2][4], bhf[4][4], blf[4][4];
            #pragma unroll
            for (int i = 0; i < 2; i++) {
                uint32_t ar = stg + (uint32_t)((wr * 32 + i * 16 + l15) * 40) * 2 + kcol;
                LDSM_X4(ah[i], ar);
                LDSM_X4(al[i], ar + (uint32_t)5120 * 2);
            }
            #pragma unroll
            for (int p = 0; p < 4; p++) {
                uint32_t bd = stg + (uint32_t)(10240 + rowd * 136 + wc * 64 + p * 16 + cofs) * 2;
                LDSM_X4_T(bhf[p], bd);
                LDSM_X4_T(blf[p], bd + (uint32_t)4352 * 2);
            }
            #pragma unroll
            for (int i = 0; i < 2; i++)
                #pragma unroll
                for (int t = 0; t < 8; t++) {
                    const int p = t >> 1, sel = t & 1;
                    MMA16816(acc[i][t], ah[i], bhf[p][sel], bhf[p][sel + 2]);
                }
            #pragma unroll
            for (int i = 0; i < 2; i++)
                #pragma unroll
                for (int t = 0; t < 8; t++) {
                    const int p = t >> 1, sel = t & 1;
                    MMA16816(acc[i][t], ah[i], blf[p][sel], blf[p][sel + 2]);
                }
            #pragma unroll
            for (int i = 0; i < 2; i++)
                #pragma unroll
                for (int t = 0; t < 8; t++) {
                    const int p = t >> 1, sel = t & 1;
                    MMA16816(acc[i][t], al[i], bhf[p][sel], bhf[p][sel + 2]);
                }
        }
        __syncthreads();
    }

    const int gr = lane >> 2;
    const int lane2 = (lane & 3) * 2;
    const int b = bh >> 4, h = bh & 15;
    #pragma unroll
    for (int i = 0; i < 2; i++) {
        int n = m0 + wr * 32 + i * 16 + gr;
        #pragma unroll
        for (int t = 0; t < 8; t++) {
            int col = wc * 64 + t * 8 + lane2;
            size_t b0 = ((size_t)(b * 4096 + n) * 16 + h) * 128 + col;
            size_t b8 = ((size_t)(b * 4096 + n + 8) * 16 + h) * 128 + col;
            *(__half2*)(g_ob16 + b0) = __floats2half2_rn(acc[i][t][0], acc[i][t][1]);
            *(__half2*)(g_ob16 + b8) = __floats2half2_rn(acc[i][t][2], acc[i][t][3]);
        }
    }
}

// ======================= mean over N =======================
__global__ void k_meanpart(const float* __restrict__ x) {
    int gid = blockIdx.x * 256 + threadIdx.x;
    int sp = gid >> 13;
    int r  = gid & 8191;
    int b = r >> 11, d = r & 2047;
    float s = 0.f;
    int nbeg = sp * 512;
    #pragma unroll 4
    for (int n = nbeg; n < nbeg + 512; n++)
        s += x[(size_t)(b * N_ + n) * DIM_ + d];
    g_meanpart[gid] = s;
}

__global__ void k_meanred() {
    int r = blockIdx.x * 256 + threadIdx.x;
    float s = 0.f;
    #pragma unroll
    for (int sp = 0; sp < 8; sp++) s += g_meanpart[sp * 8192 + r];
    g_mean[r] = s * (1.f / 4096.f);
}

// ======================= gating MLP =======================
__global__ void k_mlp1(const float* __restrict__ f1_w, const float* __restrict__ f1_b) {
    __shared__ float xm[2048];
    int b = blockIdx.x;
    for (int i = threadIdx.x; i < 2048; i += 256) xm[i] = g_mean[b * 2048 + i];
    __syncthreads();
    int j = blockIdx.y * 256 + threadIdx.x;
    float s = 0.f;
    for (int k = 0; k < 2048; k++)
        s = fmaf(xm[k], f1_w[(size_t)k * 1024 + j], s);
    s += f1_b[j];
    g_h1[b * 1024 + j] = s / (1.f + expf(-s));
}

__global__ void k_mlp2(const float* __restrict__ f2_w, const float* __restrict__ f2_b,
                       float* __restrict__ dout) {
    __shared__ float red[128];
    int bh = blockIdx.x;
    int b = bh >> 4, h = bh & 15;
    float s = 0.f;
    for (int k = threadIdx.x; k < 1024; k += 128)
        s = fmaf(g_h1[b * 1024 + k], f2_w[k * 16 + h], s);
    red[threadIdx.x] = s; __syncthreads();
    for (int off = 64; off > 0; off >>= 1) {
        if (threadIdx.x < off) red[threadIdx.x] += red[threadIdx.x + off];
        __syncthreads();
    }
    if (threadIdx.x == 0) {
        float z = red[0] + f2_b[h];
        dout[OUT_OFF_PSI + bh] = 1.f / (1.f + expf(-z));
    }
}

// ======================= resonance + k_mod + decay split =======================
__global__ __launch_bounds__(256, 2)
void k_res(const float* __restrict__ Wb, const float* __restrict__ fast_slope,
           const float* __restrict__ slow_slope) {
    __shared__ float As[16][132];
    __shared__ float Bs[16][128];
    const int m0 = blockIdx.x * 128;
    const int bh = blockIdx.y;
    const int h = bh & 15;
    const size_t slb = (size_t)bh * SLAB;
    const float* __restrict__ kslab = g_kf + slb;
    const float* __restrict__ Wbh = Wb + (size_t)h * DK_ * DK_;
    const int tx = threadIdx.x, ty = threadIdx.y;
    const int tid = ty * 16 + tx;
    float acc[8][8];
    #pragma unroll
    for (int i = 0; i < 8; i++)
        #pragma unroll
        for (int j = 0; j < 8; j++) acc[i][j] = 0.f;

    const int arow = tid >> 2, acol = (tid & 3) * 4;
    const int brow = tid >> 5, bcol = (tid & 31) * 4;

    for (int kt = 0; kt < 128; kt += 16) {
        #pragma unroll
        for (int r = 0; r < 2; r++) {
            int row = arow + r * 64;
            float4 av = *(const float4*)&kslab[(size_t)(m0 + row) * DK_ + kt + acol];
            As[acol + 0][row] = av.x; As[acol + 1][row] = av.y;
            As[acol + 2][row] = av.z; As[acol + 3][row] = av.w;
        }
        #pragma unroll
        for (int r = 0; r < 2; r++) {
            int row = brow + r * 8;
            *(float4*)&Bs[row][bcol] =
                *(const float4*)&Wbh[(size_t)(kt + row) * DK_ + bcol];
        }
        __syncthreads();
        #pragma unroll
        for (int kk = 0; kk < 16; kk++) {
            float a[8], bb[8];
            *(float4*)&a[0]  = *(const float4*)&As[kk][ty * 8];
            *(float4*)&a[4]  = *(const float4*)&As[kk][ty * 8 + 4];
            *(float4*)&bb[0] = *(const float4*)&Bs[kk][tx * 8];
            *(float4*)&bb[4] = *(const float4*)&Bs[kk][tx * 8 + 4];
            #pragma unroll
            for (int i = 0; i < 8; i++)
                #pragma unroll
                for (int j = 0; j < 8; j++)
                    acc[i][j] = fmaf(a[i], bb[j], acc[i][j]);
        }
        __syncthreads();
    }
    const float fs = fast_slope[h], ss = slow_slope[h];
    #pragma unroll
    for (int i = 0; i < 8; i++) {
        int n = m0 + ty * 8 + i;
        float idx = (float)(n - (N_ - 1));
        float fw = expf(fs * idx);
        float sw = expf(ss * idx);
        #pragma unroll
        for (int j = 0; j < 8; j += 4) {
            size_t p = slb + (size_t)n * DK_ + tx * 8 + j;
            float4 kr = *(const float4*)&g_kf[p];
            float kf0, kf1, kf2, kf3, ks0, ks1, ks2, ks3;
            float r0, km;
            r0 = tanhf(acc[i][j+0]); km = kr.x * (1.f + 0.5f * r0) * INV_SQRT_DK; kf0 = km * fw; ks0 = km * sw;
            r0 = tanhf(acc[i][j+1]); km = kr.y * (1.f + 0.5f * r0) * INV_SQRT_DK; kf1 = km * fw; ks1 = km * sw;
            r0 = tanhf(acc[i][j+2]); km = kr.z * (1.f + 0.5f * r0) * INV_SQRT_DK; kf2 = km * fw; ks2 = km * sw;
            r0 = tanhf(acc[i][j+3]); km = kr.w * (1.f + 0.5f * r0) * INV_SQRT_DK; kf3 = km * fw; ks3 = km * sw;
            split2w(kf0, kf1, g_kfh + p,     g_kfl + p);
            split2w(kf2, kf3, g_kfh + p + 2, g_kfl + p + 2);
            split2w(ks0, ks1, g_ksh + p,     g_ksl + p);
            split2w(ks2, ks3, g_ksh + p + 2, g_ksl + p + 2);
        }
    }
}

// ======================= M finalize =======================
__global__ void k_mfin(const float* __restrict__ Mf_prev, const float* __restrict__ Ms_prev,
                       const float* __restrict__ inter_fast, const float* __restrict__ inter_slow,
                       float* __restrict__ dout) {
    const int bh = blockIdx.x;
    const int which = blockIdx.y;
    const int h = bh & 15;
    const float inter = which ? inter_slow[h] : inter_fast[h];
    const float* prev = (which ? Ms_prev : Mf_prev) + (size_t)bh * 16384;
    const float* part = g_part + ((size_t)which * BH_ + bh) * 8 * 16384;
    float* dst = dout + (which ? OUT_OFF_MS : OUT_OFF_MF) + (size_t)bh * 16384;
    for (int e = threadIdx.x; e < 16384; e += 256) {
        float s = 0.f;
        #pragma unroll
        for (int sp = 0; sp < 8; sp++) s += part[(size_t)sp * 16384 + e];
        dst[e] = prev[e] * inter + s;
    }
}

// ======================= Mref = (I+S) @ M, blended -> bf16 split ============
__global__ __launch_bounds__(256, 2)
void k_mref(const float* __restrict__ S_fast, const float* __restrict__ S_slow,
            const float* __restrict__ dout, int which) {
    __shared__ float As[16][132];
    __shared__ float Bs[16][128];
    const int bh = blockIdx.x;
    const int h = bh & 15;
    const float* __restrict__ S = (which ? S_slow : S_fast) + (size_t)h * 16384;
    const float* __restrict__ M = dout + (which ? OUT_OFF_MS : OUT_OFF_MF) + (size_t)bh * 16384;
    const int tx = threadIdx.x, ty = threadIdx.y;
    const int tid = ty * 16 + tx;
    float acc[8][8];
    #pragma unroll
    for (int i = 0; i < 8; i++)
        #pragma unroll
        for (int j = 0; j < 8; j++) acc[i][j] = 0.f;

    const int arow = tid >> 2, acol = (tid & 3) * 4;
    const int brow = tid >> 5, bcol = (tid & 31) * 4;

    for (int kt = 0; kt < 128; kt += 16) {
        #pragma unroll
        for (int r = 0; r < 2; r++) {
            int row = arow + r * 64;
            float4 av = *(const float4*)&S[(size_t)row * 128 + kt + acol];
            As[acol + 0][row] = av.x + ((row == kt + acol + 0) ? 1.f : 0.f);
            As[acol + 1][row] = av.y + ((row == kt + acol + 1) ? 1.f : 0.f);
            As[acol + 2][row] = av.z + ((row == kt + acol + 2) ? 1.f : 0.f);
            As[acol + 3][row] = av.w + ((row == kt + acol + 3) ? 1.f : 0.f);
        }
        #pragma unroll
        for (int r = 0; r < 2; r++) {
            int row = brow + r * 8;
            *(float4*)&Bs[row][bcol] = *(const float4*)&M[(size_t)(kt + row) * 128 + bcol];
        }
        __syncthreads();
        #pragma unroll
        for (int kk = 0; kk < 16; kk++) {
            float a[8], bb[8];
            *(float4*)&a[0]  = *(const float4*)&As[kk][ty * 8];
            *(float4*)&a[4]  = *(const float4*)&As[kk][ty * 8 + 4];
            *(float4*)&bb[0] = *(const float4*)&Bs[kk][tx * 8];
            *(float4*)&bb[4] = *(const float4*)&Bs[kk][tx * 8 + 4];
            #pragma unroll
            for (int i = 0; i < 8; i++)
                #pragma unroll
                for (int j = 0; j < 8; j++)
                    acc[i][j] = fmaf(a[i], bb[j], acc[i][j]);
        }
        __syncthreads();
    }
    const float p = dout[OUT_OFF_PSI + bh];
    const float c0 = which ? p : (1.f - p);
    float* dst = g_mblend + (size_t)bh * 16384;
    __nv_bfloat16* mh = g_mbh + (size_t)bh * 16384;
    __nv_bfloat16* ml = g_mbl + (size_t)bh * 16384;
    #pragma unroll
    for (int i = 0; i < 8; i++)
        #pragma unroll
        for (int j = 0; j < 8; j += 2) {
            int idx = (ty * 8 + i) * 128 + tx * 8 + j;
            if (which == 0) {
                dst[idx]     = c0 * acc[i][j];
                dst[idx + 1] = c0 * acc[i][j + 1];
            } else {
                float v0 = dst[idx]     + c0 * acc[i][j];
                float v1 = dst[idx + 1] + c0 * acc[i][j + 1];
                split2w(v0, v1, mh + idx, ml + idx);
            }
        }
}

// ======================= launch =======================
extern "C" void kernel_launch(void* const* d_in, const int* in_sizes, int n_in,
                              void* d_out, int out_size) {
    (void)in_sizes; (void)n_in; (void)out_size;
    const float* x          = (const float*)d_in[0];
    const float* Mf_prev    = (const float*)d_in[1];
    const float* Ms_prev    = (const float*)d_in[2];
    const float* Wq         = (const float*)d_in[3];
    const float* Wk         = (const float*)d_in[4];
    const float* Wv         = (const float*)d_in[5];
    const float* Wo         = (const float*)d_in[6];
    const float* Wb         = (const float*)d_in[7];
    const float* fast_slope = (const float*)d_in[8];
    const float* slow_slope = (const float*)d_in[9];
    const float* inter_fast = (const float*)d_in[10];
    const float* inter_slow = (const float*)d_in[11];
    const float* S_fast     = (const float*)d_in[12];
    const float* S_slow     = (const float*)d_in[13];
    const float* f1_w       = (const float*)d_in[14];
    const float* f1_b       = (const float*)d_in[15];
    const float* f2_w       = (const float*)d_in[16];
    const float* f2_b       = (const float*)d_in[17];
    float* out = (float*)d_out;

    const int mp_smem = 2 * MP_STG * 2;       // 69632
    const int ob_smem = 2 * OB_STG * 2;       // 75776
    static bool attr_set = false;
    if (!attr_set) {
        cudaFuncSetAttribute(k_mpart_mma,  cudaFuncAttributeMaxDynamicSharedMemorySize, mp_smem);
        cudaFuncSetAttribute(k_oblend_mma, cudaFuncAttributeMaxDynamicSharedMemorySize, ob_smem);
        attr_set = true;
    }

    dim3 t16(16, 16);
    dim3 t328(32, 8);

    // launches ordered so the 6th is the QKV GEMM (ncu -s 5 -c 1 profiles it)
    k_cvt_x<<<32768, 256>>>(x);
    k_wcvt_qkv<<<dim3(64, 192), t328>>>(Wq, Wk, Wv);
    k_meanpart<<<256, 256>>>(x);
    k_meanred<<<32, 256>>>();
    k_mlp1<<<dim3(4, 4), 256>>>(f1_w, f1_b);

    // QKV projection (fp16 single-pass)
    k_f16_gemm<<<dim3(48, 128), 256>>>(nullptr, 0);

    k_mlp2<<<64, 128>>>(f2_w, f2_b, out);
    k_wcvt_o<<<dim3(64, 64), t328>>>(Wo);

    // per-head path
    k_res<<<dim3(32, 64), t16>>>(Wb, fast_slope, slow_slope);
    k_mpart_mma<<<dim3(8, 64, 2), 256, mp_smem>>>();
    k_mfin<<<dim3(64, 2), 256>>>(Mf_prev, Ms_prev, inter_fast, inter_slow, out);
    k_mref<<<64, t16>>>(S_fast, S_slow, out, 0);
    k_mref<<<64, t16>>>(S_fast, S_slow, out, 1);
    k_oblend_mma<<<dim3(32, 64), 256, ob_smem>>>();

    // output projection (fp16 single-pass)
    k_f16_gemm<<<dim3(16, 128), 256>>>(out, 1);
}

// round 12
// speedup vs baseline: 4.1360x; 1.0904x over previous
#include <cuda_runtime.h>
#include <cuda_bf16.h>
#include <cuda_fp16.h>
#include <cstdint>
#include <math.h>

static constexpr int B_   = 4;
static constexpr int N_   = 4096;
static constexpr int H_   = 16;
static constexpr int DK_  = 128;
static constexpr int DIM_ = 2048;
static constexpr int BH_  = B_ * H_;      // 64
static constexpr int MROWS_ = B_ * N_;    // 16384
static constexpr float INV_SQRT_DK = 0.08838834764831843f;
static constexpr size_t SLAB = (size_t)N_ * DK_;

static constexpr long long OUT_OFF_MF  = 33554432LL;
static constexpr long long OUT_OFF_MS  = 34603008LL;
static constexpr long long OUT_OFF_PSI = 35651584LL;

// ---------------- scratch (allocation-free: device globals) ----------------
__device__ float g_kf [(size_t)BH_ * SLAB];       // raw k fp32
__device__ float g_part[2LL * BH_ * 8 * DK_ * DK_];
__device__ float g_mblend[(size_t)BH_ * DK_ * DK_];
__device__ float g_meanpart[8 * B_ * DIM_];
__device__ float g_mean[B_ * DIM_];
__device__ float g_h1[B_ * 1024];

// fp16 operands for the two big GEMMs
__device__ __half g_x16 [(size_t)MROWS_ * DIM_];
__device__ __half g_wqkv16[(size_t)6144 * 2048];
__device__ __half g_wo16[(size_t)2048 * 2048];
__device__ __half g_ob16[(size_t)MROWS_ * DIM_];  // o_blend (b,n,h,v)

// per-head tensors [bh][n][d]
__device__ __nv_bfloat16 g_qh [(size_t)BH_ * SLAB];   // q bf16 split (oblend 3-pass)
__device__ __nv_bfloat16 g_ql [(size_t)BH_ * SLAB];
__device__ __half g_v16 [(size_t)BH_ * SLAB];         // v fp16 single
__device__ __half g_k16 [(size_t)BH_ * SLAB];         // k fp16 (res MMA input)
__device__ __half g_kf16[(size_t)BH_ * SLAB];         // k_fast fp16
__device__ __half g_ks16[(size_t)BH_ * SLAB];         // k_slow fp16
__device__ __half g_wb16[(size_t)H_ * DK_ * DK_];     // W_bilinear fp16
__device__ __nv_bfloat16 g_mbh[(size_t)BH_ * DK_ * DK_];
__device__ __nv_bfloat16 g_mbl[(size_t)BH_ * DK_ * DK_];

// ===================== PTX helpers (base-target) ===========================
__device__ __forceinline__ uint32_t smem_u32(const void* p) {
    uint32_t a;
    asm("{ .reg .u64 t; cvta.to.shared.u64 t, %1; cvt.u32.u64 %0, t; }"
        : "=r"(a) : "l"(p));
    return a;
}

#define MMA16816(d, a, b0, b1) \
    asm volatile("mma.sync.aligned.m16n8k16.row.col.f32.bf16.bf16.f32 " \
        "{%0,%1,%2,%3}, {%4,%5,%6,%7}, {%8,%9}, {%0,%1,%2,%3};" \
        : "+f"((d)[0]), "+f"((d)[1]), "+f"((d)[2]), "+f"((d)[3]) \
        : "r"((a)[0]), "r"((a)[1]), "r"((a)[2]), "r"((a)[3]), "r"(b0), "r"(b1))

#define MMAF16(d, a, b0, b1) \
    asm volatile("mma.sync.aligned.m16n8k16.row.col.f32.f16.f16.f32 " \
        "{%0,%1,%2,%3}, {%4,%5,%6,%7}, {%8,%9}, {%0,%1,%2,%3};" \
        : "+f"((d)[0]), "+f"((d)[1]), "+f"((d)[2]), "+f"((d)[3]) \
        : "r"((a)[0]), "r"((a)[1]), "r"((a)[2]), "r"((a)[3]), "r"(b0), "r"(b1))

#define LDSM_X4(r, addr) \
    asm volatile("ldmatrix.sync.aligned.m8n8.x4.shared.b16 {%0,%1,%2,%3}, [%4];" \
        : "=r"((r)[0]), "=r"((r)[1]), "=r"((r)[2]), "=r"((r)[3]) : "r"(addr))
#define LDSM_X4_T(r, addr) \
    asm volatile("ldmatrix.sync.aligned.m8n8.x4.trans.shared.b16 {%0,%1,%2,%3}, [%4];" \
        : "=r"((r)[0]), "=r"((r)[1]), "=r"((r)[2]), "=r"((r)[3]) : "r"(addr))

#define CP_ASYNC16(dst, src) \
    asm volatile("cp.async.cg.shared.global [%0], [%1], 16;" \
        :: "r"(dst), "l"(src) : "memory")
#define CP_COMMIT() asm volatile("cp.async.commit_group;" ::: "memory")
#define CP_WAIT(n)  asm volatile("cp.async.wait_group %0;" :: "n"(n) : "memory")

__device__ __forceinline__ void split2w(float a, float b,
                                        __nv_bfloat16* ph, __nv_bfloat16* pl) {
    __nv_bfloat16 h0 = __float2bfloat16_rn(a), h1 = __float2bfloat16_rn(b);
    __nv_bfloat16 l0 = __float2bfloat16_rn(a - __bfloat162float(h0));
    __nv_bfloat16 l1 = __float2bfloat16_rn(b - __bfloat162float(h1));
    __nv_bfloat162 hh; hh.x = h0; hh.y = h1;
    __nv_bfloat162 ll; ll.x = l0; ll.y = l1;
    *(__nv_bfloat162*)ph = hh;
    *(__nv_bfloat162*)pl = ll;
}

// ======================= prep =======================
__global__ void k_cvt_x(const float* __restrict__ x) {
    size_t i = ((size_t)blockIdx.x * 256 + threadIdx.x) * 4;
    float4 v = *(const float4*)(x + i);
    *(__half2*)(g_x16 + i) = __floats2half2_rn(v.x, v.y);
    *(__half2*)(g_x16 + i + 2) = __floats2half2_rn(v.z, v.w);
}

__global__ void k_wcvt_qkv(const float* __restrict__ Wq, const float* __restrict__ Wk,
                           const float* __restrict__ Wv) {
    __shared__ float tile[32][33];
    int k0 = blockIdx.x * 32, n0 = blockIdx.y * 32;
    int which = n0 >> 11;
    const float* __restrict__ W = (which == 0) ? Wq : (which == 1 ? Wk : Wv);
    int nn0 = n0 & 2047;
    for (int r = threadIdx.y; r < 32; r += 8)
        tile[r][threadIdx.x] = W[(size_t)(k0 + r) * 2048 + nn0 + threadIdx.x];
    __syncthreads();
    for (int r = threadIdx.y; r < 32; r += 8)
        g_wqkv16[(size_t)(n0 + r) * 2048 + k0 + threadIdx.x] = __float2half_rn(tile[threadIdx.x][r]);
}

__global__ void k_wcvt_o(const float* __restrict__ Wo) {
    __shared__ float tile[32][33];
    int k0 = blockIdx.x * 32, n0 = blockIdx.y * 32;
    for (int r = threadIdx.y; r < 32; r += 8)
        tile[r][threadIdx.x] = Wo[(size_t)(k0 + r) * 2048 + n0 + threadIdx.x];
    __syncthreads();
    for (int r = threadIdx.y; r < 32; r += 8)
        g_wo16[(size_t)(n0 + r) * 2048 + k0 + threadIdx.x] = __float2half_rn(tile[threadIdx.x][r]);
}

__global__ void k_wcvt_b(const float* __restrict__ Wb) {
    int i = (blockIdx.x * 256 + threadIdx.x) * 4;
    float4 v = *(const float4*)(Wb + i);
    *(__half2*)(g_wb16 + i) = __floats2half2_rn(v.x, v.y);
    *(__half2*)(g_wb16 + i + 2) = __floats2half2_rn(v.z, v.w);
}

// ======================= fp16 single-pass main GEMM ========================
__global__ __launch_bounds__(256)
void k_f16_gemm(float* __restrict__ Cout, int mode) {
    __shared__ __align__(16) __half sm[2][2][128][40];
    const __half* __restrict__ A  = (mode == 0) ? g_x16  : g_ob16;
    const __half* __restrict__ Bm = (mode == 0) ? g_wqkv16 : g_wo16;

    const uint32_t sbase = smem_u32(sm);
    const int tid = threadIdx.x;
    const int wid = tid >> 5, lane = tid & 31;
    const int wr = wid >> 1, wc = wid & 1;
    const int j0 = blockIdx.x * 128;
    const int m0 = blockIdx.y * 128;
    const int l15 = lane & 15;
    const int lhalf = (lane >> 4) * 8;

    float acc[2][8][4];
    #pragma unroll
    for (int i = 0; i < 2; i++)
        #pragma unroll
        for (int j = 0; j < 8; j++)
            #pragma unroll
            for (int k = 0; k < 4; k++) acc[i][j][k] = 0.f;

    int gl_isB[4], gl_r[4], gl_q[4];
    #pragma unroll
    for (int i = 0; i < 4; i++) {
        int idx = i * 256 + tid;
        gl_isB[i] = idx >> 9;
        int rem = idx & 511;
        gl_r[i] = rem >> 2;
        gl_q[i] = rem & 3;
    }

    auto issue = [&](int c, int st) {
        #pragma unroll
        for (int i = 0; i < 4; i++) {
            const __half* src = (gl_isB[i] ? Bm + (size_t)(j0 + gl_r[i]) * 2048
                                           : A  + (size_t)(m0 + gl_r[i]) * 2048)
                                + c * 32 + gl_q[i] * 8;
            uint32_t dst = sbase +
                (uint32_t)(((st * 2 + gl_isB[i]) * 128 + gl_r[i]) * 40 + gl_q[i] * 8) * 2;
            CP_ASYNC16(dst, src);
        }
        CP_COMMIT();
    };

    issue(0, 0);
    for (int c = 0; c < 64; c++) {
        if (c < 63) { issue(c + 1, (c + 1) & 1); CP_WAIT(1); }
        else        { CP_WAIT(0); }
        __syncthreads();
        const uint32_t stg = sbase + (uint32_t)((c & 1) * 2 * 128 * 40) * 2;

        #pragma unroll
        for (int s = 0; s < 2; s++) {
            const uint32_t kcol = (uint32_t)(s * 16 + lhalf) * 2;
            uint32_t af[2][4], bf[4][4];
            #pragma unroll
            for (int i = 0; i < 2; i++) {
                uint32_t ar = stg + (uint32_t)((wr * 32 + i * 16 + l15) * 40) * 2 + kcol;
                LDSM_X4(af[i], ar);
            }
            #pragma unroll
            for (int p = 0; p < 4; p++) {
                uint32_t br = stg + (uint32_t)((128 + wc * 64 + p * 16 + l15) * 40) * 2 + kcol;
                LDSM_X4(bf[p], br);
            }
            #pragma unroll
            for (int i = 0; i < 2; i++)
                #pragma unroll
                for (int t = 0; t < 8; t++) {
                    const int p = t >> 1, sel = t & 1;
                    MMAF16(acc[i][t], af[i], bf[p][sel], bf[p][sel + 2]);
                }
        }
        __syncthreads();
    }

    const int gr = lane >> 2;
    const int lane2 = (lane & 3) * 2;
    if (mode == 0) {
        const int which = j0 >> 11;
        const int h = (j0 >> 7) & 15;
        const int b = m0 >> 12;
        const size_t slab = (size_t)(b * 16 + h) * SLAB;
        if (which == 0) {
            __nv_bfloat16* dh = g_qh + slab;
            __nv_bfloat16* dl = g_ql + slab;
            #pragma unroll
            for (int i = 0; i < 2; i++) {
                int n = (m0 & 4095) + wr * 32 + i * 16 + gr;
                #pragma unroll
                for (int t = 0; t < 8; t++) {
                    int col = wc * 64 + t * 8 + lane2;
                    size_t o0 = (size_t)n * 128 + col;
                    split2w(acc[i][t][0], acc[i][t][1], dh + o0, dl + o0);
                    split2w(acc[i][t][2], acc[i][t][3], dh + o0 + 8 * 128, dl + o0 + 8 * 128);
                }
            }
        } else if (which == 1) {
            float* dst0 = g_kf + slab;
            __half* d16 = g_k16 + slab;
            #pragma unroll
            for (int i = 0; i < 2; i++) {
                int n = (m0 & 4095) + wr * 32 + i * 16 + gr;
                #pragma unroll
                for (int t = 0; t < 8; t++) {
                    int col = wc * 64 + t * 8 + lane2;
                    size_t o0 = (size_t)n * 128 + col;
                    *(float2*)(dst0 + o0) = make_float2(acc[i][t][0], acc[i][t][1]);
                    *(float2*)(dst0 + o0 + 8 * 128) = make_float2(acc[i][t][2], acc[i][t][3]);
                    *(__half2*)(d16 + o0) = __floats2half2_rn(acc[i][t][0], acc[i][t][1]);
                    *(__half2*)(d16 + o0 + 8 * 128) = __floats2half2_rn(acc[i][t][2], acc[i][t][3]);
                }
            }
        } else {
            __half* d16 = g_v16 + slab;
            #pragma unroll
            for (int i = 0; i < 2; i++) {
                int n = (m0 & 4095) + wr * 32 + i * 16 + gr;
                #pragma unroll
                for (int t = 0; t < 8; t++) {
                    int col = wc * 64 + t * 8 + lane2;
                    size_t o0 = (size_t)n * 128 + col;
                    *(__half2*)(d16 + o0) = __floats2half2_rn(acc[i][t][0], acc[i][t][1]);
                    *(__half2*)(d16 + o0 + 8 * 128) = __floats2half2_rn(acc[i][t][2], acc[i][t][3]);
                }
            }
        }
    } else {
        #pragma unroll
        for (int i = 0; i < 2; i++) {
            int m = m0 + wr * 32 + i * 16 + gr;
            #pragma unroll
            for (int t = 0; t < 8; t++) {
                int col = j0 + wc * 64 + t * 8 + lane2;
                float* dst = Cout + (size_t)m * 2048 + col;
                *(float2*)dst = make_float2(acc[i][t][0], acc[i][t][1]);
                *(float2*)(dst + 8 * 2048) = make_float2(acc[i][t][2], acc[i][t][3]);
            }
        }
    }
}

// ======================= k_res via fp16 MMA ================================
// res[n][e] = k[n][:] @ Wb[h][:][e]; epilogue: tanh/k_mod/decay -> kf16/ks16.
static constexpr int RS_STG = 128 * 40 + 32 * 136;   // 9472 halves per stage

__global__ __launch_bounds__(256)
void k_res_mma(const float* __restrict__ fast_slope, const float* __restrict__ slow_slope) {
    __shared__ __align__(16) __half sm[2][RS_STG];
    const int bh = blockIdx.y;
    const int m0 = blockIdx.x * 128;
    const int h = bh & 15;
    const __half* __restrict__ kslab = g_k16 + (size_t)bh * SLAB;
    const __half* __restrict__ wb = g_wb16 + (size_t)h * 16384;
    const uint32_t sbase = smem_u32(sm);
    const int tid = threadIdx.x;
    const int wid = tid >> 5, lane = tid & 31;
    const int wr = wid >> 1, wc = wid & 1;
    const int l15 = lane & 15;
    const int lhalf = (lane >> 4) * 8;

    float acc[2][8][4];
    #pragma unroll
    for (int i = 0; i < 2; i++)
        #pragma unroll
        for (int j = 0; j < 8; j++)
            #pragma unroll
            for (int k = 0; k < 4; k++) acc[i][j][k] = 0.f;

    int gA[4], gl_r[4], gl_q[4];
    #pragma unroll
    for (int i = 0; i < 4; i++) {
        int idx = i * 256 + tid;
        if (idx < 512) { gA[i] = 0; gl_r[i] = idx >> 2; gl_q[i] = idx & 3; }
        else { int l = idx - 512; gA[i] = 1; gl_r[i] = l >> 4; gl_q[i] = l & 15; }
    }

    auto issue = [&](int c, int st) {
        #pragma unroll
        for (int i = 0; i < 4; i++) {
            const __half* src;
            uint32_t soff;
            if (gA[i] == 0) {
                src = kslab + (size_t)(m0 + gl_r[i]) * 128 + c * 32 + gl_q[i] * 8;
                soff = (uint32_t)(gl_r[i] * 40 + gl_q[i] * 8);
            } else {
                src = wb + (size_t)(c * 32 + gl_r[i]) * 128 + gl_q[i] * 8;
                soff = (uint32_t)(5120 + gl_r[i] * 136 + gl_q[i] * 8);
            }
            CP_ASYNC16(sbase + (uint32_t)(st * RS_STG) * 2 + soff * 2, src);
        }
        CP_COMMIT();
    };

    const int rofs = (lane & 7) + ((lane >> 4) << 3);
    const int cofs = (lane & 8);

    issue(0, 0);
    for (int c = 0; c < 4; c++) {
        if (c < 3) { issue(c + 1, (c + 1) & 1); CP_WAIT(1); }
        else       { CP_WAIT(0); }
        __syncthreads();
        const uint32_t stg = sbase + (uint32_t)((c & 1) * RS_STG) * 2;

        #pragma unroll
        for (int s = 0; s < 2; s++) {
            const uint32_t kcol = (uint32_t)(s * 16 + lhalf) * 2;
            const int rowd = s * 16 + rofs;
            uint32_t af[2][4], bf[4][4];
            #pragma unroll
            for (int i = 0; i < 2; i++) {
                uint32_t ar = stg + (uint32_t)((wr * 32 + i * 16 + l15) * 40) * 2 + kcol;
                LDSM_X4(af[i], ar);
            }
            #pragma unroll
            for (int p = 0; p < 4; p++) {
                uint32_t bd = stg + (uint32_t)(5120 + rowd * 136 + wc * 64 + p * 16 + cofs) * 2;
                LDSM_X4_T(bf[p], bd);
            }
            #pragma unroll
            for (int i = 0; i < 2; i++)
                #pragma unroll
                for (int t = 0; t < 8; t++) {
                    const int p = t >> 1, sel = t & 1;
                    MMAF16(acc[i][t], af[i], bf[p][sel], bf[p][sel + 2]);
                }
        }
        __syncthreads();
    }

    // epilogue: k_mod + decay split -> fp16
    const int gr = lane >> 2;
    const int lane2 = (lane & 3) * 2;
    const float fs = fast_slope[h], ss = slow_slope[h];
    const size_t slb = (size_t)bh * SLAB;
    #pragma unroll
    for (int i = 0; i < 2; i++) {
        int n = m0 + wr * 32 + i * 16 + gr;
        float fw0 = expf(fs * (float)(n - (N_ - 1)));
        float sw0 = expf(ss * (float)(n - (N_ - 1)));
        float fw1 = expf(fs * (float)(n + 8 - (N_ - 1)));
        float sw1 = expf(ss * (float)(n + 8 - (N_ - 1)));
        #pragma unroll
        for (int t = 0; t < 8; t++) {
            int col = wc * 64 + t * 8 + lane2;
            size_t p0 = slb + (size_t)n * 128 + col;
            size_t p8 = p0 + 8 * 128;
            float2 k0 = *(const float2*)(g_kf + p0);
            float2 k8 = *(const float2*)(g_kf + p8);
            float r, km0, km1;
            r = tanhf(acc[i][t][0]); km0 = k0.x * (1.f + 0.5f * r) * INV_SQRT_DK;
            r = tanhf(acc[i][t][1]); km1 = k0.y * (1.f + 0.5f * r) * INV_SQRT_DK;
            *(__half2*)(g_kf16 + p0) = __floats2half2_rn(km0 * fw0, km1 * fw0);
            *(__half2*)(g_ks16 + p0) = __floats2half2_rn(km0 * sw0, km1 * sw0);
            r = tanhf(acc[i][t][2]); km0 = k8.x * (1.f + 0.5f * r) * INV_SQRT_DK;
            r = tanhf(acc[i][t][3]); km1 = k8.y * (1.f + 0.5f * r) * INV_SQRT_DK;
            *(__half2*)(g_kf16 + p8) = __floats2half2_rn(km0 * fw1, km1 * fw1);
            *(__half2*)(g_ks16 + p8) = __floats2half2_rn(km0 * sw1, km1 * sw1);
        }
    }
}

// ======================= k_mpart fp16 1-pass ===============================
static constexpr int MP_STG = 2 * 32 * 136;          // 8704 halves per stage

__global__ __launch_bounds__(256)
void k_mpart_f16() {
    __shared__ __align__(16) __half sm[2][MP_STG];
    const int split = blockIdx.x, bh = blockIdx.y, which = blockIdx.z;
    const __half* __restrict__ kslab = (which ? g_ks16 : g_kf16) + (size_t)bh * SLAB;
    const __half* __restrict__ vslab = g_v16 + (size_t)bh * SLAB;
    const uint32_t sbase = smem_u32(sm);
    const int tid = threadIdx.x;
    const int wid = tid >> 5, lane = tid & 31;
    const int wr = wid >> 1, wc = wid & 1;

    float acc[2][8][4];
    #pragma unroll
    for (int i = 0; i < 2; i++)
        #pragma unroll
        for (int j = 0; j < 8; j++)
            #pragma unroll
            for (int k = 0; k < 4; k++) acc[i][j][k] = 0.f;

    int gl_t[4], gl_r[4], gl_q[4];
    #pragma unroll
    for (int i = 0; i < 4; i++) {
        int idx = i * 256 + tid;
        gl_t[i] = idx >> 9;
        int rem = idx & 511;
        gl_r[i] = rem >> 4;
        gl_q[i] = rem & 15;
    }

    auto issue = [&](int c, int st) {
        #pragma unroll
        for (int i = 0; i < 4; i++) {
            const __half* src = (gl_t[i] ? vslab : kslab)
                + (size_t)(split * 512 + c * 32 + gl_r[i]) * 128 + gl_q[i] * 8;
            uint32_t dst = sbase +
                (uint32_t)(st * MP_STG + gl_t[i] * 4352 + gl_r[i] * 136 + gl_q[i] * 8) * 2;
            CP_ASYNC16(dst, src);
        }
        CP_COMMIT();
    };

    const int rofs = (lane & 7) + ((lane >> 4) << 3);
    const int cofs = (lane & 8);

    issue(0, 0);
    for (int c = 0; c < 16; c++) {
        if (c < 15) { issue(c + 1, (c + 1) & 1); CP_WAIT(1); }
        else        { CP_WAIT(0); }
        __syncthreads();
        const uint32_t stg = sbase + (uint32_t)((c & 1) * MP_STG) * 2;

        #pragma unroll
        for (int ks = 0; ks < 2; ks++) {
            const int rowk = ks * 16 + rofs;
            uint32_t af[2][4], bf[4][4];
            #pragma unroll
            for (int i = 0; i < 2; i++) {
                uint32_t ad = stg + (uint32_t)(rowk * 136 + wr * 32 + i * 16 + cofs) * 2;
                LDSM_X4_T(af[i], ad);
            }
            #pragma unroll
            for (int p = 0; p < 4; p++) {
                uint32_t bd = stg + (uint32_t)(4352 + rowk * 136 + wc * 64 + p * 16 + cofs) * 2;
                LDSM_X4_T(bf[p], bd);
            }
            #pragma unroll
            for (int i = 0; i < 2; i++)
                #pragma unroll
                for (int t = 0; t < 8; t++) {
                    const int p = t >> 1, sel = t & 1;
                    MMAF16(acc[i][t], af[i], bf[p][sel], bf[p][sel + 2]);
                }
        }
        __syncthreads();
    }

    const int gr = lane >> 2;
    const int lane2 = (lane & 3) * 2;
    float* dst0 = g_part + (((size_t)which * BH_ + bh) * 8 + split) * 16384;
    #pragma unroll
    for (int i = 0; i < 2; i++) {
        int m = wr * 32 + i * 16 + gr;
        #pragma unroll
        for (int t = 0; t < 8; t++) {
            int col = wc * 64 + t * 8 + lane2;
            float* dst = dst0 + m * 128 + col;
            *(float2*)dst = make_float2(acc[i][t][0], acc[i][t][1]);
            *(float2*)(dst + 8 * 128) = make_float2(acc[i][t][2], acc[i][t][3]);
        }
    }
}

// ======================= k_oblend HMMA (bf16 3-pass, unchanged) =============
static constexpr int OB_STG = 2 * 128 * 40 + 2 * 32 * 136;

__global__ __launch_bounds__(256)
void k_oblend_mma() {
    extern __shared__ __align__(16) __nv_bfloat16 smb[];
    const int bh = blockIdx.y;
    const int m0 = blockIdx.x * 128;
    const __nv_bfloat16* qsrc[2] = { g_qh + (size_t)bh * SLAB, g_ql + (size_t)bh * SLAB };
    const __nv_bfloat16* msrc[2] = { g_mbh + (size_t)bh * 16384, g_mbl + (size_t)bh * 16384 };
    const uint32_t sbase = smem_u32(smb);
    const int tid = threadIdx.x;
    const int wid = tid >> 5, lane = tid & 31;
    const int wr = wid >> 1, wc = wid & 1;
    const int l15 = lane & 15;
    const int lhalf = (lane >> 4) * 8;

    float acc[2][8][4];
    #pragma unroll
    for (int i = 0; i < 2; i++)
        #pragma unroll
        for (int j = 0; j < 8; j++)
            #pragma unroll
            for (int k = 0; k < 4; k++) acc[i][j][k] = 0.f;

    int gA[8], gl_r[8], gl_q[8];
    #pragma unroll
    for (int i = 0; i < 8; i++) {
        int idx = i * 256 + tid;
        if (idx < 1024) {
            gA[i] = idx >> 9;
            int rem = idx & 511;
            gl_r[i] = rem >> 2; gl_q[i] = rem & 3;
        } else {
            gA[i] = 2 + ((idx - 1024) >> 9);
            int rem = (idx - 1024) & 511;
            gl_r[i] = rem >> 4; gl_q[i] = rem & 15;
        }
    }

    auto issue = [&](int c, int st) {
        #pragma unroll
        for (int i = 0; i < 8; i++) {
            const __nv_bfloat16* src;
            uint32_t soff;
            if (gA[i] < 2) {
                src = qsrc[gA[i]] + (size_t)(m0 + gl_r[i]) * 128 + c * 32 + gl_q[i] * 8;
                soff = (uint32_t)(gA[i] * 5120 + gl_r[i] * 40 + gl_q[i] * 8);
            } else {
                src = msrc[gA[i] - 2] + (size_t)(c * 32 + gl_r[i]) * 128 + gl_q[i] * 8;
                soff = (uint32_t)(10240 + (gA[i] - 2) * 4352 + gl_r[i] * 136 + gl_q[i] * 8);
            }
            CP_ASYNC16(sbase + (uint32_t)(st * OB_STG) * 2 + soff * 2, src);
        }
        CP_COMMIT();
    };

    const int rofs = (lane & 7) + ((lane >> 4) << 3);
    const int cofs = (lane & 8);

    issue(0, 0);
    for (int c = 0; c < 4; c++) {
        if (c < 3) { issue(c + 1, (c + 1) & 1); CP_WAIT(1); }
        else       { CP_WAIT(0); }
        __syncthreads();
        const uint32_t stg = sbase + (uint32_t)((c & 1) * OB_STG) * 2;

        #pragma unroll
        for (int s = 0; s < 2; s++) {
            const uint32_t kcol = (uint32_t)(s * 16 + lhalf) * 2;
            const int rowd = s * 16 + rofs;
            uint32_t ah[2][4], al[2][4], bhf[4][4], blf[4][4];
            #pragma unroll
            for (int i = 0; i < 2; i++) {
                uint32_t ar = stg + (uint32_t)((wr * 32 + i * 16 + l15) * 40) * 2 + kcol;
                LDSM_X4(ah[i], ar);
                LDSM_X4(al[i], ar + (uint32_t)5120 * 2);
            }
            #pragma unroll
            for (int p = 0; p < 4; p++) {
                uint32_t bd = stg + (uint32_t)(10240 + rowd * 136 + wc * 64 + p * 16 + cofs) * 2;
                LDSM_X4_T(bhf[p], bd);
                LDSM_X4_T(blf[p], bd + (uint32_t)4352 * 2);
            }
            #pragma unroll
            for (int i = 0; i < 2; i++)
                #pragma unroll
                for (int t = 0; t < 8; t++) {
                    const int p = t >> 1, sel = t & 1;
                    MMA16816(acc[i][t], ah[i], bhf[p][sel], bhf[p][sel + 2]);
                }
            #pragma unroll
            for (int i = 0; i < 2; i++)
                #pragma unroll
                for (int t = 0; t < 8; t++) {
                    const int p = t >> 1, sel = t & 1;
                    MMA16816(acc[i][t], ah[i], blf[p][sel], blf[p][sel + 2]);
                }
            #pragma unroll
            for (int i = 0; i < 2; i++)
                #pragma unroll
                for (int t = 0; t < 8; t++) {
                    const int p = t >> 1, sel = t & 1;
                    MMA16816(acc[i][t], al[i], bhf[p][sel], bhf[p][sel + 2]);
                }
        }
        __syncthreads();
    }

    const int gr = lane >> 2;
    const int lane2 = (lane & 3) * 2;
    const int b = bh >> 4, h = bh & 15;
    #pragma unroll
    for (int i = 0; i < 2; i++) {
        int n = m0 + wr * 32 + i * 16 + gr;
        #pragma unroll
        for (int t = 0; t < 8; t++) {
            int col = wc * 64 + t * 8 + lane2;
            size_t b0 = ((size_t)(b * 4096 + n) * 16 + h) * 128 + col;
            size_t b8 = ((size_t)(b * 4096 + n + 8) * 16 + h) * 128 + col;
            *(__half2*)(g_ob16 + b0) = __floats2half2_rn(acc[i][t][0], acc[i][t][1]);
            *(__half2*)(g_ob16 + b8) = __floats2half2_rn(acc[i][t][2], acc[i][t][3]);
        }
    }
}

// ======================= mean over N =======================
__global__ void k_meanpart(const float* __restrict__ x) {
    int gid = blockIdx.x * 256 + threadIdx.x;
    int sp = gid >> 13;
    int r  = gid & 8191;
    int b = r >> 11, d = r & 2047;
    float s = 0.f;
    int nbeg = sp * 512;
    #pragma unroll 8
    for (int n = nbeg; n < nbeg + 512; n++)
        s += x[(size_t)(b * N_ + n) * DIM_ + d];
    g_meanpart[gid] = s;
}

__global__ void k_meanred() {
    int r = blockIdx.x * 256 + threadIdx.x;
    float s = 0.f;
    #pragma unroll
    for (int sp = 0; sp < 8; sp++) s += g_meanpart[sp * 8192 + r];
    g_mean[r] = s * (1.f / 4096.f);
}

// ======================= gating MLP =======================
__global__ void k_mlp1(const float* __restrict__ f1_w, const float* __restrict__ f1_b) {
    __shared__ float xm[2048];
    int b = blockIdx.x;
    for (int i = threadIdx.x; i < 2048; i += 256) xm[i] = g_mean[b * 2048 + i];
    __syncthreads();
    int j = blockIdx.y * 256 + threadIdx.x;
    float s = 0.f;
    for (int k = 0; k < 2048; k++)
        s = fmaf(xm[k], f1_w[(size_t)k * 1024 + j], s);
    s += f1_b[j];
    g_h1[b * 1024 + j] = s / (1.f + expf(-s));
}

__global__ void k_mlp2(const float* __restrict__ f2_w, const float* __restrict__ f2_b,
                       float* __restrict__ dout) {
    __shared__ float red[128];
    int bh = blockIdx.x;
    int b = bh >> 4, h = bh & 15;
    float s = 0.f;
    for (int k = threadIdx.x; k < 1024; k += 128)
        s = fmaf(g_h1[b * 1024 + k], f2_w[k * 16 + h], s);
    red[threadIdx.x] = s; __syncthreads();
    for (int off = 64; off > 0; off >>= 1) {
        if (threadIdx.x < off) red[threadIdx.x] += red[threadIdx.x + off];
        __syncthreads();
    }
    if (threadIdx.x == 0) {
        float z = red[0] + f2_b[h];
        dout[OUT_OFF_PSI + bh] = 1.f / (1.f + expf(-z));
    }
}

// ======================= M finalize =======================
__global__ void k_mfin(const float* __restrict__ Mf_prev, const float* __restrict__ Ms_prev,
                       const float* __restrict__ inter_fast, const float* __restrict__ inter_slow,
                       float* __restrict__ dout) {
    const int bh = blockIdx.x;
    const int which = blockIdx.y;
    const int h = bh & 15;
    const float inter = which ? inter_slow[h] : inter_fast[h];
    const float* prev = (which ? Ms_prev : Mf_prev) + (size_t)bh * 16384;
    const float* part = g_part + ((size_t)which * BH_ + bh) * 8 * 16384;
    float* dst = dout + (which ? OUT_OFF_MS : OUT_OFF_MF) + (size_t)bh * 16384;
    for (int e = threadIdx.x; e < 16384; e += 256) {
        float s = 0.f;
        #pragma unroll
        for (int sp = 0; sp < 8; sp++) s += part[(size_t)sp * 16384 + e];
        dst[e] = prev[e] * inter + s;
    }
}

// ======================= Mref = (I+S) @ M, blended -> bf16 split ============
__global__ __launch_bounds__(256, 2)
void k_mref(const float* __restrict__ S_fast, const float* __restrict__ S_slow,
            const float* __restrict__ dout, int which) {
    __shared__ float As[16][132];
    __shared__ float Bs[16][128];
    const int bh = blockIdx.x;
    const int h = bh & 15;
    const float* __restrict__ S = (which ? S_slow : S_fast) + (size_t)h * 16384;
    const float* __restrict__ M = dout + (which ? OUT_OFF_MS : OUT_OFF_MF) + (size_t)bh * 16384;
    const int tx = threadIdx.x, ty = threadIdx.y;
    const int tid = ty * 16 + tx;
    float acc[8][8];
    #pragma unroll
    for (int i = 0; i < 8; i++)
        #pragma unroll
        for (int j = 0; j < 8; j++) acc[i][j] = 0.f;

    const int arow = tid >> 2, acol = (tid & 3) * 4;
    const int brow = tid >> 5, bcol = (tid & 31) * 4;

    for (int kt = 0; kt < 128; kt += 16) {
        #pragma unroll
        for (int r = 0; r < 2; r++) {
            int row = arow + r * 64;
            float4 av = *(const float4*)&S[(size_t)row * 128 + kt + acol];
            As[acol + 0][row] = av.x + ((row == kt + acol + 0) ? 1.f : 0.f);
            As[acol + 1][row] = av.y + ((row == kt + acol + 1) ? 1.f : 0.f);
            As[acol + 2][row] = av.z + ((row == kt + acol + 2) ? 1.f : 0.f);
            As[acol + 3][row] = av.w + ((row == kt + acol + 3) ? 1.f : 0.f);
        }
        #pragma unroll
        for (int r = 0; r < 2; r++) {
            int row = brow + r * 8;
            *(float4*)&Bs[row][bcol] = *(const float4*)&M[(size_t)(kt + row) * 128 + bcol];
        }
        __syncthreads();
        #pragma unroll
        for (int kk = 0; kk < 16; kk++) {
            float a[8], bb[8];
            *(float4*)&a[0]  = *(const float4*)&As[kk][ty * 8];
            *(float4*)&a[4]  = *(const float4*)&As[kk][ty * 8 + 4];
            *(float4*)&bb[0] = *(const float4*)&Bs[kk][tx * 8];
            *(float4*)&bb[4] = *(const float4*)&Bs[kk][tx * 8 + 4];
            #pragma unroll
            for (int i = 0; i < 8; i++)
                #pragma unroll
                for (int j = 0; j < 8; j++)
                    acc[i][j] = fmaf(a[i], bb[j], acc[i][j]);
        }
        __syncthreads();
    }
    const float p = dout[OUT_OFF_PSI + bh];
    const float c0 = which ? p : (1.f - p);
    float* dst = g_mblend + (size_t)bh * 16384;
    __nv_bfloat16* mh = g_mbh + (size_t)bh * 16384;
    __nv_bfloat16* ml = g_mbl + (size_t)bh * 16384;
    #pragma unroll
    for (int i = 0; i < 8; i++)
        #pragma unroll
        for (int j = 0; j < 8; j += 2) {
            int idx = (ty * 8 + i) * 128 + tx * 8 + j;
            if (which == 0) {
                dst[idx]     = c0 * acc[i][j];
                dst[idx + 1] = c0 * acc[i][j + 1];
            } else {
                float v0 = dst[idx]     + c0 * acc[i][j];
                float v1 = dst[idx + 1] + c0 * acc[i][j + 1];
                split2w(v0, v1, mh + idx, ml + idx);
            }
        }
}

// ======================= launch =======================
extern "C" void kernel_launch(void* const* d_in, const int* in_sizes, int n_in,
                              void* d_out, int out_size) {
    (void)in_sizes; (void)n_in; (void)out_size;
    const float* x          = (const float*)d_in[0];
    const float* Mf_prev    = (const float*)d_in[1];
    const float* Ms_prev    = (const float*)d_in[2];
    const float* Wq         = (const float*)d_in[3];
    const float* Wk         = (const float*)d_in[4];
    const float* Wv         = (const float*)d_in[5];
    const float* Wo         = (const float*)d_in[6];
    const float* Wb         = (const float*)d_in[7];
    const float* fast_slope = (const float*)d_in[8];
    const float* slow_slope = (const float*)d_in[9];
    const float* inter_fast = (const float*)d_in[10];
    const float* inter_slow = (const float*)d_in[11];
    const float* S_fast     = (const float*)d_in[12];
    const float* S_slow     = (const float*)d_in[13];
    const float* f1_w       = (const float*)d_in[14];
    const float* f1_b       = (const float*)d_in[15];
    const float* f2_w       = (const float*)d_in[16];
    const float* f2_b       = (const float*)d_in[17];
    float* out = (float*)d_out;

    const int ob_smem = 2 * OB_STG * 2;       // 75776
    static bool attr_set = false;
    if (!attr_set) {
        cudaFuncSetAttribute(k_oblend_mma, cudaFuncAttributeMaxDynamicSharedMemorySize, ob_smem);
        attr_set = true;
    }

    dim3 t16(16, 16);
    dim3 t328(32, 8);

    // launches ordered so the 6th is the QKV GEMM (ncu -s 5 -c 1 profiles it)
    k_cvt_x<<<32768, 256>>>(x);
    k_wcvt_qkv<<<dim3(64, 192), t328>>>(Wq, Wk, Wv);
    k_meanpart<<<256, 256>>>(x);
    k_meanred<<<32, 256>>>();
    k_mlp1<<<dim3(4, 4), 256>>>(f1_w, f1_b);

    // QKV projection (fp16 single-pass)
    k_f16_gemm<<<dim3(48, 128), 256>>>(nullptr, 0);

    k_mlp2<<<64, 128>>>(f2_w, f2_b, out);
    k_wcvt_o<<<dim3(64, 64), t328>>>(Wo);
    k_wcvt_b<<<256, 256>>>(Wb);

    // per-head path
    k_res_mma<<<dim3(32, 64), 256>>>(fast_slope, slow_slope);
    k_mpart_f16<<<dim3(8, 64, 2), 256>>>();
    k_mfin<<<dim3(64, 2), 256>>>(Mf_prev, Ms_prev, inter_fast, inter_slow, out);
    k_mref<<<64, t16>>>(S_fast, S_slow, out, 0);
    k_mref<<<64, t16>>>(S_fast, S_slow, out, 1);
    k_oblend_mma<<<dim3(32, 64), 256, ob_smem>>>();

    // output projection (fp16 single-pass)
    k_f16_gemm<<<dim3(16, 128), 256>>>(out, 1);
}

// round 13
// speedup vs baseline: 4.2737x; 1.0333x over previous
#include <cuda_runtime.h>
#include <cuda_bf16.h>
#include <cuda_fp16.h>
#include <cstdint>
#include <math.h>

static constexpr int B_   = 4;
static constexpr int N_   = 4096;
static constexpr int H_   = 16;
static constexpr int DK_  = 128;
static constexpr int DIM_ = 2048;
static constexpr int BH_  = B_ * H_;      // 64
static constexpr int MROWS_ = B_ * N_;    // 16384
static constexpr float INV_SQRT_DK = 0.08838834764831843f;
static constexpr size_t SLAB = (size_t)N_ * DK_;

static constexpr long long OUT_OFF_MF  = 33554432LL;
static constexpr long long OUT_OFF_MS  = 34603008LL;
static constexpr long long OUT_OFF_PSI = 35651584LL;

// ---------------- scratch (allocation-free: device globals) ----------------
__device__ float g_kf [(size_t)BH_ * SLAB];       // raw k fp32
__device__ float g_part[2LL * BH_ * 8 * DK_ * DK_];
__device__ float g_mblend[(size_t)BH_ * DK_ * DK_];
__device__ float g_meanpart[8 * B_ * DIM_];
__device__ float g_mean[B_ * DIM_];
__device__ float g_h1[B_ * 1024];

// fp16 operands
__device__ __half g_x16 [(size_t)MROWS_ * DIM_];
__device__ __half g_wqkv16[(size_t)6144 * 2048];
__device__ __half g_wo16[(size_t)2048 * 2048];
__device__ __half g_ob16[(size_t)MROWS_ * DIM_];  // o_blend (b,n,h,v)

// per-head fp16 tensors [bh][n][d]
__device__ __half g_q16 [(size_t)BH_ * SLAB];
__device__ __half g_v16 [(size_t)BH_ * SLAB];
__device__ __half g_k16 [(size_t)BH_ * SLAB];
__device__ __half g_kf16[(size_t)BH_ * SLAB];
__device__ __half g_ks16[(size_t)BH_ * SLAB];
__device__ __half g_wb16[(size_t)H_ * DK_ * DK_];
__device__ __half g_mb16[(size_t)BH_ * DK_ * DK_];   // blended state fp16

// ===================== PTX helpers (base-target) ===========================
__device__ __forceinline__ uint32_t smem_u32(const void* p) {
    uint32_t a;
    asm("{ .reg .u64 t; cvta.to.shared.u64 t, %1; cvt.u32.u64 %0, t; }"
        : "=r"(a) : "l"(p));
    return a;
}

#define MMAF16(d, a, b0, b1) \
    asm volatile("mma.sync.aligned.m16n8k16.row.col.f32.f16.f16.f32 " \
        "{%0,%1,%2,%3}, {%4,%5,%6,%7}, {%8,%9}, {%0,%1,%2,%3};" \
        : "+f"((d)[0]), "+f"((d)[1]), "+f"((d)[2]), "+f"((d)[3]) \
        : "r"((a)[0]), "r"((a)[1]), "r"((a)[2]), "r"((a)[3]), "r"(b0), "r"(b1))

#define LDSM_X4(r, addr) \
    asm volatile("ldmatrix.sync.aligned.m8n8.x4.shared.b16 {%0,%1,%2,%3}, [%4];" \
        : "=r"((r)[0]), "=r"((r)[1]), "=r"((r)[2]), "=r"((r)[3]) : "r"(addr))
#define LDSM_X4_T(r, addr) \
    asm volatile("ldmatrix.sync.aligned.m8n8.x4.trans.shared.b16 {%0,%1,%2,%3}, [%4];" \
        : "=r"((r)[0]), "=r"((r)[1]), "=r"((r)[2]), "=r"((r)[3]) : "r"(addr))

#define CP_ASYNC16(dst, src) \
    asm volatile("cp.async.cg.shared.global [%0], [%1], 16;" \
        :: "r"(dst), "l"(src) : "memory")
#define CP_COMMIT() asm volatile("cp.async.commit_group;" ::: "memory")
#define CP_WAIT(n)  asm volatile("cp.async.wait_group %0;" :: "n"(n) : "memory")

// ======================= fused x convert + mean partial ====================
__global__ void k_cvtmean(const float* __restrict__ x) {
    int gid = blockIdx.x * 256 + threadIdx.x;
    int sp = gid >> 13;
    int r  = gid & 8191;
    int b = r >> 11, d = r & 2047;
    float s = 0.f;
    int nbeg = sp * 512;
    #pragma unroll 8
    for (int n = nbeg; n < nbeg + 512; n++) {
        size_t idx = (size_t)(b * N_ + n) * DIM_ + d;
        float v = x[idx];
        s += v;
        g_x16[idx] = __float2half_rn(v);
    }
    g_meanpart[gid] = s;
}

__global__ void k_meanred() {
    int r = blockIdx.x * 256 + threadIdx.x;
    float s = 0.f;
    #pragma unroll
    for (int sp = 0; sp < 8; sp++) s += g_meanpart[sp * 8192 + r];
    g_mean[r] = s * (1.f / 4096.f);
}

// ======================= weight prep =======================
__global__ void k_wcvt_qkv(const float* __restrict__ Wq, const float* __restrict__ Wk,
                           const float* __restrict__ Wv) {
    __shared__ float tile[32][33];
    int k0 = blockIdx.x * 32, n0 = blockIdx.y * 32;
    int which = n0 >> 11;
    const float* __restrict__ W = (which == 0) ? Wq : (which == 1 ? Wk : Wv);
    int nn0 = n0 & 2047;
    for (int r = threadIdx.y; r < 32; r += 8)
        tile[r][threadIdx.x] = W[(size_t)(k0 + r) * 2048 + nn0 + threadIdx.x];
    __syncthreads();
    for (int r = threadIdx.y; r < 32; r += 8)
        g_wqkv16[(size_t)(n0 + r) * 2048 + k0 + threadIdx.x] = __float2half_rn(tile[threadIdx.x][r]);
}

__global__ void k_wcvt_o(const float* __restrict__ Wo) {
    __shared__ float tile[32][33];
    int k0 = blockIdx.x * 32, n0 = blockIdx.y * 32;
    for (int r = threadIdx.y; r < 32; r += 8)
        tile[r][threadIdx.x] = Wo[(size_t)(k0 + r) * 2048 + n0 + threadIdx.x];
    __syncthreads();
    for (int r = threadIdx.y; r < 32; r += 8)
        g_wo16[(size_t)(n0 + r) * 2048 + k0 + threadIdx.x] = __float2half_rn(tile[threadIdx.x][r]);
}

__global__ void k_wcvt_b(const float* __restrict__ Wb) {
    int i = (blockIdx.x * 256 + threadIdx.x) * 4;
    float4 v = *(const float4*)(Wb + i);
    *(__half2*)(g_wb16 + i) = __floats2half2_rn(v.x, v.y);
    *(__half2*)(g_wb16 + i + 2) = __floats2half2_rn(v.z, v.w);
}

// ======================= fp16 single-pass main GEMM ========================
__global__ __launch_bounds__(256)
void k_f16_gemm(float* __restrict__ Cout, int mode) {
    __shared__ __align__(16) __half sm[2][2][128][40];
    const __half* __restrict__ A  = (mode == 0) ? g_x16  : g_ob16;
    const __half* __restrict__ Bm = (mode == 0) ? g_wqkv16 : g_wo16;

    const uint32_t sbase = smem_u32(sm);
    const int tid = threadIdx.x;
    const int wid = tid >> 5, lane = tid & 31;
    const int wr = wid >> 1, wc = wid & 1;
    const int j0 = blockIdx.x * 128;
    const int m0 = blockIdx.y * 128;
    const int l15 = lane & 15;
    const int lhalf = (lane >> 4) * 8;

    float acc[2][8][4];
    #pragma unroll
    for (int i = 0; i < 2; i++)
        #pragma unroll
        for (int j = 0; j < 8; j++)
            #pragma unroll
            for (int k = 0; k < 4; k++) acc[i][j][k] = 0.f;

    int gl_isB[4], gl_r[4], gl_q[4];
    #pragma unroll
    for (int i = 0; i < 4; i++) {
        int idx = i * 256 + tid;
        gl_isB[i] = idx >> 9;
        int rem = idx & 511;
        gl_r[i] = rem >> 2;
        gl_q[i] = rem & 3;
    }

    auto issue = [&](int c, int st) {
        #pragma unroll
        for (int i = 0; i < 4; i++) {
            const __half* src = (gl_isB[i] ? Bm + (size_t)(j0 + gl_r[i]) * 2048
                                           : A  + (size_t)(m0 + gl_r[i]) * 2048)
                                + c * 32 + gl_q[i] * 8;
            uint32_t dst = sbase +
                (uint32_t)(((st * 2 + gl_isB[i]) * 128 + gl_r[i]) * 40 + gl_q[i] * 8) * 2;
            CP_ASYNC16(dst, src);
        }
        CP_COMMIT();
    };

    issue(0, 0);
    for (int c = 0; c < 64; c++) {
        if (c < 63) { issue(c + 1, (c + 1) & 1); CP_WAIT(1); }
        else        { CP_WAIT(0); }
        __syncthreads();
        const uint32_t stg = sbase + (uint32_t)((c & 1) * 2 * 128 * 40) * 2;

        #pragma unroll
        for (int s = 0; s < 2; s++) {
            const uint32_t kcol = (uint32_t)(s * 16 + lhalf) * 2;
            uint32_t af[2][4], bf[4][4];
            #pragma unroll
            for (int i = 0; i < 2; i++) {
                uint32_t ar = stg + (uint32_t)((wr * 32 + i * 16 + l15) * 40) * 2 + kcol;
                LDSM_X4(af[i], ar);
            }
            #pragma unroll
            for (int p = 0; p < 4; p++) {
                uint32_t br = stg + (uint32_t)((128 + wc * 64 + p * 16 + l15) * 40) * 2 + kcol;
                LDSM_X4(bf[p], br);
            }
            #pragma unroll
            for (int i = 0; i < 2; i++)
                #pragma unroll
                for (int t = 0; t < 8; t++) {
                    const int p = t >> 1, sel = t & 1;
                    MMAF16(acc[i][t], af[i], bf[p][sel], bf[p][sel + 2]);
                }
        }
        __syncthreads();
    }

    const int gr = lane >> 2;
    const int lane2 = (lane & 3) * 2;
    if (mode == 0) {
        const int which = j0 >> 11;
        const int h = (j0 >> 7) & 15;
        const int b = m0 >> 12;
        const size_t slab = (size_t)(b * 16 + h) * SLAB;
        if (which == 1) {
            float* dst0 = g_kf + slab;
            __half* d16 = g_k16 + slab;
            #pragma unroll
            for (int i = 0; i < 2; i++) {
                int n = (m0 & 4095) + wr * 32 + i * 16 + gr;
                #pragma unroll
                for (int t = 0; t < 8; t++) {
                    int col = wc * 64 + t * 8 + lane2;
                    size_t o0 = (size_t)n * 128 + col;
                    *(float2*)(dst0 + o0) = make_float2(acc[i][t][0], acc[i][t][1]);
                    *(float2*)(dst0 + o0 + 8 * 128) = make_float2(acc[i][t][2], acc[i][t][3]);
                    *(__half2*)(d16 + o0) = __floats2half2_rn(acc[i][t][0], acc[i][t][1]);
                    *(__half2*)(d16 + o0 + 8 * 128) = __floats2half2_rn(acc[i][t][2], acc[i][t][3]);
                }
            }
        } else {
            __half* d16 = ((which == 0) ? g_q16 : g_v16) + slab;
            #pragma unroll
            for (int i = 0; i < 2; i++) {
                int n = (m0 & 4095) + wr * 32 + i * 16 + gr;
                #pragma unroll
                for (int t = 0; t < 8; t++) {
                    int col = wc * 64 + t * 8 + lane2;
                    size_t o0 = (size_t)n * 128 + col;
                    *(__half2*)(d16 + o0) = __floats2half2_rn(acc[i][t][0], acc[i][t][1]);
                    *(__half2*)(d16 + o0 + 8 * 128) = __floats2half2_rn(acc[i][t][2], acc[i][t][3]);
                }
            }
        }
    } else {
        #pragma unroll
        for (int i = 0; i < 2; i++) {
            int m = m0 + wr * 32 + i * 16 + gr;
            #pragma unroll
            for (int t = 0; t < 8; t++) {
                int col = j0 + wc * 64 + t * 8 + lane2;
                float* dst = Cout + (size_t)m * 2048 + col;
                *(float2*)dst = make_float2(acc[i][t][0], acc[i][t][1]);
                *(float2*)(dst + 8 * 2048) = make_float2(acc[i][t][2], acc[i][t][3]);
            }
        }
    }
}

// ======================= k_res via fp16 MMA ================================
static constexpr int RS_STG = 128 * 40 + 32 * 136;   // 9472 halves per stage

__global__ __launch_bounds__(256)
void k_res_mma(const float* __restrict__ fast_slope, const float* __restrict__ slow_slope) {
    __shared__ __align__(16) __half sm[2][RS_STG];
    const int bh = blockIdx.y;
    const int m0 = blockIdx.x * 128;
    const int h = bh & 15;
    const __half* __restrict__ kslab = g_k16 + (size_t)bh * SLAB;
    const __half* __restrict__ wb = g_wb16 + (size_t)h * 16384;
    const uint32_t sbase = smem_u32(sm);
    const int tid = threadIdx.x;
    const int wid = tid >> 5, lane = tid & 31;
    const int wr = wid >> 1, wc = wid & 1;
    const int l15 = lane & 15;
    const int lhalf = (lane >> 4) * 8;

    float acc[2][8][4];
    #pragma unroll
    for (int i = 0; i < 2; i++)
        #pragma unroll
        for (int j = 0; j < 8; j++)
            #pragma unroll
            for (int k = 0; k < 4; k++) acc[i][j][k] = 0.f;

    int gA[4], gl_r[4], gl_q[4];
    #pragma unroll
    for (int i = 0; i < 4; i++) {
        int idx = i * 256 + tid;
        if (idx < 512) { gA[i] = 0; gl_r[i] = idx >> 2; gl_q[i] = idx & 3; }
        else { int l = idx - 512; gA[i] = 1; gl_r[i] = l >> 4; gl_q[i] = l & 15; }
    }

    auto issue = [&](int c, int st) {
        #pragma unroll
        for (int i = 0; i < 4; i++) {
            const __half* src;
            uint32_t soff;
            if (gA[i] == 0) {
                src = kslab + (size_t)(m0 + gl_r[i]) * 128 + c * 32 + gl_q[i] * 8;
                soff = (uint32_t)(gl_r[i] * 40 + gl_q[i] * 8);
            } else {
                src = wb + (size_t)(c * 32 + gl_r[i]) * 128 + gl_q[i] * 8;
                soff = (uint32_t)(5120 + gl_r[i] * 136 + gl_q[i] * 8);
            }
            CP_ASYNC16(sbase + (uint32_t)(st * RS_STG) * 2 + soff * 2, src);
        }
        CP_COMMIT();
    };

    const int rofs = (lane & 7) + ((lane >> 4) << 3);
    const int cofs = (lane & 8);

    issue(0, 0);
    for (int c = 0; c < 4; c++) {
        if (c < 3) { issue(c + 1, (c + 1) & 1); CP_WAIT(1); }
        else       { CP_WAIT(0); }
        __syncthreads();
        const uint32_t stg = sbase + (uint32_t)((c & 1) * RS_STG) * 2;

        #pragma unroll
        for (int s = 0; s < 2; s++) {
            const uint32_t kcol = (uint32_t)(s * 16 + lhalf) * 2;
            const int rowd = s * 16 + rofs;
            uint32_t af[2][4], bf[4][4];
            #pragma unroll
            for (int i = 0; i < 2; i++) {
                uint32_t ar = stg + (uint32_t)((wr * 32 + i * 16 + l15) * 40) * 2 + kcol;
                LDSM_X4(af[i], ar);
            }
            #pragma unroll
            for (int p = 0; p < 4; p++) {
                uint32_t bd = stg + (uint32_t)(5120 + rowd * 136 + wc * 64 + p * 16 + cofs) * 2;
                LDSM_X4_T(bf[p], bd);
            }
            #pragma unroll
            for (int i = 0; i < 2; i++)
                #pragma unroll
                for (int t = 0; t < 8; t++) {
                    const int p = t >> 1, sel = t & 1;
                    MMAF16(acc[i][t], af[i], bf[p][sel], bf[p][sel + 2]);
                }
        }
        __syncthreads();
    }

    const int gr = lane >> 2;
    const int lane2 = (lane & 3) * 2;
    const float fs = fast_slope[h], ss = slow_slope[h];
    const size_t slb = (size_t)bh * SLAB;
    #pragma unroll
    for (int i = 0; i < 2; i++) {
        int n = m0 + wr * 32 + i * 16 + gr;
        float fw0 = expf(fs * (float)(n - (N_ - 1)));
        float sw0 = expf(ss * (float)(n - (N_ - 1)));
        float fw1 = expf(fs * (float)(n + 8 - (N_ - 1)));
        float sw1 = expf(ss * (float)(n + 8 - (N_ - 1)));
        #pragma unroll
        for (int t = 0; t < 8; t++) {
            int col = wc * 64 + t * 8 + lane2;
            size_t p0 = slb + (size_t)n * 128 + col;
            size_t p8 = p0 + 8 * 128;
            float2 k0 = *(const float2*)(g_kf + p0);
            float2 k8 = *(const float2*)(g_kf + p8);
            float r, km0, km1;
            r = tanhf(acc[i][t][0]); km0 = k0.x * (1.f + 0.5f * r) * INV_SQRT_DK;
            r = tanhf(acc[i][t][1]); km1 = k0.y * (1.f + 0.5f * r) * INV_SQRT_DK;
            *(__half2*)(g_kf16 + p0) = __floats2half2_rn(km0 * fw0, km1 * fw0);
            *(__half2*)(g_ks16 + p0) = __floats2half2_rn(km0 * sw0, km1 * sw0);
            r = tanhf(acc[i][t][2]); km0 = k8.x * (1.f + 0.5f * r) * INV_SQRT_DK;
            r = tanhf(acc[i][t][3]); km1 = k8.y * (1.f + 0.5f * r) * INV_SQRT_DK;
            *(__half2*)(g_kf16 + p8) = __floats2half2_rn(km0 * fw1, km1 * fw1);
            *(__half2*)(g_ks16 + p8) = __floats2half2_rn(km0 * sw1, km1 * sw1);
        }
    }
}

// ======================= k_oblend fp16 1-pass: o = q @ Mb ===================
__global__ __launch_bounds__(256)
void k_oblend_f16() {
    __shared__ __align__(16) __half sm[2][RS_STG];
    const int bh = blockIdx.y;
    const int m0 = blockIdx.x * 128;
    const __half* __restrict__ qslab = g_q16 + (size_t)bh * SLAB;
    const __half* __restrict__ mb = g_mb16 + (size_t)bh * 16384;
    const uint32_t sbase = smem_u32(sm);
    const int tid = threadIdx.x;
    const int wid = tid >> 5, lane = tid & 31;
    const int wr = wid >> 1, wc = wid & 1;
    const int l15 = lane & 15;
    const int lhalf = (lane >> 4) * 8;

    float acc[2][8][4];
    #pragma unroll
    for (int i = 0; i < 2; i++)
        #pragma unroll
        for (int j = 0; j < 8; j++)
            #pragma unroll
            for (int k = 0; k < 4; k++) acc[i][j][k] = 0.f;

    int gA[4], gl_r[4], gl_q[4];
    #pragma unroll
    for (int i = 0; i < 4; i++) {
        int idx = i * 256 + tid;
        if (idx < 512) { gA[i] = 0; gl_r[i] = idx >> 2; gl_q[i] = idx & 3; }
        else { int l = idx - 512; gA[i] = 1; gl_r[i] = l >> 4; gl_q[i] = l & 15; }
    }

    auto issue = [&](int c, int st) {
        #pragma unroll
        for (int i = 0; i < 4; i++) {
            const __half* src;
            uint32_t soff;
            if (gA[i] == 0) {
                src = qslab + (size_t)(m0 + gl_r[i]) * 128 + c * 32 + gl_q[i] * 8;
                soff = (uint32_t)(gl_r[i] * 40 + gl_q[i] * 8);
            } else {
                src = mb + (size_t)(c * 32 + gl_r[i]) * 128 + gl_q[i] * 8;
                soff = (uint32_t)(5120 + gl_r[i] * 136 + gl_q[i] * 8);
            }
            CP_ASYNC16(sbase + (uint32_t)(st * RS_STG) * 2 + soff * 2, src);
        }
        CP_COMMIT();
    };

    const int rofs = (lane & 7) + ((lane >> 4) << 3);
    const int cofs = (lane & 8);

    issue(0, 0);
    for (int c = 0; c < 4; c++) {
        if (c < 3) { issue(c + 1, (c + 1) & 1); CP_WAIT(1); }
        else       { CP_WAIT(0); }
        __syncthreads();
        const uint32_t stg = sbase + (uint32_t)((c & 1) * RS_STG) * 2;

        #pragma unroll
        for (int s = 0; s < 2; s++) {
            const uint32_t kcol = (uint32_t)(s * 16 + lhalf) * 2;
            const int rowd = s * 16 + rofs;
            uint32_t af[2][4], bf[4][4];
            #pragma unroll
            for (int i = 0; i < 2; i++) {
                uint32_t ar = stg + (uint32_t)((wr * 32 + i * 16 + l15) * 40) * 2 + kcol;
                LDSM_X4(af[i], ar);
            }
            #pragma unroll
            for (int p = 0; p < 4; p++) {
                uint32_t bd = stg + (uint32_t)(5120 + rowd * 136 + wc * 64 + p * 16 + cofs) * 2;
                LDSM_X4_T(bf[p], bd);
            }
            #pragma unroll
            for (int i = 0; i < 2; i++)
                #pragma unroll
                for (int t = 0; t < 8; t++) {
                    const int p = t >> 1, sel = t & 1;
                    MMAF16(acc[i][t], af[i], bf[p][sel], bf[p][sel + 2]);
                }
        }
        __syncthreads();
    }

    const int gr = lane >> 2;
    const int lane2 = (lane & 3) * 2;
    const int b = bh >> 4, h = bh & 15;
    #pragma unroll
    for (int i = 0; i < 2; i++) {
        int n = m0 + wr * 32 + i * 16 + gr;
        #pragma unroll
        for (int t = 0; t < 8; t++) {
            int col = wc * 64 + t * 8 + lane2;
            size_t b0 = ((size_t)(b * 4096 + n) * 16 + h) * 128 + col;
            size_t b8 = ((size_t)(b * 4096 + n + 8) * 16 + h) * 128 + col;
            *(__half2*)(g_ob16 + b0) = __floats2half2_rn(acc[i][t][0], acc[i][t][1]);
            *(__half2*)(g_ob16 + b8) = __floats2half2_rn(acc[i][t][2], acc[i][t][3]);
        }
    }
}

// ======================= k_mpart fp16 1-pass ===============================
static constexpr int MP_STG = 2 * 32 * 136;

__global__ __launch_bounds__(256)
void k_mpart_f16() {
    __shared__ __align__(16) __half sm[2][MP_STG];
    const int split = blockIdx.x, bh = blockIdx.y, which = blockIdx.z;
    const __half* __restrict__ kslab = (which ? g_ks16 : g_kf16) + (size_t)bh * SLAB;
    const __half* __restrict__ vslab = g_v16 + (size_t)bh * SLAB;
    const uint32_t sbase = smem_u32(sm);
    const int tid = threadIdx.x;
    const int wid = tid >> 5, lane = tid & 31;
    const int wr = wid >> 1, wc = wid & 1;

    float acc[2][8][4];
    #pragma unroll
    for (int i = 0; i < 2; i++)
        #pragma unroll
        for (int j = 0; j < 8; j++)
            #pragma unroll
            for (int k = 0; k < 4; k++) acc[i][j][k] = 0.f;

    int gl_t[4], gl_r[4], gl_q[4];
    #pragma unroll
    for (int i = 0; i < 4; i++) {
        int idx = i * 256 + tid;
        gl_t[i] = idx >> 9;
        int rem = idx & 511;
        gl_r[i] = rem >> 4;
        gl_q[i] = rem & 15;
    }

    auto issue = [&](int c, int st) {
        #pragma unroll
        for (int i = 0; i < 4; i++) {
            const __half* src = (gl_t[i] ? vslab : kslab)
                + (size_t)(split * 512 + c * 32 + gl_r[i]) * 128 + gl_q[i] * 8;
            uint32_t dst = sbase +
                (uint32_t)(st * MP_STG + gl_t[i] * 4352 + gl_r[i] * 136 + gl_q[i] * 8) * 2;
            CP_ASYNC16(dst, src);
        }
        CP_COMMIT();
    };

    const int rofs = (lane & 7) + ((lane >> 4) << 3);
    const int cofs = (lane & 8);

    issue(0, 0);
    for (int c = 0; c < 16; c++) {
        if (c < 15) { issue(c + 1, (c + 1) & 1); CP_WAIT(1); }
        else        { CP_WAIT(0); }
        __syncthreads();
        const uint32_t stg = sbase + (uint32_t)((c & 1) * MP_STG) * 2;

        #pragma unroll
        for (int ks = 0; ks < 2; ks++) {
            const int rowk = ks * 16 + rofs;
            uint32_t af[2][4], bf[4][4];
            #pragma unroll
            for (int i = 0; i < 2; i++) {
                uint32_t ad = stg + (uint32_t)(rowk * 136 + wr * 32 + i * 16 + cofs) * 2;
                LDSM_X4_T(af[i], ad);
            }
            #pragma unroll
            for (int p = 0; p < 4; p++) {
                uint32_t bd = stg + (uint32_t)(4352 + rowk * 136 + wc * 64 + p * 16 + cofs) * 2;
                LDSM_X4_T(bf[p], bd);
            }
            #pragma unroll
            for (int i = 0; i < 2; i++)
                #pragma unroll
                for (int t = 0; t < 8; t++) {
                    const int p = t >> 1, sel = t & 1;
                    MMAF16(acc[i][t], af[i], bf[p][sel], bf[p][sel + 2]);
                }
        }
        __syncthreads();
    }

    const int gr = lane >> 2;
    const int lane2 = (lane & 3) * 2;
    float* dst0 = g_part + (((size_t)which * BH_ + bh) * 8 + split) * 16384;
    #pragma unroll
    for (int i = 0; i < 2; i++) {
        int m = wr * 32 + i * 16 + gr;
        #pragma unroll
        for (int t = 0; t < 8; t++) {
            int col = wc * 64 + t * 8 + lane2;
            float* dst = dst0 + m * 128 + col;
            *(float2*)dst = make_float2(acc[i][t][0], acc[i][t][1]);
            *(float2*)(dst + 8 * 128) = make_float2(acc[i][t][2], acc[i][t][3]);
        }
    }
}

// ======================= gating MLP =======================
__global__ void k_mlp1(const float* __restrict__ f1_w, const float* __restrict__ f1_b) {
    __shared__ float xm[2048];
    int b = blockIdx.x;
    for (int i = threadIdx.x; i < 2048; i += 256) xm[i] = g_mean[b * 2048 + i];
    __syncthreads();
    int j = blockIdx.y * 256 + threadIdx.x;
    float s = 0.f;
    for (int k = 0; k < 2048; k++)
        s = fmaf(xm[k], f1_w[(size_t)k * 1024 + j], s);
    s += f1_b[j];
    g_h1[b * 1024 + j] = s / (1.f + expf(-s));
}

__global__ void k_mlp2(const float* __restrict__ f2_w, const float* __restrict__ f2_b,
                       float* __restrict__ dout) {
    __shared__ float red[128];
    int bh = blockIdx.x;
    int b = bh >> 4, h = bh & 15;
    float s = 0.f;
    for (int k = threadIdx.x; k < 1024; k += 128)
        s = fmaf(g_h1[b * 1024 + k], f2_w[k * 16 + h], s);
    red[threadIdx.x] = s; __syncthreads();
    for (int off = 64; off > 0; off >>= 1) {
        if (threadIdx.x < off) red[threadIdx.x] += red[threadIdx.x + off];
        __syncthreads();
    }
    if (threadIdx.x == 0) {
        float z = red[0] + f2_b[h];
        dout[OUT_OFF_PSI + bh] = 1.f / (1.f + expf(-z));
    }
}

// ======================= M finalize =======================
__global__ void k_mfin(const float* __restrict__ Mf_prev, const float* __restrict__ Ms_prev,
                       const float* __restrict__ inter_fast, const float* __restrict__ inter_slow,
                       float* __restrict__ dout) {
    const int bh = blockIdx.x;
    const int which = blockIdx.y;
    const int h = bh & 15;
    const float inter = which ? inter_slow[h] : inter_fast[h];
    const float* prev = (which ? Ms_prev : Mf_prev) + (size_t)bh * 16384;
    const float* part = g_part + ((size_t)which * BH_ + bh) * 8 * 16384;
    float* dst = dout + (which ? OUT_OFF_MS : OUT_OFF_MF) + (size_t)bh * 16384;
    for (int e = threadIdx.x; e < 16384; e += 256) {
        float s = 0.f;
        #pragma unroll
        for (int sp = 0; sp < 8; sp++) s += part[(size_t)sp * 16384 + e];
        dst[e] = prev[e] * inter + s;
    }
}

// ======================= Mref = (I+S) @ M, blended -> fp16 ==================
__global__ __launch_bounds__(256, 2)
void k_mref(const float* __restrict__ S_fast, const float* __restrict__ S_slow,
            const float* __restrict__ dout, int which) {
    __shared__ float As[16][132];
    __shared__ float Bs[16][128];
    const int bh = blockIdx.x;
    const int h = bh & 15;
    const float* __restrict__ S = (which ? S_slow : S_fast) + (size_t)h * 16384;
    const float* __restrict__ M = dout + (which ? OUT_OFF_MS : OUT_OFF_MF) + (size_t)bh * 16384;
    const int tx = threadIdx.x, ty = threadIdx.y;
    const int tid = ty * 16 + tx;
    float acc[8][8];
    #pragma unroll
    for (int i = 0; i < 8; i++)
        #pragma unroll
        for (int j = 0; j < 8; j++) acc[i][j] = 0.f;

    const int arow = tid >> 2, acol = (tid & 3) * 4;
    const int brow = tid >> 5, bcol = (tid & 31) * 4;

    for (int kt = 0; kt < 128; kt += 16) {
        #pragma unroll
        for (int r = 0; r < 2; r++) {
            int row = arow + r * 64;
            float4 av = *(const float4*)&S[(size_t)row * 128 + kt + acol];
            As[acol + 0][row] = av.x + ((row == kt + acol + 0) ? 1.f : 0.f);
            As[acol + 1][row] = av.y + ((row == kt + acol + 1) ? 1.f : 0.f);
            As[acol + 2][row] = av.z + ((row == kt + acol + 2) ? 1.f : 0.f);
            As[acol + 3][row] = av.w + ((row == kt + acol + 3) ? 1.f : 0.f);
        }
        #pragma unroll
        for (int r = 0; r < 2; r++) {
            int row = brow + r * 8;
            *(float4*)&Bs[row][bcol] = *(const float4*)&M[(size_t)(kt + row) * 128 + bcol];
        }
        __syncthreads();
        #pragma unroll
        for (int kk = 0; kk < 16; kk++) {
            float a[8], bb[8];
            *(float4*)&a[0]  = *(const float4*)&As[kk][ty * 8];
            *(float4*)&a[4]  = *(const float4*)&As[kk][ty * 8 + 4];
            *(float4*)&bb[0] = *(const float4*)&Bs[kk][tx * 8];
            *(float4*)&bb[4] = *(const float4*)&Bs[kk][tx * 8 + 4];
            #pragma unroll
            for (int i = 0; i < 8; i++)
                #pragma unroll
                for (int j = 0; j < 8; j++)
                    acc[i][j] = fmaf(a[i], bb[j], acc[i][j]);
        }
        __syncthreads();
    }
    const float p = dout[OUT_OFF_PSI + bh];
    const float c0 = which ? p : (1.f - p);
    float* dst = g_mblend + (size_t)bh * 16384;
    __half* m16 = g_mb16 + (size_t)bh * 16384;
    #pragma unroll
    for (int i = 0; i < 8; i++)
        #pragma unroll
        for (int j = 0; j < 8; j += 2) {
            int idx = (ty * 8 + i) * 128 + tx * 8 + j;
            if (which == 0) {
                dst[idx]     = c0 * acc[i][j];
                dst[idx + 1] = c0 * acc[i][j + 1];
            } else {
                float v0 = dst[idx]     + c0 * acc[i][j];
                float v1 = dst[idx + 1] + c0 * acc[i][j + 1];
                *(__half2*)(m16 + idx) = __floats2half2_rn(v0, v1);
            }
        }
}

// ======================= launch =======================
extern "C" void kernel_launch(void* const* d_in, const int* in_sizes, int n_in,
                              void* d_out, int out_size) {
    (void)in_sizes; (void)n_in; (void)out_size;
    const float* x          = (const float*)d_in[0];
    const float* Mf_prev    = (const float*)d_in[1];
    const float* Ms_prev    = (const float*)d_in[2];
    const float* Wq         = (const float*)d_in[3];
    const float* Wk         = (const float*)d_in[4];
    const float* Wv         = (const float*)d_in[5];
    const float* Wo         = (const float*)d_in[6];
    const float* Wb         = (const float*)d_in[7];
    const float* fast_slope = (const float*)d_in[8];
    const float* slow_slope = (const float*)d_in[9];
    const float* inter_fast = (const float*)d_in[10];
    const float* inter_slow = (const float*)d_in[11];
    const float* S_fast     = (const float*)d_in[12];
    const float* S_slow     = (const float*)d_in[13];
    const float* f1_w       = (const float*)d_in[14];
    const float* f1_b       = (const float*)d_in[15];
    const float* f2_w       = (const float*)d_in[16];
    const float* f2_b       = (const float*)d_in[17];
    float* out = (float*)d_out;

    dim3 t16(16, 16);
    dim3 t328(32, 8);

    // launches ordered so the 6th is the QKV GEMM (ncu -s 5 -c 1 profiles it)
    k_cvtmean<<<256, 256>>>(x);
    k_wcvt_qkv<<<dim3(64, 192), t328>>>(Wq, Wk, Wv);
    k_meanred<<<32, 256>>>();
    k_mlp1<<<dim3(4, 4), 256>>>(f1_w, f1_b);
    k_wcvt_b<<<256, 256>>>(Wb);

    // QKV projection (fp16 single-pass)
    k_f16_gemm<<<dim3(48, 128), 256>>>(nullptr, 0);

    k_mlp2<<<64, 128>>>(f2_w, f2_b, out);
    k_wcvt_o<<<dim3(64, 64), t328>>>(Wo);

    // per-head path
    k_res_mma<<<dim3(32, 64), 256>>>(fast_slope, slow_slope);
    k_mpart_f16<<<dim3(8, 64, 2), 256>>>();
    k_mfin<<<dim3(64, 2), 256>>>(Mf_prev, Ms_prev, inter_fast, inter_slow, out);
    k_mref<<<64, t16>>>(S_fast, S_slow, out, 0);
    k_mref<<<64, t16>>>(S_fast, S_slow, out, 1);
    k_oblend_f16<<<dim3(32, 64), 256>>>();

    // output projection (fp16 single-pass)
    k_f16_gemm<<<dim3(16, 128), 256>>>(out, 1);
}

// round 14
// speedup vs baseline: 4.4127x; 1.0325x over previous
#include <cuda_runtime.h>
#include <cuda_bf16.h>
#include <cuda_fp16.h>
#include <cstdint>
#include <math.h>

static constexpr int B_   = 4;
static constexpr int N_   = 4096;
static constexpr int H_   = 16;
static constexpr int DK_  = 128;
static constexpr int DIM_ = 2048;
static constexpr int BH_  = B_ * H_;      // 64
static constexpr int MROWS_ = B_ * N_;    // 16384
static constexpr float INV_SQRT_DK = 0.08838834764831843f;
static constexpr size_t SLAB = (size_t)N_ * DK_;

static constexpr long long OUT_OFF_MF  = 33554432LL;
static constexpr long long OUT_OFF_MS  = 34603008LL;
static constexpr long long OUT_OFF_PSI = 35651584LL;

// ---------------- scratch (allocation-free: device globals) ----------------
__device__ float g_kf [(size_t)BH_ * SLAB];       // raw k fp32
__device__ float g_part[2LL * BH_ * 8 * DK_ * DK_];
__device__ float g_mblend[(size_t)BH_ * DK_ * DK_];
__device__ float g_meanpart[32 * B_ * DIM_];
__device__ float g_mean[B_ * DIM_];
__device__ float g_h1part[8 * B_ * 1024];
__device__ float g_h1[B_ * 1024];

// fp16 operands
__device__ __half g_x16 [(size_t)MROWS_ * DIM_];
__device__ __half g_wqkv16[(size_t)6144 * 2048];
__device__ __half g_wo16[(size_t)2048 * 2048];
__device__ __half g_ob16[(size_t)MROWS_ * DIM_];  // o_blend (b,n,h,v)

// per-head fp16 tensors [bh][n][d]
__device__ __half g_q16 [(size_t)BH_ * SLAB];
__device__ __half g_v16 [(size_t)BH_ * SLAB];
__device__ __half g_k16 [(size_t)BH_ * SLAB];
__device__ __half g_kf16[(size_t)BH_ * SLAB];
__device__ __half g_ks16[(size_t)BH_ * SLAB];
__device__ __half g_wb16[(size_t)H_ * DK_ * DK_];
__device__ __half g_mb16[(size_t)BH_ * DK_ * DK_];   // blended state fp16

// ===================== PTX helpers (base-target) ===========================
__device__ __forceinline__ uint32_t smem_u32(const void* p) {
    uint32_t a;
    asm("{ .reg .u64 t; cvta.to.shared.u64 t, %1; cvt.u32.u64 %0, t; }"
        : "=r"(a) : "l"(p));
    return a;
}

#define MMAF16(d, a, b0, b1) \
    asm volatile("mma.sync.aligned.m16n8k16.row.col.f32.f16.f16.f32 " \
        "{%0,%1,%2,%3}, {%4,%5,%6,%7}, {%8,%9}, {%0,%1,%2,%3};" \
        : "+f"((d)[0]), "+f"((d)[1]), "+f"((d)[2]), "+f"((d)[3]) \
        : "r"((a)[0]), "r"((a)[1]), "r"((a)[2]), "r"((a)[3]), "r"(b0), "r"(b1))

#define LDSM_X4(r, addr) \
    asm volatile("ldmatrix.sync.aligned.m8n8.x4.shared.b16 {%0,%1,%2,%3}, [%4];" \
        : "=r"((r)[0]), "=r"((r)[1]), "=r"((r)[2]), "=r"((r)[3]) : "r"(addr))
#define LDSM_X4_T(r, addr) \
    asm volatile("ldmatrix.sync.aligned.m8n8.x4.trans.shared.b16 {%0,%1,%2,%3}, [%4];" \
        : "=r"((r)[0]), "=r"((r)[1]), "=r"((r)[2]), "=r"((r)[3]) : "r"(addr))

#define CP_ASYNC16(dst, src) \
    asm volatile("cp.async.cg.shared.global [%0], [%1], 16;" \
        :: "r"(dst), "l"(src) : "memory")
#define CP_COMMIT() asm volatile("cp.async.commit_group;" ::: "memory")
#define CP_WAIT(n)  asm volatile("cp.async.wait_group %0;" :: "n"(n) : "memory")

// ======================= fused x convert + mean partial (32 splits) ========
__global__ void k_cvtmean(const float* __restrict__ x) {
    int gid = blockIdx.x * 256 + threadIdx.x;        // 262144 threads
    int sp = gid >> 13;                               // 0..31
    int r  = gid & 8191;
    int b = r >> 11, d = r & 2047;
    float s = 0.f;
    int nbeg = sp * 128;
    #pragma unroll 8
    for (int n = nbeg; n < nbeg + 128; n++) {
        size_t idx = (size_t)(b * N_ + n) * DIM_ + d;
        float v = x[idx];
        s += v;
        g_x16[idx] = __float2half_rn(v);
    }
    g_meanpart[gid] = s;
}

__global__ void k_meanred() {
    int r = blockIdx.x * 256 + threadIdx.x;
    float s = 0.f;
    #pragma unroll
    for (int sp = 0; sp < 32; sp++) s += g_meanpart[sp * 8192 + r];
    g_mean[r] = s * (1.f / 4096.f);
}

// ======================= weight prep =======================
__global__ void k_wcvt_qkv(const float* __restrict__ Wq, const float* __restrict__ Wk,
                           const float* __restrict__ Wv) {
    __shared__ float tile[32][33];
    int k0 = blockIdx.x * 32, n0 = blockIdx.y * 32;
    int which = n0 >> 11;
    const float* __restrict__ W = (which == 0) ? Wq : (which == 1 ? Wk : Wv);
    int nn0 = n0 & 2047;
    for (int r = threadIdx.y; r < 32; r += 8)
        tile[r][threadIdx.x] = W[(size_t)(k0 + r) * 2048 + nn0 + threadIdx.x];
    __syncthreads();
    for (int r = threadIdx.y; r < 32; r += 8)
        g_wqkv16[(size_t)(n0 + r) * 2048 + k0 + threadIdx.x] = __float2half_rn(tile[threadIdx.x][r]);
}

__global__ void k_wcvt_o(const float* __restrict__ Wo) {
    __shared__ float tile[32][33];
    int k0 = blockIdx.x * 32, n0 = blockIdx.y * 32;
    for (int r = threadIdx.y; r < 32; r += 8)
        tile[r][threadIdx.x] = Wo[(size_t)(k0 + r) * 2048 + n0 + threadIdx.x];
    __syncthreads();
    for (int r = threadIdx.y; r < 32; r += 8)
        g_wo16[(size_t)(n0 + r) * 2048 + k0 + threadIdx.x] = __float2half_rn(tile[threadIdx.x][r]);
}

__global__ void k_wcvt_b(const float* __restrict__ Wb) {
    int i = (blockIdx.x * 256 + threadIdx.x) * 4;
    float4 v = *(const float4*)(Wb + i);
    *(__half2*)(g_wb16 + i) = __floats2half2_rn(v.x, v.y);
    *(__half2*)(g_wb16 + i + 2) = __floats2half2_rn(v.z, v.w);
}

// ======================= fp16 single-pass main GEMM ========================
__global__ __launch_bounds__(256)
void k_f16_gemm(float* __restrict__ Cout, int mode) {
    __shared__ __align__(16) __half sm[2][2][128][40];
    const __half* __restrict__ A  = (mode == 0) ? g_x16  : g_ob16;
    const __half* __restrict__ Bm = (mode == 0) ? g_wqkv16 : g_wo16;

    const uint32_t sbase = smem_u32(sm);
    const int tid = threadIdx.x;
    const int wid = tid >> 5, lane = tid & 31;
    const int wr = wid >> 1, wc = wid & 1;
    const int j0 = blockIdx.x * 128;
    const int m0 = blockIdx.y * 128;
    const int l15 = lane & 15;
    const int lhalf = (lane >> 4) * 8;

    float acc[2][8][4];
    #pragma unroll
    for (int i = 0; i < 2; i++)
        #pragma unroll
        for (int j = 0; j < 8; j++)
            #pragma unroll
            for (int k = 0; k < 4; k++) acc[i][j][k] = 0.f;

    int gl_isB[4], gl_r[4], gl_q[4];
    #pragma unroll
    for (int i = 0; i < 4; i++) {
        int idx = i * 256 + tid;
        gl_isB[i] = idx >> 9;
        int rem = idx & 511;
        gl_r[i] = rem >> 2;
        gl_q[i] = rem & 3;
    }

    auto issue = [&](int c, int st) {
        #pragma unroll
        for (int i = 0; i < 4; i++) {
            const __half* src = (gl_isB[i] ? Bm + (size_t)(j0 + gl_r[i]) * 2048
                                           : A  + (size_t)(m0 + gl_r[i]) * 2048)
                                + c * 32 + gl_q[i] * 8;
            uint32_t dst = sbase +
                (uint32_t)(((st * 2 + gl_isB[i]) * 128 + gl_r[i]) * 40 + gl_q[i] * 8) * 2;
            CP_ASYNC16(dst, src);
        }
        CP_COMMIT();
    };

    issue(0, 0);
    for (int c = 0; c < 64; c++) {
        if (c < 63) { issue(c + 1, (c + 1) & 1); CP_WAIT(1); }
        else        { CP_WAIT(0); }
        __syncthreads();
        const uint32_t stg = sbase + (uint32_t)((c & 1) * 2 * 128 * 40) * 2;

        #pragma unroll
        for (int s = 0; s < 2; s++) {
            const uint32_t kcol = (uint32_t)(s * 16 + lhalf) * 2;
            uint32_t af[2][4], bf[4][4];
            #pragma unroll
            for (int i = 0; i < 2; i++) {
                uint32_t ar = stg + (uint32_t)((wr * 32 + i * 16 + l15) * 40) * 2 + kcol;
                LDSM_X4(af[i], ar);
            }
            #pragma unroll
            for (int p = 0; p < 4; p++) {
                uint32_t br = stg + (uint32_t)((128 + wc * 64 + p * 16 + l15) * 40) * 2 + kcol;
                LDSM_X4(bf[p], br);
            }
            #pragma unroll
            for (int i = 0; i < 2; i++)
                #pragma unroll
                for (int t = 0; t < 8; t++) {
                    const int p = t >> 1, sel = t & 1;
                    MMAF16(acc[i][t], af[i], bf[p][sel], bf[p][sel + 2]);
                }
        }
        __syncthreads();
    }

    const int gr = lane >> 2;
    const int lane2 = (lane & 3) * 2;
    if (mode == 0) {
        const int which = j0 >> 11;
        const int h = (j0 >> 7) & 15;
        const int b = m0 >> 12;
        const size_t slab = (size_t)(b * 16 + h) * SLAB;
        if (which == 1) {
            float* dst0 = g_kf + slab;
            __half* d16 = g_k16 + slab;
            #pragma unroll
            for (int i = 0; i < 2; i++) {
                int n = (m0 & 4095) + wr * 32 + i * 16 + gr;
                #pragma unroll
                for (int t = 0; t < 8; t++) {
                    int col = wc * 64 + t * 8 + lane2;
                    size_t o0 = (size_t)n * 128 + col;
                    *(float2*)(dst0 + o0) = make_float2(acc[i][t][0], acc[i][t][1]);
                    *(float2*)(dst0 + o0 + 8 * 128) = make_float2(acc[i][t][2], acc[i][t][3]);
                    *(__half2*)(d16 + o0) = __floats2half2_rn(acc[i][t][0], acc[i][t][1]);
                    *(__half2*)(d16 + o0 + 8 * 128) = __floats2half2_rn(acc[i][t][2], acc[i][t][3]);
                }
            }
        } else {
            __half* d16 = ((which == 0) ? g_q16 : g_v16) + slab;
            #pragma unroll
            for (int i = 0; i < 2; i++) {
                int n = (m0 & 4095) + wr * 32 + i * 16 + gr;
                #pragma unroll
                for (int t = 0; t < 8; t++) {
                    int col = wc * 64 + t * 8 + lane2;
                    size_t o0 = (size_t)n * 128 + col;
                    *(__half2*)(d16 + o0) = __floats2half2_rn(acc[i][t][0], acc[i][t][1]);
                    *(__half2*)(d16 + o0 + 8 * 128) = __floats2half2_rn(acc[i][t][2], acc[i][t][3]);
                }
            }
        }
    } else {
        #pragma unroll
        for (int i = 0; i < 2; i++) {
            int m = m0 + wr * 32 + i * 16 + gr;
            #pragma unroll
            for (int t = 0; t < 8; t++) {
                int col = j0 + wc * 64 + t * 8 + lane2;
                float* dst = Cout + (size_t)m * 2048 + col;
                *(float2*)dst = make_float2(acc[i][t][0], acc[i][t][1]);
                *(float2*)(dst + 8 * 2048) = make_float2(acc[i][t][2], acc[i][t][3]);
            }
        }
    }
}

// ======================= k_res via fp16 MMA ================================
static constexpr int RS_STG = 128 * 40 + 32 * 136;   // 9472 halves per stage

__global__ __launch_bounds__(256)
void k_res_mma(const float* __restrict__ fast_slope, const float* __restrict__ slow_slope) {
    __shared__ __align__(16) __half sm[2][RS_STG];
    const int bh = blockIdx.y;
    const int m0 = blockIdx.x * 128;
    const int h = bh & 15;
    const __half* __restrict__ kslab = g_k16 + (size_t)bh * SLAB;
    const __half* __restrict__ wb = g_wb16 + (size_t)h * 16384;
    const uint32_t sbase = smem_u32(sm);
    const int tid = threadIdx.x;
    const int wid = tid >> 5, lane = tid & 31;
    const int wr = wid >> 1, wc = wid & 1;
    const int l15 = lane & 15;
    const int lhalf = (lane >> 4) * 8;

    float acc[2][8][4];
    #pragma unroll
    for (int i = 0; i < 2; i++)
        #pragma unroll
        for (int j = 0; j < 8; j++)
            #pragma unroll
            for (int k = 0; k < 4; k++) acc[i][j][k] = 0.f;

    int gA[4], gl_r[4], gl_q[4];
    #pragma unroll
    for (int i = 0; i < 4; i++) {
        int idx = i * 256 + tid;
        if (idx < 512) { gA[i] = 0; gl_r[i] = idx >> 2; gl_q[i] = idx & 3; }
        else { int l = idx - 512; gA[i] = 1; gl_r[i] = l >> 4; gl_q[i] = l & 15; }
    }

    auto issue = [&](int c, int st) {
        #pragma unroll
        for (int i = 0; i < 4; i++) {
            const __half* src;
            uint32_t soff;
            if (gA[i] == 0) {
                src = kslab + (size_t)(m0 + gl_r[i]) * 128 + c * 32 + gl_q[i] * 8;
                soff = (uint32_t)(gl_r[i] * 40 + gl_q[i] * 8);
            } else {
                src = wb + (size_t)(c * 32 + gl_r[i]) * 128 + gl_q[i] * 8;
                soff = (uint32_t)(5120 + gl_r[i] * 136 + gl_q[i] * 8);
            }
            CP_ASYNC16(sbase + (uint32_t)(st * RS_STG) * 2 + soff * 2, src);
        }
        CP_COMMIT();
    };

    const int rofs = (lane & 7) + ((lane >> 4) << 3);
    const int cofs = (lane & 8);

    issue(0, 0);
    for (int c = 0; c < 4; c++) {
        if (c < 3) { issue(c + 1, (c + 1) & 1); CP_WAIT(1); }
        else       { CP_WAIT(0); }
        __syncthreads();
        const uint32_t stg = sbase + (uint32_t)((c & 1) * RS_STG) * 2;

        #pragma unroll
        for (int s = 0; s < 2; s++) {
            const uint32_t kcol = (uint32_t)(s * 16 + lhalf) * 2;
            const int rowd = s * 16 + rofs;
            uint32_t af[2][4], bf[4][4];
            #pragma unroll
            for (int i = 0; i < 2; i++) {
                uint32_t ar = stg + (uint32_t)((wr * 32 + i * 16 + l15) * 40) * 2 + kcol;
                LDSM_X4(af[i], ar);
            }
            #pragma unroll
            for (int p = 0; p < 4; p++) {
                uint32_t bd = stg + (uint32_t)(5120 + rowd * 136 + wc * 64 + p * 16 + cofs) * 2;
                LDSM_X4_T(bf[p], bd);
            }
            #pragma unroll
            for (int i = 0; i < 2; i++)
                #pragma unroll
                for (int t = 0; t < 8; t++) {
                    const int p = t >> 1, sel = t & 1;
                    MMAF16(acc[i][t], af[i], bf[p][sel], bf[p][sel + 2]);
                }
        }
        __syncthreads();
    }

    const int gr = lane >> 2;
    const int lane2 = (lane & 3) * 2;
    const float fs = fast_slope[h], ss = slow_slope[h];
    const size_t slb = (size_t)bh * SLAB;
    #pragma unroll
    for (int i = 0; i < 2; i++) {
        int n = m0 + wr * 32 + i * 16 + gr;
        float fw0 = expf(fs * (float)(n - (N_ - 1)));
        float sw0 = expf(ss * (float)(n - (N_ - 1)));
        float fw1 = expf(fs * (float)(n + 8 - (N_ - 1)));
        float sw1 = expf(ss * (float)(n + 8 - (N_ - 1)));
        #pragma unroll
        for (int t = 0; t < 8; t++) {
            int col = wc * 64 + t * 8 + lane2;
            size_t p0 = slb + (size_t)n * 128 + col;
            size_t p8 = p0 + 8 * 128;
            float2 k0 = *(const float2*)(g_kf + p0);
            float2 k8 = *(const float2*)(g_kf + p8);
            float r, km0, km1;
            r = tanhf(acc[i][t][0]); km0 = k0.x * (1.f + 0.5f * r) * INV_SQRT_DK;
            r = tanhf(acc[i][t][1]); km1 = k0.y * (1.f + 0.5f * r) * INV_SQRT_DK;
            *(__half2*)(g_kf16 + p0) = __floats2half2_rn(km0 * fw0, km1 * fw0);
            *(__half2*)(g_ks16 + p0) = __floats2half2_rn(km0 * sw0, km1 * sw0);
            r = tanhf(acc[i][t][2]); km0 = k8.x * (1.f + 0.5f * r) * INV_SQRT_DK;
            r = tanhf(acc[i][t][3]); km1 = k8.y * (1.f + 0.5f * r) * INV_SQRT_DK;
            *(__half2*)(g_kf16 + p8) = __floats2half2_rn(km0 * fw1, km1 * fw1);
            *(__half2*)(g_ks16 + p8) = __floats2half2_rn(km0 * sw1, km1 * sw1);
        }
    }
}

// ======================= k_oblend fp16 1-pass: o = q @ Mb ===================
__global__ __launch_bounds__(256)
void k_oblend_f16() {
    __shared__ __align__(16) __half sm[2][RS_STG];
    const int bh = blockIdx.y;
    const int m0 = blockIdx.x * 128;
    const __half* __restrict__ qslab = g_q16 + (size_t)bh * SLAB;
    const __half* __restrict__ mb = g_mb16 + (size_t)bh * 16384;
    const uint32_t sbase = smem_u32(sm);
    const int tid = threadIdx.x;
    const int wid = tid >> 5, lane = tid & 31;
    const int wr = wid >> 1, wc = wid & 1;
    const int l15 = lane & 15;
    const int lhalf = (lane >> 4) * 8;

    float acc[2][8][4];
    #pragma unroll
    for (int i = 0; i < 2; i++)
        #pragma unroll
        for (int j = 0; j < 8; j++)
            #pragma unroll
            for (int k = 0; k < 4; k++) acc[i][j][k] = 0.f;

    int gA[4], gl_r[4], gl_q[4];
    #pragma unroll
    for (int i = 0; i < 4; i++) {
        int idx = i * 256 + tid;
        if (idx < 512) { gA[i] = 0; gl_r[i] = idx >> 2; gl_q[i] = idx & 3; }
        else { int l = idx - 512; gA[i] = 1; gl_r[i] = l >> 4; gl_q[i] = l & 15; }
    }

    auto issue = [&](int c, int st) {
        #pragma unroll
        for (int i = 0; i < 4; i++) {
            const __half* src;
            uint32_t soff;
            if (gA[i] == 0) {
                src = qslab + (size_t)(m0 + gl_r[i]) * 128 + c * 32 + gl_q[i] * 8;
                soff = (uint32_t)(gl_r[i] * 40 + gl_q[i] * 8);
            } else {
                src = mb + (size_t)(c * 32 + gl_r[i]) * 128 + gl_q[i] * 8;
                soff = (uint32_t)(5120 + gl_r[i] * 136 + gl_q[i] * 8);
            }
            CP_ASYNC16(sbase + (uint32_t)(st * RS_STG) * 2 + soff * 2, src);
        }
        CP_COMMIT();
    };

    const int rofs = (lane & 7) + ((lane >> 4) << 3);
    const int cofs = (lane & 8);

    issue(0, 0);
    for (int c = 0; c < 4; c++) {
        if (c < 3) { issue(c + 1, (c + 1) & 1); CP_WAIT(1); }
        else       { CP_WAIT(0); }
        __syncthreads();
        const uint32_t stg = sbase + (uint32_t)((c & 1) * RS_STG) * 2;

        #pragma unroll
        for (int s = 0; s < 2; s++) {
            const uint32_t kcol = (uint32_t)(s * 16 + lhalf) * 2;
            const int rowd = s * 16 + rofs;
            uint32_t af[2][4], bf[4][4];
            #pragma unroll
            for (int i = 0; i < 2; i++) {
                uint32_t ar = stg + (uint32_t)((wr * 32 + i * 16 + l15) * 40) * 2 + kcol;
                LDSM_X4(af[i], ar);
            }
            #pragma unroll
            for (int p = 0; p < 4; p++) {
                uint32_t bd = stg + (uint32_t)(5120 + rowd * 136 + wc * 64 + p * 16 + cofs) * 2;
                LDSM_X4_T(bf[p], bd);
            }
            #pragma unroll
            for (int i = 0; i < 2; i++)
                #pragma unroll
                for (int t = 0; t < 8; t++) {
                    const int p = t >> 1, sel = t & 1;
                    MMAF16(acc[i][t], af[i], bf[p][sel], bf[p][sel + 2]);
                }
        }
        __syncthreads();
    }

    const int gr = lane >> 2;
    const int lane2 = (lane & 3) * 2;
    const int b = bh >> 4, h = bh & 15;
    #pragma unroll
    for (int i = 0; i < 2; i++) {
        int n = m0 + wr * 32 + i * 16 + gr;
        #pragma unroll
        for (int t = 0; t < 8; t++) {
            int col = wc * 64 + t * 8 + lane2;
            size_t b0 = ((size_t)(b * 4096 + n) * 16 + h) * 128 + col;
            size_t b8 = ((size_t)(b * 4096 + n + 8) * 16 + h) * 128 + col;
            *(__half2*)(g_ob16 + b0) = __floats2half2_rn(acc[i][t][0], acc[i][t][1]);
            *(__half2*)(g_ob16 + b8) = __floats2half2_rn(acc[i][t][2], acc[i][t][3]);
        }
    }
}

// ======================= k_mpart fp16 1-pass ===============================
static constexpr int MP_STG = 2 * 32 * 136;

__global__ __launch_bounds__(256)
void k_mpart_f16() {
    __shared__ __align__(16) __half sm[2][MP_STG];
    const int split = blockIdx.x, bh = blockIdx.y, which = blockIdx.z;
    const __half* __restrict__ kslab = (which ? g_ks16 : g_kf16) + (size_t)bh * SLAB;
    const __half* __restrict__ vslab = g_v16 + (size_t)bh * SLAB;
    const uint32_t sbase = smem_u32(sm);
    const int tid = threadIdx.x;
    const int wid = tid >> 5, lane = tid & 31;
    const int wr = wid >> 1, wc = wid & 1;

    float acc[2][8][4];
    #pragma unroll
    for (int i = 0; i < 2; i++)
        #pragma unroll
        for (int j = 0; j < 8; j++)
            #pragma unroll
            for (int k = 0; k < 4; k++) acc[i][j][k] = 0.f;

    int gl_t[4], gl_r[4], gl_q[4];
    #pragma unroll
    for (int i = 0; i < 4; i++) {
        int idx = i * 256 + tid;
        gl_t[i] = idx >> 9;
        int rem = idx & 511;
        gl_r[i] = rem >> 4;
        gl_q[i] = rem & 15;
    }

    auto issue = [&](int c, int st) {
        #pragma unroll
        for (int i = 0; i < 4; i++) {
            const __half* src = (gl_t[i] ? vslab : kslab)
                + (size_t)(split * 512 + c * 32 + gl_r[i]) * 128 + gl_q[i] * 8;
            uint32_t dst = sbase +
                (uint32_t)(st * MP_STG + gl_t[i] * 4352 + gl_r[i] * 136 + gl_q[i] * 8) * 2;
            CP_ASYNC16(dst, src);
        }
        CP_COMMIT();
    };

    const int rofs = (lane & 7) + ((lane >> 4) << 3);
    const int cofs = (lane & 8);

    issue(0, 0);
    for (int c = 0; c < 16; c++) {
        if (c < 15) { issue(c + 1, (c + 1) & 1); CP_WAIT(1); }
        else        { CP_WAIT(0); }
        __syncthreads();
        const uint32_t stg = sbase + (uint32_t)((c & 1) * MP_STG) * 2;

        #pragma unroll
        for (int ks = 0; ks < 2; ks++) {
            const int rowk = ks * 16 + rofs;
            uint32_t af[2][4], bf[4][4];
            #pragma unroll
            for (int i = 0; i < 2; i++) {
                uint32_t ad = stg + (uint32_t)(rowk * 136 + wr * 32 + i * 16 + cofs) * 2;
                LDSM_X4_T(af[i], ad);
            }
            #pragma unroll
            for (int p = 0; p < 4; p++) {
                uint32_t bd = stg + (uint32_t)(4352 + rowk * 136 + wc * 64 + p * 16 + cofs) * 2;
                LDSM_X4_T(bf[p], bd);
            }
            #pragma unroll
            for (int i = 0; i < 2; i++)
                #pragma unroll
                for (int t = 0; t < 8; t++) {
                    const int p = t >> 1, sel = t & 1;
                    MMAF16(acc[i][t], af[i], bf[p][sel], bf[p][sel + 2]);
                }
        }
        __syncthreads();
    }

    const int gr = lane >> 2;
    const int lane2 = (lane & 3) * 2;
    float* dst0 = g_part + (((size_t)which * BH_ + bh) * 8 + split) * 16384;
    #pragma unroll
    for (int i = 0; i < 2; i++) {
        int m = wr * 32 + i * 16 + gr;
        #pragma unroll
        for (int t = 0; t < 8; t++) {
            int col = wc * 64 + t * 8 + lane2;
            float* dst = dst0 + m * 128 + col;
            *(float2*)dst = make_float2(acc[i][t][0], acc[i][t][1]);
            *(float2*)(dst + 8 * 128) = make_float2(acc[i][t][2], acc[i][t][3]);
        }
    }
}

// ======================= gating MLP (split-K) =======================
__global__ void k_mlp1a(const float* __restrict__ f1_w) {
    __shared__ float xm4[4][256];
    const int jb = blockIdx.x;            // 0..3
    const int ks = blockIdx.y;            // 0..7
    const int k0 = ks * 256;
    const int j = jb * 256 + threadIdx.x;
    for (int i = threadIdx.x; i < 1024; i += 256) {
        int b = i >> 8, kk = i & 255;
        xm4[b][kk] = g_mean[b * 2048 + k0 + kk];
    }
    __syncthreads();
    float a0 = 0.f, a1 = 0.f, a2 = 0.f, a3 = 0.f;
    for (int kk = 0; kk < 256; kk++) {
        float w = f1_w[(size_t)(k0 + kk) * 1024 + j];
        a0 = fmaf(xm4[0][kk], w, a0);
        a1 = fmaf(xm4[1][kk], w, a1);
        a2 = fmaf(xm4[2][kk], w, a2);
        a3 = fmaf(xm4[3][kk], w, a3);
    }
    float* dst = g_h1part + ks * 4096;
    dst[0 * 1024 + j] = a0;
    dst[1 * 1024 + j] = a1;
    dst[2 * 1024 + j] = a2;
    dst[3 * 1024 + j] = a3;
}

__global__ void k_mlp1red(const float* __restrict__ f1_b) {
    int i = blockIdx.x * 256 + threadIdx.x;     // 0..4095
    int j = i & 1023;
    float s = 0.f;
    #pragma unroll
    for (int ks = 0; ks < 8; ks++) s += g_h1part[ks * 4096 + i];
    s += f1_b[j];
    g_h1[i] = s / (1.f + expf(-s));
}

__global__ void k_mlp2(const float* __restrict__ f2_w, const float* __restrict__ f2_b,
                       float* __restrict__ dout) {
    __shared__ float red[128];
    int bh = blockIdx.x;
    int b = bh >> 4, h = bh & 15;
    float s = 0.f;
    for (int k = threadIdx.x; k < 1024; k += 128)
        s = fmaf(g_h1[b * 1024 + k], f2_w[k * 16 + h], s);
    red[threadIdx.x] = s; __syncthreads();
    for (int off = 64; off > 0; off >>= 1) {
        if (threadIdx.x < off) red[threadIdx.x] += red[threadIdx.x + off];
        __syncthreads();
    }
    if (threadIdx.x == 0) {
        float z = red[0] + f2_b[h];
        dout[OUT_OFF_PSI + bh] = 1.f / (1.f + expf(-z));
    }
}

// ======================= M finalize =======================
__global__ void k_mfin(const float* __restrict__ Mf_prev, const float* __restrict__ Ms_prev,
                       const float* __restrict__ inter_fast, const float* __restrict__ inter_slow,
                       float* __restrict__ dout) {
    const int bh = blockIdx.x;
    const int which = blockIdx.y;
    const int h = bh & 15;
    const float inter = which ? inter_slow[h] : inter_fast[h];
    const float* prev = (which ? Ms_prev : Mf_prev) + (size_t)bh * 16384;
    const float* part = g_part + ((size_t)which * BH_ + bh) * 8 * 16384;
    float* dst = dout + (which ? OUT_OFF_MS : OUT_OFF_MF) + (size_t)bh * 16384;
    for (int e = threadIdx.x; e < 16384; e += 256) {
        float s = 0.f;
        #pragma unroll
        for (int sp = 0; sp < 8; sp++) s += part[(size_t)sp * 16384 + e];
        dst[e] = prev[e] * inter + s;
    }
}

// ======================= Mref = (I+S) @ M, blended -> fp16 ==================
__global__ __launch_bounds__(256, 2)
void k_mref(const float* __restrict__ S_fast, const float* __restrict__ S_slow,
            const float* __restrict__ dout, int which) {
    __shared__ float As[16][132];
    __shared__ float Bs[16][128];
    const int bh = blockIdx.x;
    const int h = bh & 15;
    const float* __restrict__ S = (which ? S_slow : S_fast) + (size_t)h * 16384;
    const float* __restrict__ M = dout + (which ? OUT_OFF_MS : OUT_OFF_MF) + (size_t)bh * 16384;
    const int tx = threadIdx.x, ty = threadIdx.y;
    const int tid = ty * 16 + tx;
    float acc[8][8];
    #pragma unroll
    for (int i = 0; i < 8; i++)
        #pragma unroll
        for (int j = 0; j < 8; j++) acc[i][j] = 0.f;

    const int arow = tid >> 2, acol = (tid & 3) * 4;
    const int brow = tid >> 5, bcol = (tid & 31) * 4;

    for (int kt = 0; kt < 128; kt += 16) {
        #pragma unroll
        for (int r = 0; r < 2; r++) {
            int row = arow + r * 64;
            float4 av = *(const float4*)&S[(size_t)row * 128 + kt + acol];
            As[acol + 0][row] = av.x + ((row == kt + acol + 0) ? 1.f : 0.f);
            As[acol + 1][row] = av.y + ((row == kt + acol + 1) ? 1.f : 0.f);
            As[acol + 2][row] = av.z + ((row == kt + acol + 2) ? 1.f : 0.f);
            As[acol + 3][row] = av.w + ((row == kt + acol + 3) ? 1.f : 0.f);
        }
        #pragma unroll
        for (int r = 0; r < 2; r++) {
            int row = brow + r * 8;
            *(float4*)&Bs[row][bcol] = *(const float4*)&M[(size_t)(kt + row) * 128 + bcol];
        }
        __syncthreads();
        #pragma unroll
        for (int kk = 0; kk < 16; kk++) {
            float a[8], bb[8];
            *(float4*)&a[0]  = *(const float4*)&As[kk][ty * 8];
            *(float4*)&a[4]  = *(const float4*)&As[kk][ty * 8 + 4];
            *(float4*)&bb[0] = *(const float4*)&Bs[kk][tx * 8];
            *(float4*)&bb[4] = *(const float4*)&Bs[kk][tx * 8 + 4];
            #pragma unroll
            for (int i = 0; i < 8; i++)
                #pragma unroll
                for (int j = 0; j < 8; j++)
                    acc[i][j] = fmaf(a[i], bb[j], acc[i][j]);
        }
        __syncthreads();
    }
    const float p = dout[OUT_OFF_PSI + bh];
    const float c0 = which ? p : (1.f - p);
    float* dst = g_mblend + (size_t)bh * 16384;
    __half* m16 = g_mb16 + (size_t)bh * 16384;
    #pragma unroll
    for (int i = 0; i < 8; i++)
        #pragma unroll
        for (int j = 0; j < 8; j += 2) {
            int idx = (ty * 8 + i) * 128 + tx * 8 + j;
            if (which == 0) {
                dst[idx]     = c0 * acc[i][j];
                dst[idx + 1] = c0 * acc[i][j + 1];
            } else {
                float v0 = dst[idx]     + c0 * acc[i][j];
                float v1 = dst[idx + 1] + c0 * acc[i][j + 1];
                *(__half2*)(m16 + idx) = __floats2half2_rn(v0, v1);
            }
        }
}

// ======================= launch =======================
extern "C" void kernel_launch(void* const* d_in, const int* in_sizes, int n_in,
                              void* d_out, int out_size) {
    (void)in_sizes; (void)n_in; (void)out_size;
    const float* x          = (const float*)d_in[0];
    const float* Mf_prev    = (const float*)d_in[1];
    const float* Ms_prev    = (const float*)d_in[2];
    const float* Wq         = (const float*)d_in[3];
    const float* Wk         = (const float*)d_in[4];
    const float* Wv         = (const float*)d_in[5];
    const float* Wo         = (const float*)d_in[6];
    const float* Wb         = (const float*)d_in[7];
    const float* fast_slope = (const float*)d_in[8];
    const float* slow_slope = (const float*)d_in[9];
    const float* inter_fast = (const float*)d_in[10];
    const float* inter_slow = (const float*)d_in[11];
    const float* S_fast     = (const float*)d_in[12];
    const float* S_slow     = (const float*)d_in[13];
    const float* f1_w       = (const float*)d_in[14];
    const float* f1_b       = (const float*)d_in[15];
    const float* f2_w       = (const float*)d_in[16];
    const float* f2_b       = (const float*)d_in[17];
    float* out = (float*)d_out;

    dim3 t16(16, 16);
    dim3 t328(32, 8);

    // launches ordered so the 6th is the QKV GEMM (ncu -s 5 -c 1 profiles it)
    k_cvtmean<<<1024, 256>>>(x);
    k_wcvt_qkv<<<dim3(64, 192), t328>>>(Wq, Wk, Wv);
    k_meanred<<<32, 256>>>();
    k_mlp1a<<<dim3(4, 8), 256>>>(f1_w);
    k_mlp1red<<<16, 256>>>(f1_b);

    // QKV projection (fp16 single-pass)
    k_f16_gemm<<<dim3(48, 128), 256>>>(nullptr, 0);

    k_mlp2<<<64, 128>>>(f2_w, f2_b, out);
    k_wcvt_o<<<dim3(64, 64), t328>>>(Wo);
    k_wcvt_b<<<256, 256>>>(Wb);

    // per-head path
    k_res_mma<<<dim3(32, 64), 256>>>(fast_slope, slow_slope);
    k_mpart_f16<<<dim3(8, 64, 2), 256>>>();
    k_mfin<<<dim3(64, 2), 256>>>(Mf_prev, Ms_prev, inter_fast, inter_slow, out);
    k_mref<<<64, t16>>>(S_fast, S_slow, out, 0);
    k_mref<<<64, t16>>>(S_fast, S_slow, out, 1);
    k_oblend_f16<<<dim3(32, 64), 256>>>();

    // output projection (fp16 single-pass)
    k_f16_gemm<<<dim3(16, 128), 256>>>(out, 1);
}

// round 15
// speedup vs baseline: 4.5304x; 1.0267x over previous
#include <cuda_runtime.h>
#include <cuda_bf16.h>
#include <cuda_fp16.h>
#include <cstdint>
#include <math.h>

static constexpr int B_   = 4;
static constexpr int N_   = 4096;
static constexpr int H_   = 16;
static constexpr int DK_  = 128;
static constexpr int DIM_ = 2048;
static constexpr int BH_  = B_ * H_;      // 64
static constexpr int MROWS_ = B_ * N_;    // 16384
static constexpr float INV_SQRT_DK = 0.08838834764831843f;
static constexpr size_t SLAB = (size_t)N_ * DK_;

static constexpr long long OUT_OFF_MF  = 33554432LL;
static constexpr long long OUT_OFF_MS  = 34603008LL;
static constexpr long long OUT_OFF_PSI = 35651584LL;

// ---------------- scratch (allocation-free: device globals) ----------------
__device__ float g_kf [(size_t)BH_ * SLAB];       // raw k fp32
__device__ float g_part[2LL * BH_ * 8 * DK_ * DK_];
__device__ float g_mblend[(size_t)BH_ * DK_ * DK_];
__device__ float g_meanpart[32 * B_ * DIM_];
__device__ float g_mean[B_ * DIM_];
__device__ float g_h1part[32 * B_ * 1024];
__device__ float g_h1[B_ * 1024];

// fp16 operands
__device__ __half g_x16 [(size_t)MROWS_ * DIM_];
__device__ __half g_wqkv16[(size_t)6144 * 2048];
__device__ __half g_wo16[(size_t)2048 * 2048];
__device__ __half g_ob16[(size_t)MROWS_ * DIM_];  // o_blend (b,n,h,v)

// per-head fp16 tensors [bh][n][d]
__device__ __half g_q16 [(size_t)BH_ * SLAB];
__device__ __half g_v16 [(size_t)BH_ * SLAB];
__device__ __half g_k16 [(size_t)BH_ * SLAB];
__device__ __half g_kf16[(size_t)BH_ * SLAB];
__device__ __half g_ks16[(size_t)BH_ * SLAB];
__device__ __half g_wb16[(size_t)H_ * DK_ * DK_];
__device__ __half g_mb16[(size_t)BH_ * DK_ * DK_];   // blended state fp16

// ===================== PTX helpers (base-target) ===========================
__device__ __forceinline__ uint32_t smem_u32(const void* p) {
    uint32_t a;
    asm("{ .reg .u64 t; cvta.to.shared.u64 t, %1; cvt.u32.u64 %0, t; }"
        : "=r"(a) : "l"(p));
    return a;
}

#define MMAF16(d, a, b0, b1) \
    asm volatile("mma.sync.aligned.m16n8k16.row.col.f32.f16.f16.f32 " \
        "{%0,%1,%2,%3}, {%4,%5,%6,%7}, {%8,%9}, {%0,%1,%2,%3};" \
        : "+f"((d)[0]), "+f"((d)[1]), "+f"((d)[2]), "+f"((d)[3]) \
        : "r"((a)[0]), "r"((a)[1]), "r"((a)[2]), "r"((a)[3]), "r"(b0), "r"(b1))

#define LDSM_X4(r, addr) \
    asm volatile("ldmatrix.sync.aligned.m8n8.x4.shared.b16 {%0,%1,%2,%3}, [%4];" \
        : "=r"((r)[0]), "=r"((r)[1]), "=r"((r)[2]), "=r"((r)[3]) : "r"(addr))
#define LDSM_X4_T(r, addr) \
    asm volatile("ldmatrix.sync.aligned.m8n8.x4.trans.shared.b16 {%0,%1,%2,%3}, [%4];" \
        : "=r"((r)[0]), "=r"((r)[1]), "=r"((r)[2]), "=r"((r)[3]) : "r"(addr))

#define CP_ASYNC16(dst, src) \
    asm volatile("cp.async.cg.shared.global [%0], [%1], 16;" \
        :: "r"(dst), "l"(src) : "memory")
#define CP_COMMIT() asm volatile("cp.async.commit_group;" ::: "memory")
#define CP_WAIT(n)  asm volatile("cp.async.wait_group %0;" :: "n"(n) : "memory")

// ======================= fused x convert + mean partial (32 splits) ========
__global__ void k_cvtmean(const float* __restrict__ x) {
    int gid = blockIdx.x * 256 + threadIdx.x;        // 262144 threads
    int sp = gid >> 13;                               // 0..31
    int r  = gid & 8191;
    int b = r >> 11, d = r & 2047;
    float s = 0.f;
    int nbeg = sp * 128;
    #pragma unroll 8
    for (int n = nbeg; n < nbeg + 128; n++) {
        size_t idx = (size_t)(b * N_ + n) * DIM_ + d;
        float v = x[idx];
        s += v;
        g_x16[idx] = __float2half_rn(v);
    }
    g_meanpart[gid] = s;
}

__global__ void k_meanred() {
    int r = blockIdx.x * 256 + threadIdx.x;
    float s = 0.f;
    #pragma unroll
    for (int sp = 0; sp < 32; sp++) s += g_meanpart[sp * 8192 + r];
    g_mean[r] = s * (1.f / 4096.f);
}

// ======================= weight prep =======================
__global__ void k_wcvt_qkv(const float* __restrict__ Wq, const float* __restrict__ Wk,
                           const float* __restrict__ Wv) {
    __shared__ float tile[32][33];
    int k0 = blockIdx.x * 32, n0 = blockIdx.y * 32;
    int which = n0 >> 11;
    const float* __restrict__ W = (which == 0) ? Wq : (which == 1 ? Wk : Wv);
    int nn0 = n0 & 2047;
    for (int r = threadIdx.y; r < 32; r += 8)
        tile[r][threadIdx.x] = W[(size_t)(k0 + r) * 2048 + nn0 + threadIdx.x];
    __syncthreads();
    for (int r = threadIdx.y; r < 32; r += 8)
        g_wqkv16[(size_t)(n0 + r) * 2048 + k0 + threadIdx.x] = __float2half_rn(tile[threadIdx.x][r]);
}

__global__ void k_wcvt_o(const float* __restrict__ Wo) {
    __shared__ float tile[32][33];
    int k0 = blockIdx.x * 32, n0 = blockIdx.y * 32;
    for (int r = threadIdx.y; r < 32; r += 8)
        tile[r][threadIdx.x] = Wo[(size_t)(k0 + r) * 2048 + n0 + threadIdx.x];
    __syncthreads();
    for (int r = threadIdx.y; r < 32; r += 8)
        g_wo16[(size_t)(n0 + r) * 2048 + k0 + threadIdx.x] = __float2half_rn(tile[threadIdx.x][r]);
}

__global__ void k_wcvt_b(const float* __restrict__ Wb) {
    int i = (blockIdx.x * 256 + threadIdx.x) * 4;
    float4 v = *(const float4*)(Wb + i);
    *(__half2*)(g_wb16 + i) = __floats2half2_rn(v.x, v.y);
    *(__half2*)(g_wb16 + i + 2) = __floats2half2_rn(v.z, v.w);
}

// ======================= fp16 single-pass main GEMM ========================
__global__ __launch_bounds__(256)
void k_f16_gemm(float* __restrict__ Cout, int mode) {
    __shared__ __align__(16) __half sm[2][2][128][40];
    const __half* __restrict__ A  = (mode == 0) ? g_x16  : g_ob16;
    const __half* __restrict__ Bm = (mode == 0) ? g_wqkv16 : g_wo16;

    const uint32_t sbase = smem_u32(sm);
    const int tid = threadIdx.x;
    const int wid = tid >> 5, lane = tid & 31;
    const int wr = wid >> 1, wc = wid & 1;
    const int j0 = blockIdx.x * 128;
    const int m0 = blockIdx.y * 128;
    const int l15 = lane & 15;
    const int lhalf = (lane >> 4) * 8;

    float acc[2][8][4];
    #pragma unroll
    for (int i = 0; i < 2; i++)
        #pragma unroll
        for (int j = 0; j < 8; j++)
            #pragma unroll
            for (int k = 0; k < 4; k++) acc[i][j][k] = 0.f;

    int gl_isB[4], gl_r[4], gl_q[4];
    #pragma unroll
    for (int i = 0; i < 4; i++) {
        int idx = i * 256 + tid;
        gl_isB[i] = idx >> 9;
        int rem = idx & 511;
        gl_r[i] = rem >> 2;
        gl_q[i] = rem & 3;
    }

    auto issue = [&](int c, int st) {
        #pragma unroll
        for (int i = 0; i < 4; i++) {
            const __half* src = (gl_isB[i] ? Bm + (size_t)(j0 + gl_r[i]) * 2048
                                           : A  + (size_t)(m0 + gl_r[i]) * 2048)
                                + c * 32 + gl_q[i] * 8;
            uint32_t dst = sbase +
                (uint32_t)(((st * 2 + gl_isB[i]) * 128 + gl_r[i]) * 40 + gl_q[i] * 8) * 2;
            CP_ASYNC16(dst, src);
        }
        CP_COMMIT();
    };

    issue(0, 0);
    for (int c = 0; c < 64; c++) {
        if (c < 63) { issue(c + 1, (c + 1) & 1); CP_WAIT(1); }
        else        { CP_WAIT(0); }
        __syncthreads();
        const uint32_t stg = sbase + (uint32_t)((c & 1) * 2 * 128 * 40) * 2;

        #pragma unroll
        for (int s = 0; s < 2; s++) {
            const uint32_t kcol = (uint32_t)(s * 16 + lhalf) * 2;
            uint32_t af[2][4], bf[4][4];
            #pragma unroll
            for (int i = 0; i < 2; i++) {
                uint32_t ar = stg + (uint32_t)((wr * 32 + i * 16 + l15) * 40) * 2 + kcol;
                LDSM_X4(af[i], ar);
            }
            #pragma unroll
            for (int p = 0; p < 4; p++) {
                uint32_t br = stg + (uint32_t)((128 + wc * 64 + p * 16 + l15) * 40) * 2 + kcol;
                LDSM_X4(bf[p], br);
            }
            #pragma unroll
            for (int i = 0; i < 2; i++)
                #pragma unroll
                for (int t = 0; t < 8; t++) {
                    const int p = t >> 1, sel = t & 1;
                    MMAF16(acc[i][t], af[i], bf[p][sel], bf[p][sel + 2]);
                }
        }
        __syncthreads();
    }

    const int gr = lane >> 2;
    const int lane2 = (lane & 3) * 2;
    if (mode == 0) {
        const int which = j0 >> 11;
        const int h = (j0 >> 7) & 15;
        const int b = m0 >> 12;
        const size_t slab = (size_t)(b * 16 + h) * SLAB;
        if (which == 1) {
            float* dst0 = g_kf + slab;
            __half* d16 = g_k16 + slab;
            #pragma unroll
            for (int i = 0; i < 2; i++) {
                int n = (m0 & 4095) + wr * 32 + i * 16 + gr;
                #pragma unroll
                for (int t = 0; t < 8; t++) {
                    int col = wc * 64 + t * 8 + lane2;
                    size_t o0 = (size_t)n * 128 + col;
                    *(float2*)(dst0 + o0) = make_float2(acc[i][t][0], acc[i][t][1]);
                    *(float2*)(dst0 + o0 + 8 * 128) = make_float2(acc[i][t][2], acc[i][t][3]);
                    *(__half2*)(d16 + o0) = __floats2half2_rn(acc[i][t][0], acc[i][t][1]);
                    *(__half2*)(d16 + o0 + 8 * 128) = __floats2half2_rn(acc[i][t][2], acc[i][t][3]);
                }
            }
        } else {
            __half* d16 = ((which == 0) ? g_q16 : g_v16) + slab;
            #pragma unroll
            for (int i = 0; i < 2; i++) {
                int n = (m0 & 4095) + wr * 32 + i * 16 + gr;
                #pragma unroll
                for (int t = 0; t < 8; t++) {
                    int col = wc * 64 + t * 8 + lane2;
                    size_t o0 = (size_t)n * 128 + col;
                    *(__half2*)(d16 + o0) = __floats2half2_rn(acc[i][t][0], acc[i][t][1]);
                    *(__half2*)(d16 + o0 + 8 * 128) = __floats2half2_rn(acc[i][t][2], acc[i][t][3]);
                }
            }
        }
    } else {
        #pragma unroll
        for (int i = 0; i < 2; i++) {
            int m = m0 + wr * 32 + i * 16 + gr;
            #pragma unroll
            for (int t = 0; t < 8; t++) {
                int col = j0 + wc * 64 + t * 8 + lane2;
                float* dst = Cout + (size_t)m * 2048 + col;
                *(float2*)dst = make_float2(acc[i][t][0], acc[i][t][1]);
                *(float2*)(dst + 8 * 2048) = make_float2(acc[i][t][2], acc[i][t][3]);
            }
        }
    }
}

// ======================= k_res via fp16 MMA ================================
static constexpr int RS_STG = 128 * 40 + 32 * 136;   // 9472 halves per stage

__global__ __launch_bounds__(256)
void k_res_mma(const float* __restrict__ fast_slope, const float* __restrict__ slow_slope) {
    __shared__ __align__(16) __half sm[2][RS_STG];
    const int bh = blockIdx.y;
    const int m0 = blockIdx.x * 128;
    const int h = bh & 15;
    const __half* __restrict__ kslab = g_k16 + (size_t)bh * SLAB;
    const __half* __restrict__ wb = g_wb16 + (size_t)h * 16384;
    const uint32_t sbase = smem_u32(sm);
    const int tid = threadIdx.x;
    const int wid = tid >> 5, lane = tid & 31;
    const int wr = wid >> 1, wc = wid & 1;
    const int l15 = lane & 15;
    const int lhalf = (lane >> 4) * 8;

    float acc[2][8][4];
    #pragma unroll
    for (int i = 0; i < 2; i++)
        #pragma unroll
        for (int j = 0; j < 8; j++)
            #pragma unroll
            for (int k = 0; k < 4; k++) acc[i][j][k] = 0.f;

    int gA[4], gl_r[4], gl_q[4];
    #pragma unroll
    for (int i = 0; i < 4; i++) {
        int idx = i * 256 + tid;
        if (idx < 512) { gA[i] = 0; gl_r[i] = idx >> 2; gl_q[i] = idx & 3; }
        else { int l = idx - 512; gA[i] = 1; gl_r[i] = l >> 4; gl_q[i] = l & 15; }
    }

    auto issue = [&](int c, int st) {
        #pragma unroll
        for (int i = 0; i < 4; i++) {
            const __half* src;
            uint32_t soff;
            if (gA[i] == 0) {
                src = kslab + (size_t)(m0 + gl_r[i]) * 128 + c * 32 + gl_q[i] * 8;
                soff = (uint32_t)(gl_r[i] * 40 + gl_q[i] * 8);
            } else {
                src = wb + (size_t)(c * 32 + gl_r[i]) * 128 + gl_q[i] * 8;
                soff = (uint32_t)(5120 + gl_r[i] * 136 + gl_q[i] * 8);
            }
            CP_ASYNC16(sbase + (uint32_t)(st * RS_STG) * 2 + soff * 2, src);
        }
        CP_COMMIT();
    };

    const int rofs = (lane & 7) + ((lane >> 4) << 3);
    const int cofs = (lane & 8);

    issue(0, 0);
    for (int c = 0; c < 4; c++) {
        if (c < 3) { issue(c + 1, (c + 1) & 1); CP_WAIT(1); }
        else       { CP_WAIT(0); }
        __syncthreads();
        const uint32_t stg = sbase + (uint32_t)((c & 1) * RS_STG) * 2;

        #pragma unroll
        for (int s = 0; s < 2; s++) {
            const uint32_t kcol = (uint32_t)(s * 16 + lhalf) * 2;
            const int rowd = s * 16 + rofs;
            uint32_t af[2][4], bf[4][4];
            #pragma unroll
            for (int i = 0; i < 2; i++) {
                uint32_t ar = stg + (uint32_t)((wr * 32 + i * 16 + l15) * 40) * 2 + kcol;
                LDSM_X4(af[i], ar);
            }
            #pragma unroll
            for (int p = 0; p < 4; p++) {
                uint32_t bd = stg + (uint32_t)(5120 + rowd * 136 + wc * 64 + p * 16 + cofs) * 2;
                LDSM_X4_T(bf[p], bd);
            }
            #pragma unroll
            for (int i = 0; i < 2; i++)
                #pragma unroll
                for (int t = 0; t < 8; t++) {
                    const int p = t >> 1, sel = t & 1;
                    MMAF16(acc[i][t], af[i], bf[p][sel], bf[p][sel + 2]);
                }
        }
        __syncthreads();
    }

    const int gr = lane >> 2;
    const int lane2 = (lane & 3) * 2;
    const float fs = fast_slope[h], ss = slow_slope[h];
    const size_t slb = (size_t)bh * SLAB;
    #pragma unroll
    for (int i = 0; i < 2; i++) {
        int n = m0 + wr * 32 + i * 16 + gr;
        float fw0 = expf(fs * (float)(n - (N_ - 1)));
        float sw0 = expf(ss * (float)(n - (N_ - 1)));
        float fw1 = expf(fs * (float)(n + 8 - (N_ - 1)));
        float sw1 = expf(ss * (float)(n + 8 - (N_ - 1)));
        #pragma unroll
        for (int t = 0; t < 8; t++) {
            int col = wc * 64 + t * 8 + lane2;
            size_t p0 = slb + (size_t)n * 128 + col;
            size_t p8 = p0 + 8 * 128;
            float2 k0 = *(const float2*)(g_kf + p0);
            float2 k8 = *(const float2*)(g_kf + p8);
            float r, km0, km1;
            r = tanhf(acc[i][t][0]); km0 = k0.x * (1.f + 0.5f * r) * INV_SQRT_DK;
            r = tanhf(acc[i][t][1]); km1 = k0.y * (1.f + 0.5f * r) * INV_SQRT_DK;
            *(__half2*)(g_kf16 + p0) = __floats2half2_rn(km0 * fw0, km1 * fw0);
            *(__half2*)(g_ks16 + p0) = __floats2half2_rn(km0 * sw0, km1 * sw0);
            r = tanhf(acc[i][t][2]); km0 = k8.x * (1.f + 0.5f * r) * INV_SQRT_DK;
            r = tanhf(acc[i][t][3]); km1 = k8.y * (1.f + 0.5f * r) * INV_SQRT_DK;
            *(__half2*)(g_kf16 + p8) = __floats2half2_rn(km0 * fw1, km1 * fw1);
            *(__half2*)(g_ks16 + p8) = __floats2half2_rn(km0 * sw1, km1 * sw1);
        }
    }
}

// ======================= k_oblend fp16 1-pass: o = q @ Mb ===================
__global__ __launch_bounds__(256)
void k_oblend_f16() {
    __shared__ __align__(16) __half sm[2][RS_STG];
    const int bh = blockIdx.y;
    const int m0 = blockIdx.x * 128;
    const __half* __restrict__ qslab = g_q16 + (size_t)bh * SLAB;
    const __half* __restrict__ mb = g_mb16 + (size_t)bh * 16384;
    const uint32_t sbase = smem_u32(sm);
    const int tid = threadIdx.x;
    const int wid = tid >> 5, lane = tid & 31;
    const int wr = wid >> 1, wc = wid & 1;
    const int l15 = lane & 15;
    const int lhalf = (lane >> 4) * 8;

    float acc[2][8][4];
    #pragma unroll
    for (int i = 0; i < 2; i++)
        #pragma unroll
        for (int j = 0; j < 8; j++)
            #pragma unroll
            for (int k = 0; k < 4; k++) acc[i][j][k] = 0.f;

    int gA[4], gl_r[4], gl_q[4];
    #pragma unroll
    for (int i = 0; i < 4; i++) {
        int idx = i * 256 + tid;
        if (idx < 512) { gA[i] = 0; gl_r[i] = idx >> 2; gl_q[i] = idx & 3; }
        else { int l = idx - 512; gA[i] = 1; gl_r[i] = l >> 4; gl_q[i] = l & 15; }
    }

    auto issue = [&](int c, int st) {
        #pragma unroll
        for (int i = 0; i < 4; i++) {
            const __half* src;
            uint32_t soff;
            if (gA[i] == 0) {
                src = qslab + (size_t)(m0 + gl_r[i]) * 128 + c * 32 + gl_q[i] * 8;
                soff = (uint32_t)(gl_r[i] * 40 + gl_q[i] * 8);
            } else {
                src = mb + (size_t)(c * 32 + gl_r[i]) * 128 + gl_q[i] * 8;
                soff = (uint32_t)(5120 + gl_r[i] * 136 + gl_q[i] * 8);
            }
            CP_ASYNC16(sbase + (uint32_t)(st * RS_STG) * 2 + soff * 2, src);
        }
        CP_COMMIT();
    };

    const int rofs = (lane & 7) + ((lane >> 4) << 3);
    const int cofs = (lane & 8);

    issue(0, 0);
    for (int c = 0; c < 4; c++) {
        if (c < 3) { issue(c + 1, (c + 1) & 1); CP_WAIT(1); }
        else       { CP_WAIT(0); }
        __syncthreads();
        const uint32_t stg = sbase + (uint32_t)((c & 1) * RS_STG) * 2;

        #pragma unroll
        for (int s = 0; s < 2; s++) {
            const uint32_t kcol = (uint32_t)(s * 16 + lhalf) * 2;
            const int rowd = s * 16 + rofs;
            uint32_t af[2][4], bf[4][4];
            #pragma unroll
            for (int i = 0; i < 2; i++) {
                uint32_t ar = stg + (uint32_t)((wr * 32 + i * 16 + l15) * 40) * 2 + kcol;
                LDSM_X4(af[i], ar);
            }
            #pragma unroll
            for (int p = 0; p < 4; p++) {
                uint32_t bd = stg + (uint32_t)(5120 + rowd * 136 + wc * 64 + p * 16 + cofs) * 2;
                LDSM_X4_T(bf[p], bd);
            }
            #pragma unroll
            for (int i = 0; i < 2; i++)
                #pragma unroll
                for (int t = 0; t < 8; t++) {
                    const int p = t >> 1, sel = t & 1;
                    MMAF16(acc[i][t], af[i], bf[p][sel], bf[p][sel + 2]);
                }
        }
        __syncthreads();
    }

    const int gr = lane >> 2;
    const int lane2 = (lane & 3) * 2;
    const int b = bh >> 4, h = bh & 15;
    #pragma unroll
    for (int i = 0; i < 2; i++) {
        int n = m0 + wr * 32 + i * 16 + gr;
        #pragma unroll
        for (int t = 0; t < 8; t++) {
            int col = wc * 64 + t * 8 + lane2;
            size_t b0 = ((size_t)(b * 4096 + n) * 16 + h) * 128 + col;
            size_t b8 = ((size_t)(b * 4096 + n + 8) * 16 + h) * 128 + col;
            *(__half2*)(g_ob16 + b0) = __floats2half2_rn(acc[i][t][0], acc[i][t][1]);
            *(__half2*)(g_ob16 + b8) = __floats2half2_rn(acc[i][t][2], acc[i][t][3]);
        }
    }
}

// ======================= k_mpart fp16 1-pass ===============================
static constexpr int MP_STG = 2 * 32 * 136;

__global__ __launch_bounds__(256)
void k_mpart_f16() {
    __shared__ __align__(16) __half sm[2][MP_STG];
    const int split = blockIdx.x, bh = blockIdx.y, which = blockIdx.z;
    const __half* __restrict__ kslab = (which ? g_ks16 : g_kf16) + (size_t)bh * SLAB;
    const __half* __restrict__ vslab = g_v16 + (size_t)bh * SLAB;
    const uint32_t sbase = smem_u32(sm);
    const int tid = threadIdx.x;
    const int wid = tid >> 5, lane = tid & 31;
    const int wr = wid >> 1, wc = wid & 1;

    float acc[2][8][4];
    #pragma unroll
    for (int i = 0; i < 2; i++)
        #pragma unroll
        for (int j = 0; j < 8; j++)
            #pragma unroll
            for (int k = 0; k < 4; k++) acc[i][j][k] = 0.f;

    int gl_t[4], gl_r[4], gl_q[4];
    #pragma unroll
    for (int i = 0; i < 4; i++) {
        int idx = i * 256 + tid;
        gl_t[i] = idx >> 9;
        int rem = idx & 511;
        gl_r[i] = rem >> 4;
        gl_q[i] = rem & 15;
    }

    auto issue = [&](int c, int st) {
        #pragma unroll
        for (int i = 0; i < 4; i++) {
            const __half* src = (gl_t[i] ? vslab : kslab)
                + (size_t)(split * 512 + c * 32 + gl_r[i]) * 128 + gl_q[i] * 8;
            uint32_t dst = sbase +
                (uint32_t)(st * MP_STG + gl_t[i] * 4352 + gl_r[i] * 136 + gl_q[i] * 8) * 2;
            CP_ASYNC16(dst, src);
        }
        CP_COMMIT();
    };

    const int rofs = (lane & 7) + ((lane >> 4) << 3);
    const int cofs = (lane & 8);

    issue(0, 0);
    for (int c = 0; c < 16; c++) {
        if (c < 15) { issue(c + 1, (c + 1) & 1); CP_WAIT(1); }
        else        { CP_WAIT(0); }
        __syncthreads();
        const uint32_t stg = sbase + (uint32_t)((c & 1) * MP_STG) * 2;

        #pragma unroll
        for (int ks = 0; ks < 2; ks++) {
            const int rowk = ks * 16 + rofs;
            uint32_t af[2][4], bf[4][4];
            #pragma unroll
            for (int i = 0; i < 2; i++) {
                uint32_t ad = stg + (uint32_t)(rowk * 136 + wr * 32 + i * 16 + cofs) * 2;
                LDSM_X4_T(af[i], ad);
            }
            #pragma unroll
            for (int p = 0; p < 4; p++) {
                uint32_t bd = stg + (uint32_t)(4352 + rowk * 136 + wc * 64 + p * 16 + cofs) * 2;
                LDSM_X4_T(bf[p], bd);
            }
            #pragma unroll
            for (int i = 0; i < 2; i++)
                #pragma unroll
                for (int t = 0; t < 8; t++) {
                    const int p = t >> 1, sel = t & 1;
                    MMAF16(acc[i][t], af[i], bf[p][sel], bf[p][sel + 2]);
                }
        }
        __syncthreads();
    }

    const int gr = lane >> 2;
    const int lane2 = (lane & 3) * 2;
    float* dst0 = g_part + (((size_t)which * BH_ + bh) * 8 + split) * 16384;
    #pragma unroll
    for (int i = 0; i < 2; i++) {
        int m = wr * 32 + i * 16 + gr;
        #pragma unroll
        for (int t = 0; t < 8; t++) {
            int col = wc * 64 + t * 8 + lane2;
            float* dst = dst0 + m * 128 + col;
            *(float2*)dst = make_float2(acc[i][t][0], acc[i][t][1]);
            *(float2*)(dst + 8 * 128) = make_float2(acc[i][t][2], acc[i][t][3]);
        }
    }
}

// ======================= gating MLP (split-K x32) =======================
__global__ void k_mlp1a(const float* __restrict__ f1_w) {
    __shared__ float xm4[4][64];
    const int jb = blockIdx.x;            // 0..3
    const int ks = blockIdx.y;            // 0..31
    const int k0 = ks * 64;
    const int j = jb * 256 + threadIdx.x;
    if (threadIdx.x < 256) {
        int b = threadIdx.x >> 6, kk = threadIdx.x & 63;
        xm4[b][kk] = g_mean[b * 2048 + k0 + kk];
    }
    __syncthreads();
    float a0 = 0.f, a1 = 0.f, a2 = 0.f, a3 = 0.f;
    #pragma unroll 8
    for (int kk = 0; kk < 64; kk++) {
        float w = f1_w[(size_t)(k0 + kk) * 1024 + j];
        a0 = fmaf(xm4[0][kk], w, a0);
        a1 = fmaf(xm4[1][kk], w, a1);
        a2 = fmaf(xm4[2][kk], w, a2);
        a3 = fmaf(xm4[3][kk], w, a3);
    }
    float* dst = g_h1part + ks * 4096;
    dst[0 * 1024 + j] = a0;
    dst[1 * 1024 + j] = a1;
    dst[2 * 1024 + j] = a2;
    dst[3 * 1024 + j] = a3;
}

__global__ void k_mlp1red(const float* __restrict__ f1_b) {
    int i = blockIdx.x * 256 + threadIdx.x;     // 0..4095
    int j = i & 1023;
    float s = 0.f;
    #pragma unroll
    for (int ks = 0; ks < 32; ks++) s += g_h1part[ks * 4096 + i];
    s += f1_b[j];
    g_h1[i] = s / (1.f + expf(-s));
}

__global__ void k_mlp2(const float* __restrict__ f2_w, const float* __restrict__ f2_b,
                       float* __restrict__ dout) {
    __shared__ float red[128];
    int bh = blockIdx.x;
    int b = bh >> 4, h = bh & 15;
    float s = 0.f;
    for (int k = threadIdx.x; k < 1024; k += 128)
        s = fmaf(g_h1[b * 1024 + k], f2_w[k * 16 + h], s);
    red[threadIdx.x] = s; __syncthreads();
    for (int off = 64; off > 0; off >>= 1) {
        if (threadIdx.x < off) red[threadIdx.x] += red[threadIdx.x + off];
        __syncthreads();
    }
    if (threadIdx.x == 0) {
        float z = red[0] + f2_b[h];
        dout[OUT_OFF_PSI + bh] = 1.f / (1.f + expf(-z));
    }
}

// ======================= M finalize =======================
__global__ void k_mfin(const float* __restrict__ Mf_prev, const float* __restrict__ Ms_prev,
                       const float* __restrict__ inter_fast, const float* __restrict__ inter_slow,
                       float* __restrict__ dout) {
    const int bh = blockIdx.x;
    const int which = blockIdx.y;
    const int h = bh & 15;
    const float inter = which ? inter_slow[h] : inter_fast[h];
    const float* prev = (which ? Ms_prev : Mf_prev) + (size_t)bh * 16384;
    const float* part = g_part + ((size_t)which * BH_ + bh) * 8 * 16384;
    float* dst = dout + (which ? OUT_OFF_MS : OUT_OFF_MF) + (size_t)bh * 16384;
    for (int e = threadIdx.x; e < 16384; e += 256) {
        float s = 0.f;
        #pragma unroll
        for (int sp = 0; sp < 8; sp++) s += part[(size_t)sp * 16384 + e];
        dst[e] = prev[e] * inter + s;
    }
}

// ======================= Mref = (I+S) @ M, blended -> fp16 ==================
__global__ __launch_bounds__(256, 2)
void k_mref(const float* __restrict__ S_fast, const float* __restrict__ S_slow,
            const float* __restrict__ dout, int which) {
    __shared__ float As[16][132];
    __shared__ float Bs[16][128];
    const int bh = blockIdx.x;
    const int h = bh & 15;
    const float* __restrict__ S = (which ? S_slow : S_fast) + (size_t)h * 16384;
    const float* __restrict__ M = dout + (which ? OUT_OFF_MS : OUT_OFF_MF) + (size_t)bh * 16384;
    const int tx = threadIdx.x, ty = threadIdx.y;
    const int tid = ty * 16 + tx;
    float acc[8][8];
    #pragma unroll
    for (int i = 0; i < 8; i++)
        #pragma unroll
        for (int j = 0; j < 8; j++) acc[i][j] = 0.f;

    const int arow = tid >> 2, acol = (tid & 3) * 4;
    const int brow = tid >> 5, bcol = (tid & 31) * 4;

    for (int kt = 0; kt < 128; kt += 16) {
        #pragma unroll
        for (int r = 0; r < 2; r++) {
            int row = arow + r * 64;
            float4 av = *(const float4*)&S[(size_t)row * 128 + kt + acol];
            As[acol + 0][row] = av.x + ((row == kt + acol + 0) ? 1.f : 0.f);
            As[acol + 1][row] = av.y + ((row == kt + acol + 1) ? 1.f : 0.f);
            As[acol + 2][row] = av.z + ((row == kt + acol + 2) ? 1.f : 0.f);
            As[acol + 3][row] = av.w + ((row == kt + acol + 3) ? 1.f : 0.f);
        }
        #pragma unroll
        for (int r = 0; r < 2; r++) {
            int row = brow + r * 8;
            *(float4*)&Bs[row][bcol] = *(const float4*)&M[(size_t)(kt + row) * 128 + bcol];
        }
        __syncthreads();
        #pragma unroll
        for (int kk = 0; kk < 16; kk++) {
            float a[8], bb[8];
            *(float4*)&a[0]  = *(const float4*)&As[kk][ty * 8];
            *(float4*)&a[4]  = *(const float4*)&As[kk][ty * 8 + 4];
            *(float4*)&bb[0] = *(const float4*)&Bs[kk][tx * 8];
            *(float4*)&bb[4] = *(const float4*)&Bs[kk][tx * 8 + 4];
            #pragma unroll
            for (int i = 0; i < 8; i++)
                #pragma unroll
                for (int j = 0; j < 8; j++)
                    acc[i][j] = fmaf(a[i], bb[j], acc[i][j]);
        }
        __syncthreads();
    }
    const float p = dout[OUT_OFF_PSI + bh];
    const float c0 = which ? p : (1.f - p);
    float* dst = g_mblend + (size_t)bh * 16384;
    __half* m16 = g_mb16 + (size_t)bh * 16384;
    #pragma unroll
    for (int i = 0; i < 8; i++)
        #pragma unroll
        for (int j = 0; j < 8; j += 2) {
            int idx = (ty * 8 + i) * 128 + tx * 8 + j;
            if (which == 0) {
                dst[idx]     = c0 * acc[i][j];
                dst[idx + 1] = c0 * acc[i][j + 1];
            } else {
                float v0 = dst[idx]     + c0 * acc[i][j];
                float v1 = dst[idx + 1] + c0 * acc[i][j + 1];
                *(__half2*)(m16 + idx) = __floats2half2_rn(v0, v1);
            }
        }
}

// ======================= launch =======================
extern "C" void kernel_launch(void* const* d_in, const int* in_sizes, int n_in,
                              void* d_out, int out_size) {
    (void)in_sizes; (void)n_in; (void)out_size;
    const float* x          = (const float*)d_in[0];
    const float* Mf_prev    = (const float*)d_in[1];
    const float* Ms_prev    = (const float*)d_in[2];
    const float* Wq         = (const float*)d_in[3];
    const float* Wk         = (const float*)d_in[4];
    const float* Wv         = (const float*)d_in[5];
    const float* Wo         = (const float*)d_in[6];
    const float* Wb         = (const float*)d_in[7];
    const float* fast_slope = (const float*)d_in[8];
    const float* slow_slope = (const float*)d_in[9];
    const float* inter_fast = (const float*)d_in[10];
    const float* inter_slow = (const float*)d_in[11];
    const float* S_fast     = (const float*)d_in[12];
    const float* S_slow     = (const float*)d_in[13];
    const float* f1_w       = (const float*)d_in[14];
    const float* f1_b       = (const float*)d_in[15];
    const float* f2_w       = (const float*)d_in[16];
    const float* f2_b       = (const float*)d_in[17];
    float* out = (float*)d_out;

    static cudaStream_t s1 = nullptr;
    static cudaEvent_t e_fork = nullptr, e_join = nullptr;
    if (!s1) {
        cudaStreamCreateWithFlags(&s1, cudaStreamNonBlocking);
        cudaEventCreateWithFlags(&e_fork, cudaEventDisableTiming);
        cudaEventCreateWithFlags(&e_join, cudaEventDisableTiming);
    }

    dim3 t16(16, 16);
    dim3 t328(32, 8);

    // main stream: x convert (+ mean partials), then QKV weights + GEMM
    k_cvtmean<<<1024, 256>>>(x);
    cudaEventRecord(e_fork, 0);

    // side stream: gating path + Wo/Wb converts, hidden under the QKV GEMM
    cudaStreamWaitEvent(s1, e_fork, 0);
    k_meanred<<<32, 256, 0, s1>>>();
    k_mlp1a<<<dim3(4, 32), 256, 0, s1>>>(f1_w);
    k_mlp1red<<<16, 256, 0, s1>>>(f1_b);
    k_mlp2<<<64, 128, 0, s1>>>(f2_w, f2_b, out);
    k_wcvt_o<<<dim3(64, 64), t328, 0, s1>>>(Wo);
    k_wcvt_b<<<256, 256, 0, s1>>>(Wb);
    cudaEventRecord(e_join, s1);

    // main stream continues
    k_wcvt_qkv<<<dim3(64, 192), t328>>>(Wq, Wk, Wv);
    k_f16_gemm<<<dim3(48, 128), 256>>>(nullptr, 0);      // QKV projection

    cudaStreamWaitEvent(0, e_join, 0);

    // per-head path (main stream)
    k_res_mma<<<dim3(32, 64), 256>>>(fast_slope, slow_slope);
    k_mpart_f16<<<dim3(8, 64, 2), 256>>>();
    k_mfin<<<dim3(64, 2), 256>>>(Mf_prev, Ms_prev, inter_fast, inter_slow, out);
    k_mref<<<64, t16>>>(S_fast, S_slow, out, 0);
    k_mref<<<64, t16>>>(S_fast, S_slow, out, 1);
    k_oblend_f16<<<dim3(32, 64), 256>>>();

    // output projection (fp16 single-pass)
    k_f16_gemm<<<dim3(16, 128), 256>>>(out, 1);
}

// round 16
// speedup vs baseline: 4.5621x; 1.0070x over previous
#include <cuda_runtime.h>
#include <cuda_bf16.h>
#include <cuda_fp16.h>
#include <cstdint>
#include <math.h>

static constexpr int B_   = 4;
static constexpr int N_   = 4096;
static constexpr int H_   = 16;
static constexpr int DK_  = 128;
static constexpr int DIM_ = 2048;
static constexpr int BH_  = B_ * H_;      // 64
static constexpr int MROWS_ = B_ * N_;    // 16384
static constexpr float INV_SQRT_DK = 0.08838834764831843f;
static constexpr size_t SLAB = (size_t)N_ * DK_;

static constexpr long long OUT_OFF_MF  = 33554432LL;
static constexpr long long OUT_OFF_MS  = 34603008LL;
static constexpr long long OUT_OFF_PSI = 35651584LL;

// ---------------- scratch (allocation-free: device globals) ----------------
__device__ float g_kf [(size_t)BH_ * SLAB];       // raw k fp32
__device__ float g_part[2LL * BH_ * 8 * DK_ * DK_];
__device__ float g_mblend[(size_t)BH_ * DK_ * DK_];   // (1-psi)*Mf_ref fp32
__device__ float g_mbs2 [(size_t)BH_ * DK_ * DK_];    // psi*Ms_ref fp32
__device__ float g_meanpart[32 * B_ * DIM_];
__device__ float g_mean[B_ * DIM_];
__device__ float g_h1part[32 * B_ * 1024];
__device__ float g_h1[B_ * 1024];

// fp16 operands
__device__ __half g_x16 [(size_t)MROWS_ * DIM_];
__device__ __half g_wqkv16[(size_t)6144 * 2048];
__device__ __half g_wo16[(size_t)2048 * 2048];
__device__ __half g_ob16[(size_t)MROWS_ * DIM_];  // o_blend (b,n,h,v)

// per-head fp16 tensors [bh][n][d]
__device__ __half g_q16 [(size_t)BH_ * SLAB];
__device__ __half g_v16 [(size_t)BH_ * SLAB];
__device__ __half g_k16 [(size_t)BH_ * SLAB];
__device__ __half g_kf16[(size_t)BH_ * SLAB];
__device__ __half g_ks16[(size_t)BH_ * SLAB];
__device__ __half g_wb16[(size_t)H_ * DK_ * DK_];
__device__ __half g_mb16[(size_t)BH_ * DK_ * DK_];   // blended state fp16

// ===================== PTX helpers (base-target) ===========================
__device__ __forceinline__ uint32_t smem_u32(const void* p) {
    uint32_t a;
    asm("{ .reg .u64 t; cvta.to.shared.u64 t, %1; cvt.u32.u64 %0, t; }"
        : "=r"(a) : "l"(p));
    return a;
}

#define MMAF16(d, a, b0, b1) \
    asm volatile("mma.sync.aligned.m16n8k16.row.col.f32.f16.f16.f32 " \
        "{%0,%1,%2,%3}, {%4,%5,%6,%7}, {%8,%9}, {%0,%1,%2,%3};" \
        : "+f"((d)[0]), "+f"((d)[1]), "+f"((d)[2]), "+f"((d)[3]) \
        : "r"((a)[0]), "r"((a)[1]), "r"((a)[2]), "r"((a)[3]), "r"(b0), "r"(b1))

#define LDSM_X4(r, addr) \
    asm volatile("ldmatrix.sync.aligned.m8n8.x4.shared.b16 {%0,%1,%2,%3}, [%4];" \
        : "=r"((r)[0]), "=r"((r)[1]), "=r"((r)[2]), "=r"((r)[3]) : "r"(addr))
#define LDSM_X4_T(r, addr) \
    asm volatile("ldmatrix.sync.aligned.m8n8.x4.trans.shared.b16 {%0,%1,%2,%3}, [%4];" \
        : "=r"((r)[0]), "=r"((r)[1]), "=r"((r)[2]), "=r"((r)[3]) : "r"(addr))

#define CP_ASYNC16(dst, src) \
    asm volatile("cp.async.cg.shared.global [%0], [%1], 16;" \
        :: "r"(dst), "l"(src) : "memory")
#define CP_COMMIT() asm volatile("cp.async.commit_group;" ::: "memory")
#define CP_WAIT(n)  asm volatile("cp.async.wait_group %0;" :: "n"(n) : "memory")

// ======================= fused x convert + mean partial (32 splits) ========
__global__ void k_cvtmean(const float* __restrict__ x) {
    int gid = blockIdx.x * 256 + threadIdx.x;        // 262144 threads
    int sp = gid >> 13;                               // 0..31
    int r  = gid & 8191;
    int b = r >> 11, d = r & 2047;
    float s = 0.f;
    int nbeg = sp * 128;
    #pragma unroll 8
    for (int n = nbeg; n < nbeg + 128; n++) {
        size_t idx = (size_t)(b * N_ + n) * DIM_ + d;
        float v = x[idx];
        s += v;
        g_x16[idx] = __float2half_rn(v);
    }
    g_meanpart[gid] = s;
}

__global__ void k_meanred() {
    int r = blockIdx.x * 256 + threadIdx.x;
    float s = 0.f;
    #pragma unroll
    for (int sp = 0; sp < 32; sp++) s += g_meanpart[sp * 8192 + r];
    g_mean[r] = s * (1.f / 4096.f);
}

// ======================= weight prep =======================
__global__ void k_wcvt_qkv(const float* __restrict__ Wq, const float* __restrict__ Wk,
                           const float* __restrict__ Wv) {
    __shared__ float tile[32][33];
    int k0 = blockIdx.x * 32, n0 = blockIdx.y * 32;
    int which = n0 >> 11;
    const float* __restrict__ W = (which == 0) ? Wq : (which == 1 ? Wk : Wv);
    int nn0 = n0 & 2047;
    for (int r = threadIdx.y; r < 32; r += 8)
        tile[r][threadIdx.x] = W[(size_t)(k0 + r) * 2048 + nn0 + threadIdx.x];
    __syncthreads();
    for (int r = threadIdx.y; r < 32; r += 8)
        g_wqkv16[(size_t)(n0 + r) * 2048 + k0 + threadIdx.x] = __float2half_rn(tile[threadIdx.x][r]);
}

__global__ void k_wcvt_o(const float* __restrict__ Wo) {
    __shared__ float tile[32][33];
    int k0 = blockIdx.x * 32, n0 = blockIdx.y * 32;
    for (int r = threadIdx.y; r < 32; r += 8)
        tile[r][threadIdx.x] = Wo[(size_t)(k0 + r) * 2048 + n0 + threadIdx.x];
    __syncthreads();
    for (int r = threadIdx.y; r < 32; r += 8)
        g_wo16[(size_t)(n0 + r) * 2048 + k0 + threadIdx.x] = __float2half_rn(tile[threadIdx.x][r]);
}

__global__ void k_wcvt_b(const float* __restrict__ Wb) {
    int i = (blockIdx.x * 256 + threadIdx.x) * 4;
    float4 v = *(const float4*)(Wb + i);
    *(__half2*)(g_wb16 + i) = __floats2half2_rn(v.x, v.y);
    *(__half2*)(g_wb16 + i + 2) = __floats2half2_rn(v.z, v.w);
}

// ======================= fp16 single-pass main GEMM ========================
__global__ __launch_bounds__(256)
void k_f16_gemm(float* __restrict__ Cout, int mode) {
    __shared__ __align__(16) __half sm[2][2][128][40];
    const __half* __restrict__ A  = (mode == 0) ? g_x16  : g_ob16;
    const __half* __restrict__ Bm = (mode == 0) ? g_wqkv16 : g_wo16;

    const uint32_t sbase = smem_u32(sm);
    const int tid = threadIdx.x;
    const int wid = tid >> 5, lane = tid & 31;
    const int wr = wid >> 1, wc = wid & 1;
    const int j0 = blockIdx.x * 128;
    const int m0 = blockIdx.y * 128;
    const int l15 = lane & 15;
    const int lhalf = (lane >> 4) * 8;

    float acc[2][8][4];
    #pragma unroll
    for (int i = 0; i < 2; i++)
        #pragma unroll
        for (int j = 0; j < 8; j++)
            #pragma unroll
            for (int k = 0; k < 4; k++) acc[i][j][k] = 0.f;

    int gl_isB[4], gl_r[4], gl_q[4];
    #pragma unroll
    for (int i = 0; i < 4; i++) {
        int idx = i * 256 + tid;
        gl_isB[i] = idx >> 9;
        int rem = idx & 511;
        gl_r[i] = rem >> 2;
        gl_q[i] = rem & 3;
    }

    auto issue = [&](int c, int st) {
        #pragma unroll
        for (int i = 0; i < 4; i++) {
            const __half* src = (gl_isB[i] ? Bm + (size_t)(j0 + gl_r[i]) * 2048
                                           : A  + (size_t)(m0 + gl_r[i]) * 2048)
                                + c * 32 + gl_q[i] * 8;
            uint32_t dst = sbase +
                (uint32_t)(((st * 2 + gl_isB[i]) * 128 + gl_r[i]) * 40 + gl_q[i] * 8) * 2;
            CP_ASYNC16(dst, src);
        }
        CP_COMMIT();
    };

    issue(0, 0);
    for (int c = 0; c < 64; c++) {
        if (c < 63) { issue(c + 1, (c + 1) & 1); CP_WAIT(1); }
        else        { CP_WAIT(0); }
        __syncthreads();
        const uint32_t stg = sbase + (uint32_t)((c & 1) * 2 * 128 * 40) * 2;

        #pragma unroll
        for (int s = 0; s < 2; s++) {
            const uint32_t kcol = (uint32_t)(s * 16 + lhalf) * 2;
            uint32_t af[2][4], bf[4][4];
            #pragma unroll
            for (int i = 0; i < 2; i++) {
                uint32_t ar = stg + (uint32_t)((wr * 32 + i * 16 + l15) * 40) * 2 + kcol;
                LDSM_X4(af[i], ar);
            }
            #pragma unroll
            for (int p = 0; p < 4; p++) {
                uint32_t br = stg + (uint32_t)((128 + wc * 64 + p * 16 + l15) * 40) * 2 + kcol;
                LDSM_X4(bf[p], br);
            }
            #pragma unroll
            for (int i = 0; i < 2; i++)
                #pragma unroll
                for (int t = 0; t < 8; t++) {
                    const int p = t >> 1, sel = t & 1;
                    MMAF16(acc[i][t], af[i], bf[p][sel], bf[p][sel + 2]);
                }
        }
        __syncthreads();
    }

    const int gr = lane >> 2;
    const int lane2 = (lane & 3) * 2;
    if (mode == 0) {
        const int which = j0 >> 11;
        const int h = (j0 >> 7) & 15;
        const int b = m0 >> 12;
        const size_t slab = (size_t)(b * 16 + h) * SLAB;
        if (which == 1) {
            float* dst0 = g_kf + slab;
            __half* d16 = g_k16 + slab;
            #pragma unroll
            for (int i = 0; i < 2; i++) {
                int n = (m0 & 4095) + wr * 32 + i * 16 + gr;
                #pragma unroll
                for (int t = 0; t < 8; t++) {
                    int col = wc * 64 + t * 8 + lane2;
                    size_t o0 = (size_t)n * 128 + col;
                    *(float2*)(dst0 + o0) = make_float2(acc[i][t][0], acc[i][t][1]);
                    *(float2*)(dst0 + o0 + 8 * 128) = make_float2(acc[i][t][2], acc[i][t][3]);
                    *(__half2*)(d16 + o0) = __floats2half2_rn(acc[i][t][0], acc[i][t][1]);
                    *(__half2*)(d16 + o0 + 8 * 128) = __floats2half2_rn(acc[i][t][2], acc[i][t][3]);
                }
            }
        } else {
            __half* d16 = ((which == 0) ? g_q16 : g_v16) + slab;
            #pragma unroll
            for (int i = 0; i < 2; i++) {
                int n = (m0 & 4095) + wr * 32 + i * 16 + gr;
                #pragma unroll
                for (int t = 0; t < 8; t++) {
                    int col = wc * 64 + t * 8 + lane2;
                    size_t o0 = (size_t)n * 128 + col;
                    *(__half2*)(d16 + o0) = __floats2half2_rn(acc[i][t][0], acc[i][t][1]);
                    *(__half2*)(d16 + o0 + 8 * 128) = __floats2half2_rn(acc[i][t][2], acc[i][t][3]);
                }
            }
        }
    } else {
        #pragma unroll
        for (int i = 0; i < 2; i++) {
            int m = m0 + wr * 32 + i * 16 + gr;
            #pragma unroll
            for (int t = 0; t < 8; t++) {
                int col = j0 + wc * 64 + t * 8 + lane2;
                float* dst = Cout + (size_t)m * 2048 + col;
                *(float2*)dst = make_float2(acc[i][t][0], acc[i][t][1]);
                *(float2*)(dst + 8 * 2048) = make_float2(acc[i][t][2], acc[i][t][3]);
            }
        }
    }
}

// ======================= k_res via fp16 MMA ================================
static constexpr int RS_STG = 128 * 40 + 32 * 136;   // 9472 halves per stage

__global__ __launch_bounds__(256)
void k_res_mma(const float* __restrict__ fast_slope, const float* __restrict__ slow_slope) {
    __shared__ __align__(16) __half sm[2][RS_STG];
    const int bh = blockIdx.y;
    const int m0 = blockIdx.x * 128;
    const int h = bh & 15;
    const __half* __restrict__ kslab = g_k16 + (size_t)bh * SLAB;
    const __half* __restrict__ wb = g_wb16 + (size_t)h * 16384;
    const uint32_t sbase = smem_u32(sm);
    const int tid = threadIdx.x;
    const int wid = tid >> 5, lane = tid & 31;
    const int wr = wid >> 1, wc = wid & 1;
    const int l15 = lane & 15;
    const int lhalf = (lane >> 4) * 8;

    float acc[2][8][4];
    #pragma unroll
    for (int i = 0; i < 2; i++)
        #pragma unroll
        for (int j = 0; j < 8; j++)
            #pragma unroll
            for (int k = 0; k < 4; k++) acc[i][j][k] = 0.f;

    int gA[4], gl_r[4], gl_q[4];
    #pragma unroll
    for (int i = 0; i < 4; i++) {
        int idx = i * 256 + tid;
        if (idx < 512) { gA[i] = 0; gl_r[i] = idx >> 2; gl_q[i] = idx & 3; }
        else { int l = idx - 512; gA[i] = 1; gl_r[i] = l >> 4; gl_q[i] = l & 15; }
    }

    auto issue = [&](int c, int st) {
        #pragma unroll
        for (int i = 0; i < 4; i++) {
            const __half* src;
            uint32_t soff;
            if (gA[i] == 0) {
                src = kslab + (size_t)(m0 + gl_r[i]) * 128 + c * 32 + gl_q[i] * 8;
                soff = (uint32_t)(gl_r[i] * 40 + gl_q[i] * 8);
            } else {
                src = wb + (size_t)(c * 32 + gl_r[i]) * 128 + gl_q[i] * 8;
                soff = (uint32_t)(5120 + gl_r[i] * 136 + gl_q[i] * 8);
            }
            CP_ASYNC16(sbase + (uint32_t)(st * RS_STG) * 2 + soff * 2, src);
        }
        CP_COMMIT();
    };

    const int rofs = (lane & 7) + ((lane >> 4) << 3);
    const int cofs = (lane & 8);

    issue(0, 0);
    for (int c = 0; c < 4; c++) {
        if (c < 3) { issue(c + 1, (c + 1) & 1); CP_WAIT(1); }
        else       { CP_WAIT(0); }
        __syncthreads();
        const uint32_t stg = sbase + (uint32_t)((c & 1) * RS_STG) * 2;

        #pragma unroll
        for (int s = 0; s < 2; s++) {
            const uint32_t kcol = (uint32_t)(s * 16 + lhalf) * 2;
            const int rowd = s * 16 + rofs;
            uint32_t af[2][4], bf[4][4];
            #pragma unroll
            for (int i = 0; i < 2; i++) {
                uint32_t ar = stg + (uint32_t)((wr * 32 + i * 16 + l15) * 40) * 2 + kcol;
                LDSM_X4(af[i], ar);
            }
            #pragma unroll
            for (int p = 0; p < 4; p++) {
                uint32_t bd = stg + (uint32_t)(5120 + rowd * 136 + wc * 64 + p * 16 + cofs) * 2;
                LDSM_X4_T(bf[p], bd);
            }
            #pragma unroll
            for (int i = 0; i < 2; i++)
                #pragma unroll
                for (int t = 0; t < 8; t++) {
                    const int p = t >> 1, sel = t & 1;
                    MMAF16(acc[i][t], af[i], bf[p][sel], bf[p][sel + 2]);
                }
        }
        __syncthreads();
    }

    const int gr = lane >> 2;
    const int lane2 = (lane & 3) * 2;
    const float fs = fast_slope[h], ss = slow_slope[h];
    const size_t slb = (size_t)bh * SLAB;
    #pragma unroll
    for (int i = 0; i < 2; i++) {
        int n = m0 + wr * 32 + i * 16 + gr;
        float fw0 = expf(fs * (float)(n - (N_ - 1)));
        float sw0 = expf(ss * (float)(n - (N_ - 1)));
        float fw1 = expf(fs * (float)(n + 8 - (N_ - 1)));
        float sw1 = expf(ss * (float)(n + 8 - (N_ - 1)));
        #pragma unroll
        for (int t = 0; t < 8; t++) {
            int col = wc * 64 + t * 8 + lane2;
            size_t p0 = slb + (size_t)n * 128 + col;
            size_t p8 = p0 + 8 * 128;
            float2 k0 = *(const float2*)(g_kf + p0);
            float2 k8 = *(const float2*)(g_kf + p8);
            float r, km0, km1;
            r = tanhf(acc[i][t][0]); km0 = k0.x * (1.f + 0.5f * r) * INV_SQRT_DK;
            r = tanhf(acc[i][t][1]); km1 = k0.y * (1.f + 0.5f * r) * INV_SQRT_DK;
            *(__half2*)(g_kf16 + p0) = __floats2half2_rn(km0 * fw0, km1 * fw0);
            *(__half2*)(g_ks16 + p0) = __floats2half2_rn(km0 * sw0, km1 * sw0);
            r = tanhf(acc[i][t][2]); km0 = k8.x * (1.f + 0.5f * r) * INV_SQRT_DK;
            r = tanhf(acc[i][t][3]); km1 = k8.y * (1.f + 0.5f * r) * INV_SQRT_DK;
            *(__half2*)(g_kf16 + p8) = __floats2half2_rn(km0 * fw1, km1 * fw1);
            *(__half2*)(g_ks16 + p8) = __floats2half2_rn(km0 * sw1, km1 * sw1);
        }
    }
}

// ======================= k_oblend fp16 1-pass: o = q @ Mb ===================
__global__ __launch_bounds__(256)
void k_oblend_f16() {
    __shared__ __align__(16) __half sm[2][RS_STG];
    const int bh = blockIdx.y;
    const int m0 = blockIdx.x * 128;
    const __half* __restrict__ qslab = g_q16 + (size_t)bh * SLAB;
    const __half* __restrict__ mb = g_mb16 + (size_t)bh * 16384;
    const uint32_t sbase = smem_u32(sm);
    const int tid = threadIdx.x;
    const int wid = tid >> 5, lane = tid & 31;
    const int wr = wid >> 1, wc = wid & 1;
    const int l15 = lane & 15;
    const int lhalf = (lane >> 4) * 8;

    float acc[2][8][4];
    #pragma unroll
    for (int i = 0; i < 2; i++)
        #pragma unroll
        for (int j = 0; j < 8; j++)
            #pragma unroll
            for (int k = 0; k < 4; k++) acc[i][j][k] = 0.f;

    int gA[4], gl_r[4], gl_q[4];
    #pragma unroll
    for (int i = 0; i < 4; i++) {
        int idx = i * 256 + tid;
        if (idx < 512) { gA[i] = 0; gl_r[i] = idx >> 2; gl_q[i] = idx & 3; }
        else { int l = idx - 512; gA[i] = 1; gl_r[i] = l >> 4; gl_q[i] = l & 15; }
    }

    auto issue = [&](int c, int st) {
        #pragma unroll
        for (int i = 0; i < 4; i++) {
            const __half* src;
            uint32_t soff;
            if (gA[i] == 0) {
                src = qslab + (size_t)(m0 + gl_r[i]) * 128 + c * 32 + gl_q[i] * 8;
                soff = (uint32_t)(gl_r[i] * 40 + gl_q[i] * 8);
            } else {
                src = mb + (size_t)(c * 32 + gl_r[i]) * 128 + gl_q[i] * 8;
                soff = (uint32_t)(5120 + gl_r[i] * 136 + gl_q[i] * 8);
            }
            CP_ASYNC16(sbase + (uint32_t)(st * RS_STG) * 2 + soff * 2, src);
        }
        CP_COMMIT();
    };

    const int rofs = (lane & 7) + ((lane >> 4) << 3);
    const int cofs = (lane & 8);

    issue(0, 0);
    for (int c = 0; c < 4; c++) {
        if (c < 3) { issue(c + 1, (c + 1) & 1); CP_WAIT(1); }
        else       { CP_WAIT(0); }
        __syncthreads();
        const uint32_t stg = sbase + (uint32_t)((c & 1) * RS_STG) * 2;

        #pragma unroll
        for (int s = 0; s < 2; s++) {
            const uint32_t kcol = (uint32_t)(s * 16 + lhalf) * 2;
            const int rowd = s * 16 + rofs;
            uint32_t af[2][4], bf[4][4];
            #pragma unroll
            for (int i = 0; i < 2; i++) {
                uint32_t ar = stg + (uint32_t)((wr * 32 + i * 16 + l15) * 40) * 2 + kcol;
                LDSM_X4(af[i], ar);
            }
            #pragma unroll
            for (int p = 0; p < 4; p++) {
                uint32_t bd = stg + (uint32_t)(5120 + rowd * 136 + wc * 64 + p * 16 + cofs) * 2;
                LDSM_X4_T(bf[p], bd);
            }
            #pragma unroll
            for (int i = 0; i < 2; i++)
                #pragma unroll
                for (int t = 0; t < 8; t++) {
                    const int p = t >> 1, sel = t & 1;
                    MMAF16(acc[i][t], af[i], bf[p][sel], bf[p][sel + 2]);
                }
        }
        __syncthreads();
    }

    const int gr = lane >> 2;
    const int lane2 = (lane & 3) * 2;
    const int b = bh >> 4, h = bh & 15;
    #pragma unroll
    for (int i = 0; i < 2; i++) {
        int n = m0 + wr * 32 + i * 16 + gr;
        #pragma unroll
        for (int t = 0; t < 8; t++) {
            int col = wc * 64 + t * 8 + lane2;
            size_t b0 = ((size_t)(b * 4096 + n) * 16 + h) * 128 + col;
            size_t b8 = ((size_t)(b * 4096 + n + 8) * 16 + h) * 128 + col;
            *(__half2*)(g_ob16 + b0) = __floats2half2_rn(acc[i][t][0], acc[i][t][1]);
            *(__half2*)(g_ob16 + b8) = __floats2half2_rn(acc[i][t][2], acc[i][t][3]);
        }
    }
}

// ======================= k_mpart fp16 1-pass ===============================
static constexpr int MP_STG = 2 * 32 * 136;

__global__ __launch_bounds__(256)
void k_mpart_f16() {
    __shared__ __align__(16) __half sm[2][MP_STG];
    const int split = blockIdx.x, bh = blockIdx.y, which = blockIdx.z;
    const __half* __restrict__ kslab = (which ? g_ks16 : g_kf16) + (size_t)bh * SLAB;
    const __half* __restrict__ vslab = g_v16 + (size_t)bh * SLAB;
    const uint32_t sbase = smem_u32(sm);
    const int tid = threadIdx.x;
    const int wid = tid >> 5, lane = tid & 31;
    const int wr = wid >> 1, wc = wid & 1;

    float acc[2][8][4];
    #pragma unroll
    for (int i = 0; i < 2; i++)
        #pragma unroll
        for (int j = 0; j < 8; j++)
            #pragma unroll
            for (int k = 0; k < 4; k++) acc[i][j][k] = 0.f;

    int gl_t[4], gl_r[4], gl_q[4];
    #pragma unroll
    for (int i = 0; i < 4; i++) {
        int idx = i * 256 + tid;
        gl_t[i] = idx >> 9;
        int rem = idx & 511;
        gl_r[i] = rem >> 4;
        gl_q[i] = rem & 15;
    }

    auto issue = [&](int c, int st) {
        #pragma unroll
        for (int i = 0; i < 4; i++) {
            const __half* src = (gl_t[i] ? vslab : kslab)
                + (size_t)(split * 512 + c * 32 + gl_r[i]) * 128 + gl_q[i] * 8;
            uint32_t dst = sbase +
                (uint32_t)(st * MP_STG + gl_t[i] * 4352 + gl_r[i] * 136 + gl_q[i] * 8) * 2;
            CP_ASYNC16(dst, src);
        }
        CP_COMMIT();
    };

    const int rofs = (lane & 7) + ((lane >> 4) << 3);
    const int cofs = (lane & 8);

    issue(0, 0);
    for (int c = 0; c < 16; c++) {
        if (c < 15) { issue(c + 1, (c + 1) & 1); CP_WAIT(1); }
        else        { CP_WAIT(0); }
        __syncthreads();
        const uint32_t stg = sbase + (uint32_t)((c & 1) * MP_STG) * 2;

        #pragma unroll
        for (int ks = 0; ks < 2; ks++) {
            const int rowk = ks * 16 + rofs;
            uint32_t af[2][4], bf[4][4];
            #pragma unroll
            for (int i = 0; i < 2; i++) {
                uint32_t ad = stg + (uint32_t)(rowk * 136 + wr * 32 + i * 16 + cofs) * 2;
                LDSM_X4_T(af[i], ad);
            }
            #pragma unroll
            for (int p = 0; p < 4; p++) {
                uint32_t bd = stg + (uint32_t)(4352 + rowk * 136 + wc * 64 + p * 16 + cofs) * 2;
                LDSM_X4_T(bf[p], bd);
            }
            #pragma unroll
            for (int i = 0; i < 2; i++)
                #pragma unroll
                for (int t = 0; t < 8; t++) {
                    const int p = t >> 1, sel = t & 1;
                    MMAF16(acc[i][t], af[i], bf[p][sel], bf[p][sel + 2]);
                }
        }
        __syncthreads();
    }

    const int gr = lane >> 2;
    const int lane2 = (lane & 3) * 2;
    float* dst0 = g_part + (((size_t)which * BH_ + bh) * 8 + split) * 16384;
    #pragma unroll
    for (int i = 0; i < 2; i++) {
        int m = wr * 32 + i * 16 + gr;
        #pragma unroll
        for (int t = 0; t < 8; t++) {
            int col = wc * 64 + t * 8 + lane2;
            float* dst = dst0 + m * 128 + col;
            *(float2*)dst = make_float2(acc[i][t][0], acc[i][t][1]);
            *(float2*)(dst + 8 * 128) = make_float2(acc[i][t][2], acc[i][t][3]);
        }
    }
}

// ======================= gating MLP (split-K x32) =======================
__global__ void k_mlp1a(const float* __restrict__ f1_w) {
    __shared__ float xm4[4][64];
    const int jb = blockIdx.x;            // 0..3
    const int ks = blockIdx.y;            // 0..31
    const int k0 = ks * 64;
    const int j = jb * 256 + threadIdx.x;
    if (threadIdx.x < 256) {
        int b = threadIdx.x >> 6, kk = threadIdx.x & 63;
        xm4[b][kk] = g_mean[b * 2048 + k0 + kk];
    }
    __syncthreads();
    float a0 = 0.f, a1 = 0.f, a2 = 0.f, a3 = 0.f;
    #pragma unroll 8
    for (int kk = 0; kk < 64; kk++) {
        float w = f1_w[(size_t)(k0 + kk) * 1024 + j];
        a0 = fmaf(xm4[0][kk], w, a0);
        a1 = fmaf(xm4[1][kk], w, a1);
        a2 = fmaf(xm4[2][kk], w, a2);
        a3 = fmaf(xm4[3][kk], w, a3);
    }
    float* dst = g_h1part + ks * 4096;
    dst[0 * 1024 + j] = a0;
    dst[1 * 1024 + j] = a1;
    dst[2 * 1024 + j] = a2;
    dst[3 * 1024 + j] = a3;
}

__global__ void k_mlp1red(const float* __restrict__ f1_b) {
    int i = blockIdx.x * 256 + threadIdx.x;     // 0..4095
    int j = i & 1023;
    float s = 0.f;
    #pragma unroll
    for (int ks = 0; ks < 32; ks++) s += g_h1part[ks * 4096 + i];
    s += f1_b[j];
    g_h1[i] = s / (1.f + expf(-s));
}

__global__ void k_mlp2(const float* __restrict__ f2_w, const float* __restrict__ f2_b,
                       float* __restrict__ dout) {
    __shared__ float red[128];
    int bh = blockIdx.x;
    int b = bh >> 4, h = bh & 15;
    float s = 0.f;
    for (int k = threadIdx.x; k < 1024; k += 128)
        s = fmaf(g_h1[b * 1024 + k], f2_w[k * 16 + h], s);
    red[threadIdx.x] = s; __syncthreads();
    for (int off = 64; off > 0; off >>= 1) {
        if (threadIdx.x < off) red[threadIdx.x] += red[threadIdx.x + off];
        __syncthreads();
    }
    if (threadIdx.x == 0) {
        float z = red[0] + f2_b[h];
        dout[OUT_OFF_PSI + bh] = 1.f / (1.f + expf(-z));
    }
}

// ========== fused M finalize + (I+S)@M + psi scale (per bh,which) ==========
// Phase 1: M = sum(partials) + inter*prev -> dout and smem.
// Phase 2: R = (I+S)@M from smem; write coeff*R to per-which fp32 buffer.
__global__ __launch_bounds__(256)
void k_mfinref(const float* __restrict__ Mf_prev, const float* __restrict__ Ms_prev,
               const float* __restrict__ inter_fast, const float* __restrict__ inter_slow,
               const float* __restrict__ S_fast, const float* __restrict__ S_slow,
               float* __restrict__ dout) {
    extern __shared__ float smemM[];              // 16384 floats
    __shared__ float As[16][132];
    const int bh = blockIdx.x;
    const int which = blockIdx.y;
    const int h = bh & 15;
    const int tx = threadIdx.x, ty = threadIdx.y;
    const int tid = ty * 16 + tx;

    // phase 1
    {
        const float inter = which ? inter_slow[h] : inter_fast[h];
        const float* prev = (which ? Ms_prev : Mf_prev) + (size_t)bh * 16384;
        const float* part = g_part + ((size_t)which * BH_ + bh) * 8 * 16384;
        float* dst = dout + (which ? OUT_OFF_MS : OUT_OFF_MF) + (size_t)bh * 16384;
        for (int e = tid; e < 16384; e += 256) {
            float s = 0.f;
            #pragma unroll
            for (int sp = 0; sp < 8; sp++) s += part[(size_t)sp * 16384 + e];
            s = prev[e] * inter + s;
            dst[e] = s;
            smemM[e] = s;
        }
    }
    __syncthreads();

    // phase 2: (I+S) @ M with M in smem
    const float* __restrict__ S = (which ? S_slow : S_fast) + (size_t)h * 16384;
    float acc[8][8];
    #pragma unroll
    for (int i = 0; i < 8; i++)
        #pragma unroll
        for (int j = 0; j < 8; j++) acc[i][j] = 0.f;

    const int arow = tid >> 2, acol = (tid & 3) * 4;

    for (int kt = 0; kt < 128; kt += 16) {
        #pragma unroll
        for (int r = 0; r < 2; r++) {
            int row = arow + r * 64;
            float4 av = *(const float4*)&S[(size_t)row * 128 + kt + acol];
            As[acol + 0][row] = av.x + ((row == kt + acol + 0) ? 1.f : 0.f);
            As[acol + 1][row] = av.y + ((row == kt + acol + 1) ? 1.f : 0.f);
            As[acol + 2][row] = av.z + ((row == kt + acol + 2) ? 1.f : 0.f);
            As[acol + 3][row] = av.w + ((row == kt + acol + 3) ? 1.f : 0.f);
        }
        __syncthreads();
        #pragma unroll
        for (int kk = 0; kk < 16; kk++) {
            float a[8], bb[8];
            *(float4*)&a[0]  = *(const float4*)&As[kk][ty * 8];
            *(float4*)&a[4]  = *(const float4*)&As[kk][ty * 8 + 4];
            *(float4*)&bb[0] = *(const float4*)&smemM[(kt + kk) * 128 + tx * 8];
            *(float4*)&bb[4] = *(const float4*)&smemM[(kt + kk) * 128 + tx * 8 + 4];
            #pragma unroll
            for (int i = 0; i < 8; i++)
                #pragma unroll
                for (int j = 0; j < 8; j++)
                    acc[i][j] = fmaf(a[i], bb[j], acc[i][j]);
        }
        __syncthreads();
    }

    const float p = dout[OUT_OFF_PSI + bh];
    const float c0 = which ? p : (1.f - p);
    float* mdst = (which ? g_mbs2 : g_mblend) + (size_t)bh * 16384;
    #pragma unroll
    for (int i = 0; i < 8; i++)
        #pragma unroll
        for (int j = 0; j < 8; j += 2) {
            int idx = (ty * 8 + i) * 128 + tx * 8 + j;
            *(float2*)(mdst + idx) = make_float2(c0 * acc[i][j], c0 * acc[i][j + 1]);
        }
}

// sum the two psi-scaled halves -> fp16 Mb
__global__ void k_mbadd() {
    size_t i = ((size_t)blockIdx.x * 256 + threadIdx.x) * 2;
    float2 a = *(const float2*)(g_mblend + i);
    float2 b = *(const float2*)(g_mbs2 + i);
    *(__half2*)(g_mb16 + i) = __floats2half2_rn(a.x + b.x, a.y + b.y);
}

// ======================= launch =======================
extern "C" void kernel_launch(void* const* d_in, const int* in_sizes, int n_in,
                              void* d_out, int out_size) {
    (void)in_sizes; (void)n_in; (void)out_size;
    const float* x          = (const float*)d_in[0];
    const float* Mf_prev    = (const float*)d_in[1];
    const float* Ms_prev    = (const float*)d_in[2];
    const float* Wq         = (const float*)d_in[3];
    const float* Wk         = (const float*)d_in[4];
    const float* Wv         = (const float*)d_in[5];
    const float* Wo         = (const float*)d_in[6];
    const float* Wb         = (const float*)d_in[7];
    const float* fast_slope = (const float*)d_in[8];
    const float* slow_slope = (const float*)d_in[9];
    const float* inter_fast = (const float*)d_in[10];
    const float* inter_slow = (const float*)d_in[11];
    const float* S_fast     = (const float*)d_in[12];
    const float* S_slow     = (const float*)d_in[13];
    const float* f1_w       = (const float*)d_in[14];
    const float* f1_b       = (const float*)d_in[15];
    const float* f2_w       = (const float*)d_in[16];
    const float* f2_b       = (const float*)d_in[17];
    float* out = (float*)d_out;

    static cudaStream_t s1 = nullptr;
    static cudaEvent_t e_fork0 = nullptr, e_fork = nullptr, e_wq = nullptr, e_join = nullptr;
    if (!s1) {
        cudaStreamCreateWithFlags(&s1, cudaStreamNonBlocking);
        cudaEventCreateWithFlags(&e_fork0, cudaEventDisableTiming);
        cudaEventCreateWithFlags(&e_fork, cudaEventDisableTiming);
        cudaEventCreateWithFlags(&e_wq, cudaEventDisableTiming);
        cudaEventCreateWithFlags(&e_join, cudaEventDisableTiming);
        cudaFuncSetAttribute(k_mfinref, cudaFuncAttributeMaxDynamicSharedMemorySize, 65536);
    }

    dim3 t16(16, 16);
    dim3 t328(32, 8);

    // main: fork immediately so s1 can start the QKV weight convert now
    cudaEventRecord(e_fork0, 0);
    cudaStreamWaitEvent(s1, e_fork0, 0);
    k_wcvt_qkv<<<dim3(64, 192), t328, 0, s1>>>(Wq, Wk, Wv);
    cudaEventRecord(e_wq, s1);

    // main: x convert + mean partials (concurrent with wcvt_qkv)
    k_cvtmean<<<1024, 256>>>(x);
    cudaEventRecord(e_fork, 0);

    // side stream: gating path + Wo/Wb converts, hidden under the QKV GEMM
    cudaStreamWaitEvent(s1, e_fork, 0);
    k_meanred<<<32, 256, 0, s1>>>();
    k_mlp1a<<<dim3(4, 32), 256, 0, s1>>>(f1_w);
    k_mlp1red<<<16, 256, 0, s1>>>(f1_b);
    k_mlp2<<<64, 128, 0, s1>>>(f2_w, f2_b, out);
    k_wcvt_o<<<dim3(64, 64), t328, 0, s1>>>(Wo);
    k_wcvt_b<<<256, 256, 0, s1>>>(Wb);
    cudaEventRecord(e_join, s1);

    // main stream: QKV GEMM (after its weights are ready)
    cudaStreamWaitEvent(0, e_wq, 0);
    k_f16_gemm<<<dim3(48, 128), 256>>>(nullptr, 0);

    cudaStreamWaitEvent(0, e_join, 0);

    // per-head path (main stream)
    k_res_mma<<<dim3(32, 64), 256>>>(fast_slope, slow_slope);
    k_mpart_f16<<<dim3(8, 64, 2), 256>>>();
    k_mfinref<<<dim3(64, 2), t16, 65536>>>(Mf_prev, Ms_prev, inter_fast, inter_slow,
                                           S_fast, S_slow, out);
    k_mbadd<<<2048, 256>>>();
    k_oblend_f16<<<dim3(32, 64), 256>>>();

    // output projection (fp16 single-pass)
    k_f16_gemm<<<dim3(16, 128), 256>>>(out, 1);
}

// round 17
// speedup vs baseline: 4.6365x; 1.0163x over previous
#include <cuda_runtime.h>
#include <cuda_bf16.h>
#include <cuda_fp16.h>
#include <cstdint>
#include <math.h>

static constexpr int B_   = 4;
static constexpr int N_   = 4096;
static constexpr int H_   = 16;
static constexpr int DK_  = 128;
static constexpr int DIM_ = 2048;
static constexpr int BH_  = B_ * H_;      // 64
static constexpr int MROWS_ = B_ * N_;    // 16384
static constexpr float INV_SQRT_DK = 0.08838834764831843f;
static constexpr size_t SLAB = (size_t)N_ * DK_;

static constexpr long long OUT_OFF_MF  = 33554432LL;
static constexpr long long OUT_OFF_MS  = 34603008LL;
static constexpr long long OUT_OFF_PSI = 35651584LL;

// ---------------- scratch (allocation-free: device globals) ----------------
__device__ float g_part[2LL * BH_ * 8 * DK_ * DK_];
__device__ float g_mblend[(size_t)BH_ * DK_ * DK_];   // (1-psi)*Mf_ref fp32
__device__ float g_mbs2 [(size_t)BH_ * DK_ * DK_];    // psi*Ms_ref fp32
__device__ float g_meanpart[32 * B_ * DIM_];
__device__ float g_mean[B_ * DIM_];
__device__ float g_h1part[32 * B_ * 1024];
__device__ float g_h1[B_ * 1024];

// fp16 operands
__device__ __half g_x16 [(size_t)MROWS_ * DIM_];
__device__ __half g_wqkv16[(size_t)6144 * 2048];
__device__ __half g_wo16[(size_t)2048 * 2048];
__device__ __half g_ob16[(size_t)MROWS_ * DIM_];  // o_blend (b,n,h,v)

// per-head fp16 tensors [bh][n][d]
__device__ __half g_q16 [(size_t)BH_ * SLAB];
__device__ __half g_v16 [(size_t)BH_ * SLAB];
__device__ __half g_k16 [(size_t)BH_ * SLAB];
__device__ __half g_kf16[(size_t)BH_ * SLAB];
__device__ __half g_ks16[(size_t)BH_ * SLAB];
__device__ __half g_wb16[(size_t)H_ * DK_ * DK_];
__device__ __half g_mb16[(size_t)BH_ * DK_ * DK_];   // blended state fp16

// ===================== PTX helpers (base-target) ===========================
__device__ __forceinline__ uint32_t smem_u32(const void* p) {
    uint32_t a;
    asm("{ .reg .u64 t; cvta.to.shared.u64 t, %1; cvt.u32.u64 %0, t; }"
        : "=r"(a) : "l"(p));
    return a;
}

#define MMAF16(d, a, b0, b1) \
    asm volatile("mma.sync.aligned.m16n8k16.row.col.f32.f16.f16.f32 " \
        "{%0,%1,%2,%3}, {%4,%5,%6,%7}, {%8,%9}, {%0,%1,%2,%3};" \
        : "+f"((d)[0]), "+f"((d)[1]), "+f"((d)[2]), "+f"((d)[3]) \
        : "r"((a)[0]), "r"((a)[1]), "r"((a)[2]), "r"((a)[3]), "r"(b0), "r"(b1))

#define LDSM_X4(r, addr) \
    asm volatile("ldmatrix.sync.aligned.m8n8.x4.shared.b16 {%0,%1,%2,%3}, [%4];" \
        : "=r"((r)[0]), "=r"((r)[1]), "=r"((r)[2]), "=r"((r)[3]) : "r"(addr))
#define LDSM_X4_T(r, addr) \
    asm volatile("ldmatrix.sync.aligned.m8n8.x4.trans.shared.b16 {%0,%1,%2,%3}, [%4];" \
        : "=r"((r)[0]), "=r"((r)[1]), "=r"((r)[2]), "=r"((r)[3]) : "r"(addr))

#define CP_ASYNC16(dst, src) \
    asm volatile("cp.async.cg.shared.global [%0], [%1], 16;" \
        :: "r"(dst), "l"(src) : "memory")
#define CP_COMMIT() asm volatile("cp.async.commit_group;" ::: "memory")
#define CP_WAIT(n)  asm volatile("cp.async.wait_group %0;" :: "n"(n) : "memory")

// ======================= fused x convert + mean partial (32 splits) ========
__global__ void k_cvtmean(const float* __restrict__ x) {
    int gid = blockIdx.x * 256 + threadIdx.x;        // 262144 threads
    int sp = gid >> 13;                               // 0..31
    int r  = gid & 8191;
    int b = r >> 11, d = r & 2047;
    float s = 0.f;
    int nbeg = sp * 128;
    #pragma unroll 8
    for (int n = nbeg; n < nbeg + 128; n++) {
        size_t idx = (size_t)(b * N_ + n) * DIM_ + d;
        float v = x[idx];
        s += v;
        g_x16[idx] = __float2half_rn(v);
    }
    g_meanpart[gid] = s;
}

__global__ void k_meanred() {
    int r = blockIdx.x * 256 + threadIdx.x;
    float s = 0.f;
    #pragma unroll
    for (int sp = 0; sp < 32; sp++) s += g_meanpart[sp * 8192 + r];
    g_mean[r] = s * (1.f / 4096.f);
}

// ======================= weight prep =======================
__global__ void k_wcvt_qkv(const float* __restrict__ Wq, const float* __restrict__ Wk,
                           const float* __restrict__ Wv) {
    __shared__ float tile[32][33];
    int k0 = blockIdx.x * 32, n0 = blockIdx.y * 32;
    int which = n0 >> 11;
    const float* __restrict__ W = (which == 0) ? Wq : (which == 1 ? Wk : Wv);
    int nn0 = n0 & 2047;
    for (int r = threadIdx.y; r < 32; r += 8)
        tile[r][threadIdx.x] = W[(size_t)(k0 + r) * 2048 + nn0 + threadIdx.x];
    __syncthreads();
    for (int r = threadIdx.y; r < 32; r += 8)
        g_wqkv16[(size_t)(n0 + r) * 2048 + k0 + threadIdx.x] = __float2half_rn(tile[threadIdx.x][r]);
}

__global__ void k_wcvt_o(const float* __restrict__ Wo) {
    __shared__ float tile[32][33];
    int k0 = blockIdx.x * 32, n0 = blockIdx.y * 32;
    for (int r = threadIdx.y; r < 32; r += 8)
        tile[r][threadIdx.x] = Wo[(size_t)(k0 + r) * 2048 + n0 + threadIdx.x];
    __syncthreads();
    for (int r = threadIdx.y; r < 32; r += 8)
        g_wo16[(size_t)(n0 + r) * 2048 + k0 + threadIdx.x] = __float2half_rn(tile[threadIdx.x][r]);
}

__global__ void k_wcvt_b(const float* __restrict__ Wb) {
    int i = (blockIdx.x * 256 + threadIdx.x) * 4;
    float4 v = *(const float4*)(Wb + i);
    *(__half2*)(g_wb16 + i) = __floats2half2_rn(v.x, v.y);
    *(__half2*)(g_wb16 + i + 2) = __floats2half2_rn(v.z, v.w);
}

// ======================= fp16 single-pass main GEMM ========================
// mode 0: QKV (jsel 1 = k columns only, jsel 2 = q+v columns). mode 1: out-proj.
__global__ __launch_bounds__(256)
void k_f16_gemm(float* __restrict__ Cout, int mode, int jsel) {
    __shared__ __align__(16) __half sm[2][2][128][40];
    const __half* __restrict__ A  = (mode == 0) ? g_x16  : g_ob16;
    const __half* __restrict__ Bm = (mode == 0) ? g_wqkv16 : g_wo16;

    const uint32_t sbase = smem_u32(sm);
    const int tid = threadIdx.x;
    const int wid = tid >> 5, lane = tid & 31;
    const int wr = wid >> 1, wc = wid & 1;
    int jb = blockIdx.x;
    if (jsel == 1) jb += 16;                       // k columns: j-blocks 16..31
    else if (jsel == 2 && jb >= 16) jb += 16;      // q (0..15) + v (32..47)
    const int j0 = jb * 128;
    const int m0 = blockIdx.y * 128;
    const int l15 = lane & 15;
    const int lhalf = (lane >> 4) * 8;

    float acc[2][8][4];
    #pragma unroll
    for (int i = 0; i < 2; i++)
        #pragma unroll
        for (int j = 0; j < 8; j++)
            #pragma unroll
            for (int k = 0; k < 4; k++) acc[i][j][k] = 0.f;

    int gl_isB[4], gl_r[4], gl_q[4];
    #pragma unroll
    for (int i = 0; i < 4; i++) {
        int idx = i * 256 + tid;
        gl_isB[i] = idx >> 9;
        int rem = idx & 511;
        gl_r[i] = rem >> 2;
        gl_q[i] = rem & 3;
    }

    auto issue = [&](int c, int st) {
        #pragma unroll
        for (int i = 0; i < 4; i++) {
            const __half* src = (gl_isB[i] ? Bm + (size_t)(j0 + gl_r[i]) * 2048
                                           : A  + (size_t)(m0 + gl_r[i]) * 2048)
                                + c * 32 + gl_q[i] * 8;
            uint32_t dst = sbase +
                (uint32_t)(((st * 2 + gl_isB[i]) * 128 + gl_r[i]) * 40 + gl_q[i] * 8) * 2;
            CP_ASYNC16(dst, src);
        }
        CP_COMMIT();
    };

    issue(0, 0);
    for (int c = 0; c < 64; c++) {
        if (c < 63) { issue(c + 1, (c + 1) & 1); CP_WAIT(1); }
        else        { CP_WAIT(0); }
        __syncthreads();
        const uint32_t stg = sbase + (uint32_t)((c & 1) * 2 * 128 * 40) * 2;

        #pragma unroll
        for (int s = 0; s < 2; s++) {
            const uint32_t kcol = (uint32_t)(s * 16 + lhalf) * 2;
            uint32_t af[2][4], bf[4][4];
            #pragma unroll
            for (int i = 0; i < 2; i++) {
                uint32_t ar = stg + (uint32_t)((wr * 32 + i * 16 + l15) * 40) * 2 + kcol;
                LDSM_X4(af[i], ar);
            }
            #pragma unroll
            for (int p = 0; p < 4; p++) {
                uint32_t br = stg + (uint32_t)((128 + wc * 64 + p * 16 + l15) * 40) * 2 + kcol;
                LDSM_X4(bf[p], br);
            }
            #pragma unroll
            for (int i = 0; i < 2; i++)
                #pragma unroll
                for (int t = 0; t < 8; t++) {
                    const int p = t >> 1, sel = t & 1;
                    MMAF16(acc[i][t], af[i], bf[p][sel], bf[p][sel + 2]);
                }
        }
        __syncthreads();
    }

    const int gr = lane >> 2;
    const int lane2 = (lane & 3) * 2;
    if (mode == 0) {
        const int which = j0 >> 11;
        const int h = (j0 >> 7) & 15;
        const int b = m0 >> 12;
        const size_t slab = (size_t)(b * 16 + h) * SLAB;
        __half* d16 = ((which == 0) ? g_q16 : (which == 1) ? g_k16 : g_v16) + slab;
        #pragma unroll
        for (int i = 0; i < 2; i++) {
            int n = (m0 & 4095) + wr * 32 + i * 16 + gr;
            #pragma unroll
            for (int t = 0; t < 8; t++) {
                int col = wc * 64 + t * 8 + lane2;
                size_t o0 = (size_t)n * 128 + col;
                *(__half2*)(d16 + o0) = __floats2half2_rn(acc[i][t][0], acc[i][t][1]);
                *(__half2*)(d16 + o0 + 8 * 128) = __floats2half2_rn(acc[i][t][2], acc[i][t][3]);
            }
        }
    } else {
        #pragma unroll
        for (int i = 0; i < 2; i++) {
            int m = m0 + wr * 32 + i * 16 + gr;
            #pragma unroll
            for (int t = 0; t < 8; t++) {
                int col = j0 + wc * 64 + t * 8 + lane2;
                float* dst = Cout + (size_t)m * 2048 + col;
                *(float2*)dst = make_float2(acc[i][t][0], acc[i][t][1]);
                *(float2*)(dst + 8 * 2048) = make_float2(acc[i][t][2], acc[i][t][3]);
            }
        }
    }
}

// ======================= k_res via fp16 MMA ================================
static constexpr int RS_STG = 128 * 40 + 32 * 136;   // 9472 halves per stage

__global__ __launch_bounds__(256)
void k_res_mma(const float* __restrict__ fast_slope, const float* __restrict__ slow_slope) {
    __shared__ __align__(16) __half sm[2][RS_STG];
    const int bh = blockIdx.y;
    const int m0 = blockIdx.x * 128;
    const int h = bh & 15;
    const __half* __restrict__ kslab = g_k16 + (size_t)bh * SLAB;
    const __half* __restrict__ wb = g_wb16 + (size_t)h * 16384;
    const uint32_t sbase = smem_u32(sm);
    const int tid = threadIdx.x;
    const int wid = tid >> 5, lane = tid & 31;
    const int wr = wid >> 1, wc = wid & 1;
    const int l15 = lane & 15;
    const int lhalf = (lane >> 4) * 8;

    float acc[2][8][4];
    #pragma unroll
    for (int i = 0; i < 2; i++)
        #pragma unroll
        for (int j = 0; j < 8; j++)
            #pragma unroll
            for (int k = 0; k < 4; k++) acc[i][j][k] = 0.f;

    int gA[4], gl_r[4], gl_q[4];
    #pragma unroll
    for (int i = 0; i < 4; i++) {
        int idx = i * 256 + tid;
        if (idx < 512) { gA[i] = 0; gl_r[i] = idx >> 2; gl_q[i] = idx & 3; }
        else { int l = idx - 512; gA[i] = 1; gl_r[i] = l >> 4; gl_q[i] = l & 15; }
    }

    auto issue = [&](int c, int st) {
        #pragma unroll
        for (int i = 0; i < 4; i++) {
            const __half* src;
            uint32_t soff;
            if (gA[i] == 0) {
                src = kslab + (size_t)(m0 + gl_r[i]) * 128 + c * 32 + gl_q[i] * 8;
                soff = (uint32_t)(gl_r[i] * 40 + gl_q[i] * 8);
            } else {
                src = wb + (size_t)(c * 32 + gl_r[i]) * 128 + gl_q[i] * 8;
                soff = (uint32_t)(5120 + gl_r[i] * 136 + gl_q[i] * 8);
            }
            CP_ASYNC16(sbase + (uint32_t)(st * RS_STG) * 2 + soff * 2, src);
        }
        CP_COMMIT();
    };

    const int rofs = (lane & 7) + ((lane >> 4) << 3);
    const int cofs = (lane & 8);

    issue(0, 0);
    for (int c = 0; c < 4; c++) {
        if (c < 3) { issue(c + 1, (c + 1) & 1); CP_WAIT(1); }
        else       { CP_WAIT(0); }
        __syncthreads();
        const uint32_t stg = sbase + (uint32_t)((c & 1) * RS_STG) * 2;

        #pragma unroll
        for (int s = 0; s < 2; s++) {
            const uint32_t kcol = (uint32_t)(s * 16 + lhalf) * 2;
            const int rowd = s * 16 + rofs;
            uint32_t af[2][4], bf[4][4];
            #pragma unroll
            for (int i = 0; i < 2; i++) {
                uint32_t ar = stg + (uint32_t)((wr * 32 + i * 16 + l15) * 40) * 2 + kcol;
                LDSM_X4(af[i], ar);
            }
            #pragma unroll
            for (int p = 0; p < 4; p++) {
                uint32_t bd = stg + (uint32_t)(5120 + rowd * 136 + wc * 64 + p * 16 + cofs) * 2;
                LDSM_X4_T(bf[p], bd);
            }
            #pragma unroll
            for (int i = 0; i < 2; i++)
                #pragma unroll
                for (int t = 0; t < 8; t++) {
                    const int p = t >> 1, sel = t & 1;
                    MMAF16(acc[i][t], af[i], bf[p][sel], bf[p][sel + 2]);
                }
        }
        __syncthreads();
    }

    const int gr = lane >> 2;
    const int lane2 = (lane & 3) * 2;
    const float fs = fast_slope[h], ss = slow_slope[h];
    const size_t slb = (size_t)bh * SLAB;
    #pragma unroll
    for (int i = 0; i < 2; i++) {
        int n = m0 + wr * 32 + i * 16 + gr;
        float fw0 = expf(fs * (float)(n - (N_ - 1)));
        float sw0 = expf(ss * (float)(n - (N_ - 1)));
        float fw1 = expf(fs * (float)(n + 8 - (N_ - 1)));
        float sw1 = expf(ss * (float)(n + 8 - (N_ - 1)));
        #pragma unroll
        for (int t = 0; t < 8; t++) {
            int col = wc * 64 + t * 8 + lane2;
            size_t p0 = slb + (size_t)n * 128 + col;
            size_t p8 = p0 + 8 * 128;
            float2 k0 = __half22float2(*(const __half2*)(g_k16 + p0));
            float2 k8 = __half22float2(*(const __half2*)(g_k16 + p8));
            float r, km0, km1;
            r = tanhf(acc[i][t][0]); km0 = k0.x * (1.f + 0.5f * r) * INV_SQRT_DK;
            r = tanhf(acc[i][t][1]); km1 = k0.y * (1.f + 0.5f * r) * INV_SQRT_DK;
            *(__half2*)(g_kf16 + p0) = __floats2half2_rn(km0 * fw0, km1 * fw0);
            *(__half2*)(g_ks16 + p0) = __floats2half2_rn(km0 * sw0, km1 * sw0);
            r = tanhf(acc[i][t][2]); km0 = k8.x * (1.f + 0.5f * r) * INV_SQRT_DK;
            r = tanhf(acc[i][t][3]); km1 = k8.y * (1.f + 0.5f * r) * INV_SQRT_DK;
            *(__half2*)(g_kf16 + p8) = __floats2half2_rn(km0 * fw1, km1 * fw1);
            *(__half2*)(g_ks16 + p8) = __floats2half2_rn(km0 * sw1, km1 * sw1);
        }
    }
}

// ======================= k_oblend fp16 1-pass: o = q @ Mb ===================
__global__ __launch_bounds__(256)
void k_oblend_f16() {
    __shared__ __align__(16) __half sm[2][RS_STG];
    const int bh = blockIdx.y;
    const int m0 = blockIdx.x * 128;
    const __half* __restrict__ qslab = g_q16 + (size_t)bh * SLAB;
    const __half* __restrict__ mb = g_mb16 + (size_t)bh * 16384;
    const uint32_t sbase = smem_u32(sm);
    const int tid = threadIdx.x;
    const int wid = tid >> 5, lane = tid & 31;
    const int wr = wid >> 1, wc = wid & 1;
    const int l15 = lane & 15;
    const int lhalf = (lane >> 4) * 8;

    float acc[2][8][4];
    #pragma unroll
    for (int i = 0; i < 2; i++)
        #pragma unroll
        for (int j = 0; j < 8; j++)
            #pragma unroll
            for (int k = 0; k < 4; k++) acc[i][j][k] = 0.f;

    int gA[4], gl_r[4], gl_q[4];
    #pragma unroll
    for (int i = 0; i < 4; i++) {
        int idx = i * 256 + tid;
        if (idx < 512) { gA[i] = 0; gl_r[i] = idx >> 2; gl_q[i] = idx & 3; }
        else { int l = idx - 512; gA[i] = 1; gl_r[i] = l >> 4; gl_q[i] = l & 15; }
    }

    auto issue = [&](int c, int st) {
        #pragma unroll
        for (int i = 0; i < 4; i++) {
            const __half* src;
            uint32_t soff;
            if (gA[i] == 0) {
                src = qslab + (size_t)(m0 + gl_r[i]) * 128 + c * 32 + gl_q[i] * 8;
                soff = (uint32_t)(gl_r[i] * 40 + gl_q[i] * 8);
            } else {
                src = mb + (size_t)(c * 32 + gl_r[i]) * 128 + gl_q[i] * 8;
                soff = (uint32_t)(5120 + gl_r[i] * 136 + gl_q[i] * 8);
            }
            CP_ASYNC16(sbase + (uint32_t)(st * RS_STG) * 2 + soff * 2, src);
        }
        CP_COMMIT();
    };

    const int rofs = (lane & 7) + ((lane >> 4) << 3);
    const int cofs = (lane & 8);

    issue(0, 0);
    for (int c = 0; c < 4; c++) {
        if (c < 3) { issue(c + 1, (c + 1) & 1); CP_WAIT(1); }
        else       { CP_WAIT(0); }
        __syncthreads();
        const uint32_t stg = sbase + (uint32_t)((c & 1) * RS_STG) * 2;

        #pragma unroll
        for (int s = 0; s < 2; s++) {
            const uint32_t kcol = (uint32_t)(s * 16 + lhalf) * 2;
            const int rowd = s * 16 + rofs;
            uint32_t af[2][4], bf[4][4];
            #pragma unroll
            for (int i = 0; i < 2; i++) {
                uint32_t ar = stg + (uint32_t)((wr * 32 + i * 16 + l15) * 40) * 2 + kcol;
                LDSM_X4(af[i], ar);
            }
            #pragma unroll
            for (int p = 0; p < 4; p++) {
                uint32_t bd = stg + (uint32_t)(5120 + rowd * 136 + wc * 64 + p * 16 + cofs) * 2;
                LDSM_X4_T(bf[p], bd);
            }
            #pragma unroll
            for (int i = 0; i < 2; i++)
                #pragma unroll
                for (int t = 0; t < 8; t++) {
                    const int p = t >> 1, sel = t & 1;
                    MMAF16(acc[i][t], af[i], bf[p][sel], bf[p][sel + 2]);
                }
        }
        __syncthreads();
    }

    const int gr = lane >> 2;
    const int lane2 = (lane & 3) * 2;
    const int b = bh >> 4, h = bh & 15;
    #pragma unroll
    for (int i = 0; i < 2; i++) {
        int n = m0 + wr * 32 + i * 16 + gr;
        #pragma unroll
        for (int t = 0; t < 8; t++) {
            int col = wc * 64 + t * 8 + lane2;
            size_t b0 = ((size_t)(b * 4096 + n) * 16 + h) * 128 + col;
            size_t b8 = ((size_t)(b * 4096 + n + 8) * 16 + h) * 128 + col;
            *(__half2*)(g_ob16 + b0) = __floats2half2_rn(acc[i][t][0], acc[i][t][1]);
            *(__half2*)(g_ob16 + b8) = __floats2half2_rn(acc[i][t][2], acc[i][t][3]);
        }
    }
}

// ======================= k_mpart fp16 1-pass ===============================
static constexpr int MP_STG = 2 * 32 * 136;

__global__ __launch_bounds__(256)
void k_mpart_f16() {
    __shared__ __align__(16) __half sm[2][MP_STG];
    const int split = blockIdx.x, bh = blockIdx.y, which = blockIdx.z;
    const __half* __restrict__ kslab = (which ? g_ks16 : g_kf16) + (size_t)bh * SLAB;
    const __half* __restrict__ vslab = g_v16 + (size_t)bh * SLAB;
    const uint32_t sbase = smem_u32(sm);
    const int tid = threadIdx.x;
    const int wid = tid >> 5, lane = tid & 31;
    const int wr = wid >> 1, wc = wid & 1;

    float acc[2][8][4];
    #pragma unroll
    for (int i = 0; i < 2; i++)
        #pragma unroll
        for (int j = 0; j < 8; j++)
            #pragma unroll
            for (int k = 0; k < 4; k++) acc[i][j][k] = 0.f;

    int gl_t[4], gl_r[4], gl_q[4];
    #pragma unroll
    for (int i = 0; i < 4; i++) {
        int idx = i * 256 + tid;
        gl_t[i] = idx >> 9;
        int rem = idx & 511;
        gl_r[i] = rem >> 4;
        gl_q[i] = rem & 15;
    }

    auto issue = [&](int c, int st) {
        #pragma unroll
        for (int i = 0; i < 4; i++) {
            const __half* src = (gl_t[i] ? vslab : kslab)
                + (size_t)(split * 512 + c * 32 + gl_r[i]) * 128 + gl_q[i] * 8;
            uint32_t dst = sbase +
                (uint32_t)(st * MP_STG + gl_t[i] * 4352 + gl_r[i] * 136 + gl_q[i] * 8) * 2;
            CP_ASYNC16(dst, src);
        }
        CP_COMMIT();
    };

    const int rofs = (lane & 7) + ((lane >> 4) << 3);
    const int cofs = (lane & 8);

    issue(0, 0);
    for (int c = 0; c < 16; c++) {
        if (c < 15) { issue(c + 1, (c + 1) & 1); CP_WAIT(1); }
        else        { CP_WAIT(0); }
        __syncthreads();
        const uint32_t stg = sbase + (uint32_t)((c & 1) * MP_STG) * 2;

        #pragma unroll
        for (int ks = 0; ks < 2; ks++) {
            const int rowk = ks * 16 + rofs;
            uint32_t af[2][4], bf[4][4];
            #pragma unroll
            for (int i = 0; i < 2; i++) {
                uint32_t ad = stg + (uint32_t)(rowk * 136 + wr * 32 + i * 16 + cofs) * 2;
                LDSM_X4_T(af[i], ad);
            }
            #pragma unroll
            for (int p = 0; p < 4; p++) {
                uint32_t bd = stg + (uint32_t)(4352 + rowk * 136 + wc * 64 + p * 16 + cofs) * 2;
                LDSM_X4_T(bf[p], bd);
            }
            #pragma unroll
            for (int i = 0; i < 2; i++)
                #pragma unroll
                for (int t = 0; t < 8; t++) {
                    const int p = t >> 1, sel = t & 1;
                    MMAF16(acc[i][t], af[i], bf[p][sel], bf[p][sel + 2]);
                }
        }
        __syncthreads();
    }

    const int gr = lane >> 2;
    const int lane2 = (lane & 3) * 2;
    float* dst0 = g_part + (((size_t)which * BH_ + bh) * 8 + split) * 16384;
    #pragma unroll
    for (int i = 0; i < 2; i++) {
        int m = wr * 32 + i * 16 + gr;
        #pragma unroll
        for (int t = 0; t < 8; t++) {
            int col = wc * 64 + t * 8 + lane2;
            float* dst = dst0 + m * 128 + col;
            *(float2*)dst = make_float2(acc[i][t][0], acc[i][t][1]);
            *(float2*)(dst + 8 * 128) = make_float2(acc[i][t][2], acc[i][t][3]);
        }
    }
}

// ======================= gating MLP (split-K x32) =======================
__global__ void k_mlp1a(const float* __restrict__ f1_w) {
    __shared__ float xm4[4][64];
    const int jb = blockIdx.x;            // 0..3
    const int ks = blockIdx.y;            // 0..31
    const int k0 = ks * 64;
    const int j = jb * 256 + threadIdx.x;
    if (threadIdx.x < 256) {
        int b = threadIdx.x >> 6, kk = threadIdx.x & 63;
        xm4[b][kk] = g_mean[b * 2048 + k0 + kk];
    }
    __syncthreads();
    float a0 = 0.f, a1 = 0.f, a2 = 0.f, a3 = 0.f;
    #pragma unroll 8
    for (int kk = 0; kk < 64; kk++) {
        float w = f1_w[(size_t)(k0 + kk) * 1024 + j];
        a0 = fmaf(xm4[0][kk], w, a0);
        a1 = fmaf(xm4[1][kk], w, a1);
        a2 = fmaf(xm4[2][kk], w, a2);
        a3 = fmaf(xm4[3][kk], w, a3);
    }
    float* dst = g_h1part + ks * 4096;
    dst[0 * 1024 + j] = a0;
    dst[1 * 1024 + j] = a1;
    dst[2 * 1024 + j] = a2;
    dst[3 * 1024 + j] = a3;
}

__global__ void k_mlp1red(const float* __restrict__ f1_b) {
    int i = blockIdx.x * 256 + threadIdx.x;     // 0..4095
    int j = i & 1023;
    float s = 0.f;
    #pragma unroll
    for (int ks = 0; ks < 32; ks++) s += g_h1part[ks * 4096 + i];
    s += f1_b[j];
    g_h1[i] = s / (1.f + expf(-s));
}

__global__ void k_mlp2(const float* __restrict__ f2_w, const float* __restrict__ f2_b,
                       float* __restrict__ dout) {
    __shared__ float red[128];
    int bh = blockIdx.x;
    int b = bh >> 4, h = bh & 15;
    float s = 0.f;
    for (int k = threadIdx.x; k < 1024; k += 128)
        s = fmaf(g_h1[b * 1024 + k], f2_w[k * 16 + h], s);
    red[threadIdx.x] = s; __syncthreads();
    for (int off = 64; off > 0; off >>= 1) {
        if (threadIdx.x < off) red[threadIdx.x] += red[threadIdx.x + off];
        __syncthreads();
    }
    if (threadIdx.x == 0) {
        float z = red[0] + f2_b[h];
        dout[OUT_OFF_PSI + bh] = 1.f / (1.f + expf(-z));
    }
}

// ========== fused M finalize + (I+S)@M + psi scale (per bh,which) ==========
__global__ __launch_bounds__(256)
void k_mfinref(const float* __restrict__ Mf_prev, const float* __restrict__ Ms_prev,
               const float* __restrict__ inter_fast, const float* __restrict__ inter_slow,
               const float* __restrict__ S_fast, const float* __restrict__ S_slow,
               float* __restrict__ dout) {
    extern __shared__ float smemM[];              // 16384 floats
    __shared__ float As[16][132];
    const int bh = blockIdx.x;
    const int which = blockIdx.y;
    const int h = bh & 15;
    const int tx = threadIdx.x, ty = threadIdx.y;
    const int tid = ty * 16 + tx;

    {
        const float inter = which ? inter_slow[h] : inter_fast[h];
        const float* prev = (which ? Ms_prev : Mf_prev) + (size_t)bh * 16384;
        const float* part = g_part + ((size_t)which * BH_ + bh) * 8 * 16384;
        float* dst = dout + (which ? OUT_OFF_MS : OUT_OFF_MF) + (size_t)bh * 16384;
        for (int e = tid; e < 16384; e += 256) {
            float s = 0.f;
            #pragma unroll
            for (int sp = 0; sp < 8; sp++) s += part[(size_t)sp * 16384 + e];
            s = prev[e] * inter + s;
            dst[e] = s;
            smemM[e] = s;
        }
    }
    __syncthreads();

    const float* __restrict__ S = (which ? S_slow : S_fast) + (size_t)h * 16384;
    float acc[8][8];
    #pragma unroll
    for (int i = 0; i < 8; i++)
        #pragma unroll
        for (int j = 0; j < 8; j++) acc[i][j] = 0.f;

    const int arow = tid >> 2, acol = (tid & 3) * 4;

    for (int kt = 0; kt < 128; kt += 16) {
        #pragma unroll
        for (int r = 0; r < 2; r++) {
            int row = arow + r * 64;
            float4 av = *(const float4*)&S[(size_t)row * 128 + kt + acol];
            As[acol + 0][row] = av.x + ((row == kt + acol + 0) ? 1.f : 0.f);
            As[acol + 1][row] = av.y + ((row == kt + acol + 1) ? 1.f : 0.f);
            As[acol + 2][row] = av.z + ((row == kt + acol + 2) ? 1.f : 0.f);
            As[acol + 3][row] = av.w + ((row == kt + acol + 3) ? 1.f : 0.f);
        }
        __syncthreads();
        #pragma unroll
        for (int kk = 0; kk < 16; kk++) {
            float a[8], bb[8];
            *(float4*)&a[0]  = *(const float4*)&As[kk][ty * 8];
            *(float4*)&a[4]  = *(const float4*)&As[kk][ty * 8 + 4];
            *(float4*)&bb[0] = *(const float4*)&smemM[(kt + kk) * 128 + tx * 8];
            *(float4*)&bb[4] = *(const float4*)&smemM[(kt + kk) * 128 + tx * 8 + 4];
            #pragma unroll
            for (int i = 0; i < 8; i++)
                #pragma unroll
                for (int j = 0; j < 8; j++)
                    acc[i][j] = fmaf(a[i], bb[j], acc[i][j]);
        }
        __syncthreads();
    }

    const float p = dout[OUT_OFF_PSI + bh];
    const float c0 = which ? p : (1.f - p);
    float* mdst = (which ? g_mbs2 : g_mblend) + (size_t)bh * 16384;
    #pragma unroll
    for (int i = 0; i < 8; i++)
        #pragma unroll
        for (int j = 0; j < 8; j += 2) {
            int idx = (ty * 8 + i) * 128 + tx * 8 + j;
            *(float2*)(mdst + idx) = make_float2(c0 * acc[i][j], c0 * acc[i][j + 1]);
        }
}

// sum the two psi-scaled halves -> fp16 Mb
__global__ void k_mbadd() {
    size_t i = ((size_t)blockIdx.x * 256 + threadIdx.x) * 2;
    float2 a = *(const float2*)(g_mblend + i);
    float2 b = *(const float2*)(g_mbs2 + i);
    *(__half2*)(g_mb16 + i) = __floats2half2_rn(a.x + b.x, a.y + b.y);
}

// ======================= launch =======================
extern "C" void kernel_launch(void* const* d_in, const int* in_sizes, int n_in,
                              void* d_out, int out_size) {
    (void)in_sizes; (void)n_in; (void)out_size;
    const float* x          = (const float*)d_in[0];
    const float* Mf_prev    = (const float*)d_in[1];
    const float* Ms_prev    = (const float*)d_in[2];
    const float* Wq         = (const float*)d_in[3];
    const float* Wk         = (const float*)d_in[4];
    const float* Wv         = (const float*)d_in[5];
    const float* Wo         = (const float*)d_in[6];
    const float* Wb         = (const float*)d_in[7];
    const float* fast_slope = (const float*)d_in[8];
    const float* slow_slope = (const float*)d_in[9];
    const float* inter_fast = (const float*)d_in[10];
    const float* inter_slow = (const float*)d_in[11];
    const float* S_fast     = (const float*)d_in[12];
    const float* S_slow     = (const float*)d_in[13];
    const float* f1_w       = (const float*)d_in[14];
    const float* f1_b       = (const float*)d_in[15];
    const float* f2_w       = (const float*)d_in[16];
    const float* f2_b       = (const float*)d_in[17];
    float* out = (float*)d_out;

    static cudaStream_t s1 = nullptr, s2 = nullptr;
    static cudaEvent_t e_fork0, e_fork, e_wq, e_wb, e_psi, e_qv, e_join;
    if (!s1) {
        cudaStreamCreateWithFlags(&s1, cudaStreamNonBlocking);
        cudaStreamCreateWithFlags(&s2, cudaStreamNonBlocking);
        cudaEventCreateWithFlags(&e_fork0, cudaEventDisableTiming);
        cudaEventCreateWithFlags(&e_fork, cudaEventDisableTiming);
        cudaEventCreateWithFlags(&e_wq, cudaEventDisableTiming);
        cudaEventCreateWithFlags(&e_wb, cudaEventDisableTiming);
        cudaEventCreateWithFlags(&e_psi, cudaEventDisableTiming);
        cudaEventCreateWithFlags(&e_qv, cudaEventDisableTiming);
        cudaEventCreateWithFlags(&e_join, cudaEventDisableTiming);
        cudaFuncSetAttribute(k_mfinref, cudaFuncAttributeMaxDynamicSharedMemorySize, 65536);
    }

    dim3 t16(16, 16);
    dim3 t328(32, 8);

    // fork: s1 converts QKV weights + Wb while main converts x
    cudaEventRecord(e_fork0, 0);
    cudaStreamWaitEvent(s1, e_fork0, 0);
    k_wcvt_qkv<<<dim3(64, 192), t328, 0, s1>>>(Wq, Wk, Wv);
    cudaEventRecord(e_wq, s1);
    k_wcvt_b<<<256, 256, 0, s1>>>(Wb);
    cudaEventRecord(e_wb, s1);

    k_cvtmean<<<1024, 256>>>(x);
    cudaEventRecord(e_fork, 0);

    // s1 continues: gating path, then Wo convert
    cudaStreamWaitEvent(s1, e_fork, 0);
    k_meanred<<<32, 256, 0, s1>>>();
    k_mlp1a<<<dim3(4, 32), 256, 0, s1>>>(f1_w);
    k_mlp1red<<<16, 256, 0, s1>>>(f1_b);
    k_mlp2<<<64, 128, 0, s1>>>(f2_w, f2_b, out);
    cudaEventRecord(e_psi, s1);
    k_wcvt_o<<<dim3(64, 64), t328, 0, s1>>>(Wo);
    cudaEventRecord(e_join, s1);

    // main: k-columns GEMM first (launch ahead of q/v so it drains early)
    cudaStreamWaitEvent(0, e_wq, 0);
    k_f16_gemm<<<dim3(16, 128), 256>>>(nullptr, 0, 1);   // k only

    // s2: q/v GEMM, concurrent with the k-chain below
    cudaStreamWaitEvent(s2, e_wq, 0);
    cudaStreamWaitEvent(s2, e_fork, 0);
    k_f16_gemm<<<dim3(32, 128), 256, 0, s2>>>(nullptr, 0, 2);  // q + v
    cudaEventRecord(e_qv, s2);

    // main: k-chain (overlaps with q/v GEMM)
    cudaStreamWaitEvent(0, e_wb, 0);
    k_res_mma<<<dim3(32, 64), 256>>>(fast_slope, slow_slope);
    k_mpart_f16<<<dim3(8, 64, 2), 256>>>();
    cudaStreamWaitEvent(0, e_psi, 0);
    k_mfinref<<<dim3(64, 2), t16, 65536>>>(Mf_prev, Ms_prev, inter_fast, inter_slow,
                                           S_fast, S_slow, out);
    k_mbadd<<<2048, 256>>>();

    // oblend needs q (s2) + Mb
    cudaStreamWaitEvent(0, e_qv, 0);
    k_oblend_f16<<<dim3(32, 64), 256>>>();

    // out-proj needs Wo (s1)
    cudaStreamWaitEvent(0, e_join, 0);
    k_f16_gemm<<<dim3(16, 128), 256>>>(out, 1, 0);
}